// round 9
// baseline (speedup 1.0000x reference)
#include <cuda_runtime.h>
#include <cstdint>

// Problem constants
#define B_     8
#define CDIM   64
#define NPOS   9216      // 96*96
#define INNER  128
#define O3     384       // 3*INNER
#define HEADS  4
#define DHEAD  32
#define NCH    9
#define CHUNK  1024
#define NGC    (32 * NCH)   // 288 (g, ch) pairs
#define GN_TILES 72

// Scratch (device globals — no allocations allowed)
__device__ float g_part[B_][8][GN_TILES][2];                        // groupnorm partials
__device__ __align__(16) float g_Apart[NGC][8][DHEAD * DHEAD];      // partial A (unnormalized)
__device__ __align__(16) float g_W2[B_ * NCH][2][CDIM][CDIM];       // fused weights hi/lo

// ---------------------------------------------------------------------------
__device__ __forceinline__ uint32_t f2tf(float x) {
    uint32_t r;
    asm("cvt.rna.tf32.f32 %0, %1;" : "=r"(r) : "f"(x));
    return r;
}

#define MMA(d, a, b)                                                          \
    asm volatile(                                                             \
        "mma.sync.aligned.m16n8k8.row.col.f32.tf32.tf32.f32 "                 \
        "{%0,%1,%2,%3},{%4,%5,%6,%7},{%8,%9},{%0,%1,%2,%3};"                  \
        : "+f"((d)[0]), "+f"((d)[1]), "+f"((d)[2]), "+f"((d)[3])              \
        : "r"((a)[0]), "r"((a)[1]), "r"((a)[2]), "r"((a)[3]),                 \
          "r"((b)[0]), "r"((b)[1]))

// ---------------------------------------------------------------------------
// ATT (fused): per (ch, g, sub) CTA of 128 threads:
//   q,k tiles [32 x 128] computed in-smem from Wqkv + x (tf32x3 mma),
//   column softmax for k / exp for q, then A_part = Eq * Ks^T (tf32x3 mma).
// grid (9, 32, 8), 128 threads, 102.4 KB smem, occ 2.
// ---------------------------------------------------------------------------
#define WPAD   68
#define XPAD   132
#define QPAD   132
#define A2_PAD 132
// word offsets
#define OFF_WQH 0
#define OFF_WQL 2176
#define OFF_WKH 4352
#define OFF_WKL 6528
#define OFF_XS  8704              // [64][132] = 8448
#define OFF_QS  17152             // [32][132] = 4224
#define OFF_KS  21376             // [32][132] = 4224
#define ATT_SMEM_WORDS 25600
#define ATT_SMEM (ATT_SMEM_WORDS * 4)
// aliases (valid after q/k mma phase: W and xs regions dead)
#define OFF_EQH 0
#define OFF_EQL 4224
#define OFF_KSH 8448
#define OFF_KSL 12672
// alias for A partial reduce (qs/ks dead after staging built)
#define OFF_APART 17152           // [4][32][33] = 4224

__global__ __launch_bounds__(128, 2) void att_fused_kernel(const float* __restrict__ x,
                                                           const float* __restrict__ Wqkv) {
    extern __shared__ uint32_t sm[];
    float* smf = (float*)sm;

    const int ch = blockIdx.x, g = blockIdx.y, sub = blockIdx.z;
    const int gc = g * NCH + ch;
    const int b = g >> 2, head = g & 3;
    const int tid = threadIdx.x, lane = tid & 31, wrp = tid >> 5;
    const int j = tid;
    const int n0 = ch * CHUNK + sub * 128;

    // ---- stage Wq_head / Wk_head [32 x 64] tf32-split ----
    for (int idx = tid; idx < 32 * 16; idx += 128) {
        int row = idx >> 4, c4 = (idx & 15) * 4;
        float4 wq = *(const float4*)(Wqkv + (size_t)(head * DHEAD + row) * CDIM + c4);
        float4 wk = *(const float4*)(Wqkv + (size_t)(INNER + head * DHEAD + row) * CDIM + c4);
        float vq[4] = {wq.x, wq.y, wq.z, wq.w};
        float vk[4] = {wk.x, wk.y, wk.z, wk.w};
#pragma unroll
        for (int t = 0; t < 4; t++) {
            uint32_t hq = f2tf(vq[t]);
            sm[OFF_WQH + row * WPAD + c4 + t] = hq;
            sm[OFF_WQL + row * WPAD + c4 + t] = f2tf(vq[t] - __uint_as_float(hq));
            uint32_t hk = f2tf(vk[t]);
            sm[OFF_WKH + row * WPAD + c4 + t] = hk;
            sm[OFF_WKL + row * WPAD + c4 + t] = f2tf(vk[t] - __uint_as_float(hk));
        }
    }
    // ---- stage x tile [64 c][128 j] raw ----
    const float* xb = x + (size_t)b * CDIM * NPOS + n0;
    for (int idx = tid; idx < 64 * 32; idx += 128) {
        int c = idx >> 5, j4 = (idx & 31) * 4;
        float4 v = *(const float4*)(xb + (size_t)c * NPOS + j4);
        float* d = smf + OFF_XS + c * XPAD + j4;
        d[0] = v.x; d[1] = v.y; d[2] = v.z; d[3] = v.w;
    }
    __syncthreads();

    const int gq = lane >> 2, tig = lane & 3;
    const int jw = wrp * 32;

    // ---- q then k: [32 x 128] = W[32x64] @ x[64x128], warp owns 32 N-cols ----
#pragma unroll
    for (int qk = 0; qk < 2; qk++) {
        const uint32_t* Wh = sm + (qk == 0 ? OFF_WQH : OFF_WKH);
        const uint32_t* Wl = sm + (qk == 0 ? OFF_WQL : OFF_WKL);
        float* outs = smf + (qk == 0 ? OFF_QS : OFF_KS);

        float acc[2][4][4];
#pragma unroll
        for (int i = 0; i < 2; i++)
#pragma unroll
            for (int jj = 0; jj < 4; jj++)
#pragma unroll
                for (int q = 0; q < 4; q++) acc[i][jj][q] = 0.f;

#pragma unroll
        for (int k8 = 0; k8 < 8; k8++) {
            const int kb = k8 * 8;
            uint32_t bh[4][2], bl[4][2];
#pragma unroll
            for (int nf = 0; nf < 4; nf++) {
                int col = jw + nf * 8 + gq;
                float v0 = smf[OFF_XS + (kb + tig) * XPAD + col];
                float v1 = smf[OFF_XS + (kb + tig + 4) * XPAD + col];
                uint32_t h0 = f2tf(v0), h1 = f2tf(v1);
                bh[nf][0] = h0; bh[nf][1] = h1;
                bl[nf][0] = f2tf(v0 - __uint_as_float(h0));
                bl[nf][1] = f2tf(v1 - __uint_as_float(h1));
            }
            uint32_t ah[2][4], al[2][4];
#pragma unroll
            for (int mf = 0; mf < 2; mf++) {
                int r0 = (mf * 16 + gq) * WPAD + kb + tig;
                int r1 = r0 + 8 * WPAD;
                ah[mf][0] = Wh[r0]; ah[mf][1] = Wh[r1];
                ah[mf][2] = Wh[r0 + 4]; ah[mf][3] = Wh[r1 + 4];
                al[mf][0] = Wl[r0]; al[mf][1] = Wl[r1];
                al[mf][2] = Wl[r0 + 4]; al[mf][3] = Wl[r1 + 4];
            }
#pragma unroll
            for (int mf = 0; mf < 2; mf++)
#pragma unroll
                for (int nf = 0; nf < 4; nf++) {
                    MMA(acc[mf][nf], ah[mf], bh[nf]);
                    MMA(acc[mf][nf], ah[mf], bl[nf]);
                    MMA(acc[mf][nf], al[mf], bh[nf]);
                }
        }
        // scatter to smem [d][j]
#pragma unroll
        for (int mf = 0; mf < 2; mf++)
#pragma unroll
            for (int nf = 0; nf < 4; nf++) {
                int row = mf * 16 + gq, col = jw + nf * 8 + tig * 2;
                *(float2*)(outs + row * QPAD + col) = make_float2(acc[mf][nf][0], acc[mf][nf][1]);
                *(float2*)(outs + (row + 8) * QPAD + col) = make_float2(acc[mf][nf][2], acc[mf][nf][3]);
            }
    }
    __syncthreads();

    // ---- softmax/exponentials, build tf32-split staging (aliases W + xs) ----
    {
        float kr[DHEAD];
#pragma unroll
        for (int d = 0; d < DHEAD; d++) kr[d] = smf[OFF_KS + d * QPAD + j];
        float km = -1e30f;
#pragma unroll
        for (int d = 0; d < DHEAD; d++) km = fmaxf(km, kr[d]);
        float kssum = 0.f;
#pragma unroll
        for (int d = 0; d < DHEAD; d++) { kr[d] = __expf(kr[d] - km); kssum += kr[d]; }
        float kinv = 1.0f / kssum;
        float qr[DHEAD];
#pragma unroll
        for (int d = 0; d < DHEAD; d++) qr[d] = smf[OFF_QS + d * QPAD + j];
#pragma unroll
        for (int d = 0; d < DHEAD; d++) {
            float v = kr[d] * kinv;
            uint32_t h = f2tf(v);
            sm[OFF_KSH + d * A2_PAD + j] = h;
            sm[OFF_KSL + d * A2_PAD + j] = f2tf(v - __uint_as_float(h));
            float e = __expf(qr[d]);
            uint32_t he = f2tf(e);
            sm[OFF_EQH + d * A2_PAD + j] = he;
            sm[OFF_EQL + d * A2_PAD + j] = f2tf(e - __uint_as_float(he));
        }
    }
    __syncthreads();

    // ---- A_part = Eq[32x128] * Ks[32x128]^T, K split across 4 warps ----
    float acc[2][4][4];
#pragma unroll
    for (int i = 0; i < 2; i++)
#pragma unroll
        for (int jj = 0; jj < 4; jj++)
#pragma unroll
            for (int q = 0; q < 4; q++) acc[i][jj][q] = 0.f;

#pragma unroll
    for (int kk = 0; kk < 4; kk++) {
        const int kb = (wrp * 4 + kk) * 8;
        uint32_t ah[2][4], al[2][4];
#pragma unroll
        for (int mf = 0; mf < 2; mf++) {
            int r0 = (mf * 16 + gq) * A2_PAD + kb + tig;
            int r1 = r0 + 8 * A2_PAD;
            ah[mf][0] = sm[OFF_EQH + r0]; ah[mf][1] = sm[OFF_EQH + r1];
            ah[mf][2] = sm[OFF_EQH + r0 + 4]; ah[mf][3] = sm[OFF_EQH + r1 + 4];
            al[mf][0] = sm[OFF_EQL + r0]; al[mf][1] = sm[OFF_EQL + r1];
            al[mf][2] = sm[OFF_EQL + r0 + 4]; al[mf][3] = sm[OFF_EQL + r1 + 4];
        }
        uint32_t bh[4][2], bl[4][2];
#pragma unroll
        for (int nf = 0; nf < 4; nf++) {
            int c0 = (nf * 8 + gq) * A2_PAD + kb + tig;
            bh[nf][0] = sm[OFF_KSH + c0]; bh[nf][1] = sm[OFF_KSH + c0 + 4];
            bl[nf][0] = sm[OFF_KSL + c0]; bl[nf][1] = sm[OFF_KSL + c0 + 4];
        }
#pragma unroll
        for (int mf = 0; mf < 2; mf++)
#pragma unroll
            for (int nf = 0; nf < 4; nf++) {
                MMA(acc[mf][nf], ah[mf], bh[nf]);
                MMA(acc[mf][nf], ah[mf], bl[nf]);
                MMA(acc[mf][nf], al[mf], bh[nf]);
            }
    }
    __syncthreads();

    float* Apart = smf + OFF_APART;   // [4][32][33]
#pragma unroll
    for (int mf = 0; mf < 2; mf++)
#pragma unroll
        for (int nf = 0; nf < 4; nf++) {
            int row = mf * 16 + gq, col = nf * 8 + tig * 2;
            Apart[(wrp * 32 + row) * 33 + col]     = acc[mf][nf][0];
            Apart[(wrp * 32 + row) * 33 + col + 1] = acc[mf][nf][1];
            Apart[(wrp * 32 + row + 8) * 33 + col]     = acc[mf][nf][2];
            Apart[(wrp * 32 + row + 8) * 33 + col + 1] = acc[mf][nf][3];
        }
    __syncthreads();

    float* out = g_Apart[gc][sub];
#pragma unroll
    for (int r = 0; r < 8; r++) {
        int idx = tid + 128 * r;
        int d = idx >> 5, dp = idx & 31;
        float s = 0.f;
#pragma unroll
        for (int w = 0; w < 4; w++) s += Apart[(w * 32 + d) * 33 + dp];
        out[idx] = s;
    }
}

// ---------------------------------------------------------------------------
// WEFF (fused, all heads): per (ch, b): reduce A partials, 1/Zq from row sums,
// Weff = Wout @ blockdiag(A), W2 = Weff @ Wv, split hi/lo. grid (9, 8), 256 thr.
// ---------------------------------------------------------------------------
#define WF_A    0                     // [4*32*33] = 4224
#define WF_WO   4224                  // [64][132] = 8448
#define WF_WEFF 12672                 // [64][132] = 8448
#define WF_WV   0                     // alias over A+Wo: [128][68] = 8704
#define WF_SMEM_WORDS 21120
#define WF_SMEM (WF_SMEM_WORDS * 4)

__global__ __launch_bounds__(256, 2) void weff_kernel(const float* __restrict__ Wqkv,
                                                      const float* __restrict__ Wout) {
    extern __shared__ float wsm[];
    __shared__ float rinv_s[128];
    const int ch = blockIdx.x, b = blockIdx.y;
    const int cc = b * NCH + ch;
    const int tid = threadIdx.x;

    // reduce A partials for all 4 heads
#pragma unroll
    for (int r = 0; r < 16; r++) {
        int idx = tid + 256 * r;
        int head = idx >> 10, e = idx & 1023;
        int d = e >> 5, dp = e & 31;
        const float* ap = g_Apart[(b * HEADS + head) * NCH + ch][0] + e;
        float s = 0.f;
#pragma unroll
        for (int sub = 0; sub < 8; sub++) s += ap[sub * DHEAD * DHEAD];
        wsm[WF_A + (head * 32 + d) * 33 + dp] = s;
    }
    // stage Wout [64][128]
#pragma unroll
    for (int r = 0; r < 8; r++) {
        int idx = tid + 256 * r;
        int o = idx >> 5, ic4 = (idx & 31) * 4;
        float4 v = *(const float4*)(Wout + (size_t)o * INNER + ic4);
        float* d = wsm + WF_WO + o * 132 + ic4;
        d[0] = v.x; d[1] = v.y; d[2] = v.z; d[3] = v.w;
    }
    __syncthreads();

    // 1/Zq per (head, d)
    if (tid < 128) {
        float s = 0.f;
#pragma unroll
        for (int dp = 0; dp < DHEAD; dp++) s += wsm[WF_A + tid * 33 + dp];
        rinv_s[tid] = 1.0f / s;
    }
    __syncthreads();
#pragma unroll
    for (int r = 0; r < 16; r++) {
        int idx = tid + 256 * r;
        int row = idx >> 5, dp = idx & 31;
        wsm[WF_A + row * 33 + dp] *= rinv_s[row];
    }
    __syncthreads();

    // Weff[o][ic] = sum_d Wout[o][head*32+d] * A[head][d][dp], ic = head*32+dp
#pragma unroll
    for (int r = 0; r < 32; r++) {
        int idx = tid + 256 * r;
        int o = idx >> 7, ic = idx & 127, head = ic >> 5, dp = ic & 31;
        float acc = 0.f;
#pragma unroll
        for (int d = 0; d < DHEAD; d++)
            acc += wsm[WF_WO + o * 132 + head * 32 + d] * wsm[WF_A + (head * 32 + d) * 33 + dp];
        wsm[WF_WEFF + o * 132 + ic] = acc;
    }
    __syncthreads();

    // load Wv [128][64] into alias region (A + Wout dead)
#pragma unroll
    for (int r = 0; r < 8; r++) {
        int idx = tid + 256 * r;
        int ic = idx >> 4, c4 = (idx & 15) * 4;
        float4 v = *(const float4*)(Wqkv + (size_t)(2 * INNER + ic) * CDIM + c4);
        float* d = wsm + WF_WV + ic * 68 + c4;
        d[0] = v.x; d[1] = v.y; d[2] = v.z; d[3] = v.w;
    }
    __syncthreads();

    // W2[o][c] = sum_ic Weff[o][ic] * Wv[ic][c]
    const int o = tid >> 2, c0 = (tid & 3) * 16;
    float w2[16];
#pragma unroll
    for (int i = 0; i < 16; i++) w2[i] = 0.f;
#pragma unroll
    for (int ic = 0; ic < INNER; ic++) {
        float we = wsm[WF_WEFF + o * 132 + ic];
#pragma unroll
        for (int i = 0; i < 16; i++) w2[i] += we * wsm[WF_WV + ic * 68 + c0 + i];
    }
#pragma unroll
    for (int i = 0; i < 16; i++) {
        uint32_t h = f2tf(w2[i]);
        *(uint32_t*)&g_W2[cc][0][o][c0 + i] = h;
        *(uint32_t*)&g_W2[cc][1][o][c0 + i] = f2tf(w2[i] - __uint_as_float(h));
    }
}

// ---------------------------------------------------------------------------
// K3'' (fused): y = W2(b,ch) @ x + b_out, groupnorm partials (unchanged R8).
// CTA tile [64 M x 128 N], K=64. grid (72, 8), 256 threads, occ 2.
// ---------------------------------------------------------------------------
#define K3_PAD 68
#define K3_SMEM (64 * K3_PAD * 2 * 4)

__global__ __launch_bounds__(256, 2) void outproj_mma_kernel(const float* __restrict__ x,
                                                             const float* __restrict__ bout,
                                                             float* __restrict__ y) {
    extern __shared__ uint32_t smu[];
    uint32_t* Ahi = smu;
    uint32_t* Alo = Ahi + 64 * K3_PAD;
    __shared__ float swp[8][8][2];

    const int b = blockIdx.y, n0 = blockIdx.x * 128, tid = threadIdx.x;
    const int cc = b * NCH + (n0 / CHUNK);

    for (int idx = tid; idx < 64 * 16; idx += 256) {
        int row = idx >> 4, c4 = (idx & 15) * 4;
        float4 h4 = *(const float4*)(&g_W2[cc][0][row][c4]);
        float4 l4 = *(const float4*)(&g_W2[cc][1][row][c4]);
        Ahi[row * K3_PAD + c4]     = __float_as_uint(h4.x);
        Ahi[row * K3_PAD + c4 + 1] = __float_as_uint(h4.y);
        Ahi[row * K3_PAD + c4 + 2] = __float_as_uint(h4.z);
        Ahi[row * K3_PAD + c4 + 3] = __float_as_uint(h4.w);
        Alo[row * K3_PAD + c4]     = __float_as_uint(l4.x);
        Alo[row * K3_PAD + c4 + 1] = __float_as_uint(l4.y);
        Alo[row * K3_PAD + c4 + 2] = __float_as_uint(l4.z);
        Alo[row * K3_PAD + c4 + 3] = __float_as_uint(l4.w);
    }
    __syncthreads();

    const int wid = tid >> 5, lane = tid & 31, g = lane >> 2, tig = lane & 3;
    const int wn = wid * 16;
    const float* xb = x + (size_t)b * CDIM * NPOS + n0;

    float acc[4][2][4];
#pragma unroll
    for (int i = 0; i < 4; i++)
#pragma unroll
        for (int j = 0; j < 2; j++)
#pragma unroll
            for (int q = 0; q < 4; q++) acc[i][j][q] = 0.f;

#pragma unroll
    for (int k8 = 0; k8 < 8; k8++) {
        const int kb = k8 * 8;
        const float* xr0 = xb + (size_t)(kb + tig) * NPOS;
        const float* xr1 = xr0 + 4 * NPOS;
        uint32_t bh[2][2], bl[2][2];
#pragma unroll
        for (int nf = 0; nf < 2; nf++) {
            int col = wn + nf * 8 + g;
            float v0 = __ldg(xr0 + col);
            float v1 = __ldg(xr1 + col);
            uint32_t h0 = f2tf(v0), h1 = f2tf(v1);
            bh[nf][0] = h0; bh[nf][1] = h1;
            bl[nf][0] = f2tf(v0 - __uint_as_float(h0));
            bl[nf][1] = f2tf(v1 - __uint_as_float(h1));
        }
        uint32_t ah[4][4], al[4][4];
#pragma unroll
        for (int mf = 0; mf < 4; mf++) {
            int r0 = (mf * 16 + g) * K3_PAD + kb + tig;
            int r1 = r0 + 8 * K3_PAD;
            ah[mf][0] = Ahi[r0]; ah[mf][1] = Ahi[r1];
            ah[mf][2] = Ahi[r0 + 4]; ah[mf][3] = Ahi[r1 + 4];
            al[mf][0] = Alo[r0]; al[mf][1] = Alo[r1];
            al[mf][2] = Alo[r0 + 4]; al[mf][3] = Alo[r1 + 4];
        }
#pragma unroll
        for (int mf = 0; mf < 4; mf++)
#pragma unroll
            for (int nf = 0; nf < 2; nf++) {
                MMA(acc[mf][nf], ah[mf], bh[nf]);
                MMA(acc[mf][nf], ah[mf], bl[nf]);
                MMA(acc[mf][nf], al[mf], bh[nf]);
            }
    }

    float gs[8], gq[8];
#pragma unroll
    for (int i = 0; i < 8; i++) { gs[i] = 0.f; gq[i] = 0.f; }

    float* yp = y + (size_t)b * CDIM * NPOS + n0 + wn;
#pragma unroll
    for (int mf = 0; mf < 4; mf++) {
        float bias0 = __ldg(bout + mf * 16 + g);
        float bias1 = __ldg(bout + mf * 16 + g + 8);
#pragma unroll
        for (int nf = 0; nf < 2; nf++) {
            int col = nf * 8 + tig * 2;
            float v0 = acc[mf][nf][0] + bias0, v1 = acc[mf][nf][1] + bias0;
            float v2 = acc[mf][nf][2] + bias1, v3 = acc[mf][nf][3] + bias1;
            *(float2*)(yp + (size_t)(mf * 16 + g) * NPOS + col) = make_float2(v0, v1);
            *(float2*)(yp + (size_t)(mf * 16 + g + 8) * NPOS + col) = make_float2(v2, v3);
            gs[2 * mf]     += v0 + v1;
            gq[2 * mf]     += v0 * v0 + v1 * v1;
            gs[2 * mf + 1] += v2 + v3;
            gq[2 * mf + 1] += v2 * v2 + v3 * v3;
        }
    }

#pragma unroll
    for (int gr = 0; gr < 8; gr++) {
        float s = gs[gr], q = gq[gr];
        for (int off = 16; off; off >>= 1) {
            s += __shfl_xor_sync(0xffffffffu, s, off);
            q += __shfl_xor_sync(0xffffffffu, q, off);
        }
        if (lane == 0) { swp[wid][gr][0] = s; swp[wid][gr][1] = q; }
    }
    __syncthreads();
    if (tid < 16) {
        int gr = tid >> 1, qq = tid & 1;
        float s = 0.f;
#pragma unroll
        for (int w = 0; w < 8; w++) s += swp[w][gr][qq];
        g_part[b][gr][blockIdx.x][qq] = s;
    }
}

// ---------------------------------------------------------------------------
// K4: groupnorm finalize, float4-vectorized. grid (9, 8), 256 threads.
// ---------------------------------------------------------------------------
__global__ __launch_bounds__(256, 4) void gnorm_kernel(float* __restrict__ y,
                                                       const float* __restrict__ gamma,
                                                       const float* __restrict__ beta) {
    __shared__ float tmp[8][2];
    __shared__ float mu[8], rs[8];
    const int b = blockIdx.y, n0 = blockIdx.x * 1024, tid = threadIdx.x;

    if (tid < 16) {
        int g = tid >> 1, qq = tid & 1;
        float s = 0.f;
        for (int t = 0; t < GN_TILES; t++) s += g_part[b][g][t][qq];
        tmp[g][qq] = s;
    }
    __syncthreads();
    if (tid < 8) {
        const float invn = 1.0f / (8.0f * NPOS);
        float m = tmp[tid][0] * invn;
        float v = tmp[tid][1] * invn - m * m;
        mu[tid] = m;
        rs[tid] = rsqrtf(v + 1e-5f);
    }
    __syncthreads();

    float* yb = y + (size_t)b * CDIM * NPOS + n0 + tid * 4;
#pragma unroll 4
    for (int c = 0; c < CDIM; c++) {
        float4* p = (float4*)(yb + (size_t)c * NPOS);
        float4 v = *p;
        int g = c >> 3;
        float sc = rs[g] * __ldg(gamma + c);
        float sh = __ldg(beta + c) - mu[g] * sc;
        v.x = v.x * sc + sh;
        v.y = v.y * sc + sh;
        v.z = v.z * sc + sh;
        v.w = v.w * sc + sh;
        *p = v;
    }
}

// ---------------------------------------------------------------------------
extern "C" void kernel_launch(void* const* d_in, const int* in_sizes, int n_in,
                              void* d_out, int out_size) {
    const float* x     = (const float*)d_in[0];
    const float* Wqkv  = (const float*)d_in[1];
    const float* Wout  = (const float*)d_in[2];
    const float* bout  = (const float*)d_in[3];
    const float* gamma = (const float*)d_in[4];
    const float* beta  = (const float*)d_in[5];
    float* y = (float*)d_out;

    cudaFuncSetAttribute(att_fused_kernel, cudaFuncAttributeMaxDynamicSharedMemorySize, ATT_SMEM);
    cudaFuncSetAttribute(weff_kernel, cudaFuncAttributeMaxDynamicSharedMemorySize, WF_SMEM);
    cudaFuncSetAttribute(outproj_mma_kernel, cudaFuncAttributeMaxDynamicSharedMemorySize, K3_SMEM);

    att_fused_kernel<<<dim3(NCH, 32, 8), 128, ATT_SMEM>>>(x, Wqkv);
    weff_kernel<<<dim3(NCH, B_), 256, WF_SMEM>>>(Wqkv, Wout);
    outproj_mma_kernel<<<dim3(GN_TILES, B_), 256, K3_SMEM>>>(x, bout, y);
    gnorm_kernel<<<dim3(NCH, B_), 256>>>(y, gamma, beta);
}

// round 10
// speedup vs baseline: 1.0593x; 1.0593x over previous
#include <cuda_runtime.h>
#include <cstdint>

// Problem constants
#define B_     8
#define CDIM   64
#define NPOS   9216      // 96*96
#define INNER  128
#define O3     384       // 3*INNER
#define HEADS  4
#define DHEAD  32
#define NCH    9
#define CHUNK  1024
#define NGC    (32 * NCH)   // 288 (g, ch) pairs
#define GN_TILES 72

// Scratch (device globals — no allocations allowed)
__device__ __align__(16) float g_qkv[(size_t)B_ * O3 * NPOS];      // [b][o][n] (q,k used)
__device__ float g_part[B_][8][GN_TILES][2];                        // groupnorm partials
__device__ __align__(16) float g_Apart[NGC][8][DHEAD * DHEAD];      // partial A (unnormalized)
__device__ __align__(16) float g_W2[B_ * NCH][2][CDIM][CDIM];       // fused weights hi/lo

// ---------------------------------------------------------------------------
__device__ __forceinline__ uint32_t f2tf(float x) {
    uint32_t r;
    asm("cvt.rna.tf32.f32 %0, %1;" : "=r"(r) : "f"(x));
    return r;
}

#define MMA(d, a, b)                                                          \
    asm volatile(                                                             \
        "mma.sync.aligned.m16n8k8.row.col.f32.tf32.tf32.f32 "                 \
        "{%0,%1,%2,%3},{%4,%5,%6,%7},{%8,%9},{%0,%1,%2,%3};"                  \
        : "+f"((d)[0]), "+f"((d)[1]), "+f"((d)[2]), "+f"((d)[3])              \
        : "r"((a)[0]), "r"((a)[1]), "r"((a)[2]), "r"((a)[3]),                 \
          "r"((b)[0]), "r"((b)[1]))

// ---------------------------------------------------------------------------
// K1 (mma): qk[b][o][n] = sum_c W_qkv[o][c] * x[b][c][n], o in [0, 256) only.
// A (W tile, hi/lo) in padded smem; B (x) streamed from global (R6 form).
// CTA tile [128 M x 128 N], K=64. grid (72, 2, 8), 256 threads, occ 2.
// ---------------------------------------------------------------------------
#define K1_APAD 68
#define K1_SMEM (128 * K1_APAD * 2 * 4)

__global__ __launch_bounds__(256, 2) void qkv_mma_kernel(const float* __restrict__ x,
                                                         const float* __restrict__ Wq) {
    extern __shared__ uint32_t smu[];
    uint32_t* Ahi = smu;
    uint32_t* Alo = Ahi + 128 * K1_APAD;

    const int b = blockIdx.z, mt = blockIdx.y, n0 = blockIdx.x * 128;
    const int tid = threadIdx.x;

    for (int idx = tid; idx < 128 * 16; idx += 256) {
        int row = idx >> 4, c4 = (idx & 15) * 4;
        float4 w = *(const float4*)(Wq + (size_t)(mt * 128 + row) * CDIM + c4);
        float v[4] = {w.x, w.y, w.z, w.w};
#pragma unroll
        for (int j = 0; j < 4; j++) {
            uint32_t h = f2tf(v[j]);
            Ahi[row * K1_APAD + c4 + j] = h;
            Alo[row * K1_APAD + c4 + j] = f2tf(v[j] - __uint_as_float(h));
        }
    }
    __syncthreads();

    const int wid = tid >> 5, lane = tid & 31, g = lane >> 2, tig = lane & 3;
    const int wm = (wid >> 2) * 64, wn = (wid & 3) * 32;

    const float* xb = x + (size_t)b * CDIM * NPOS + n0;

    float c[4][4][4];
#pragma unroll
    for (int i = 0; i < 4; i++)
#pragma unroll
        for (int j = 0; j < 4; j++)
#pragma unroll
            for (int q = 0; q < 4; q++) c[i][j][q] = 0.f;

#pragma unroll
    for (int k8 = 0; k8 < 8; k8++) {
        const int kb = k8 * 8;
        const float* xr0 = xb + (size_t)(kb + tig) * NPOS;
        const float* xr1 = xr0 + 4 * NPOS;
        uint32_t bh[4][2], bl[4][2];
#pragma unroll
        for (int nf = 0; nf < 4; nf++) {
            int col = wn + nf * 8 + g;
            float v0 = __ldg(xr0 + col);
            float v1 = __ldg(xr1 + col);
            uint32_t h0 = f2tf(v0), h1 = f2tf(v1);
            bh[nf][0] = h0; bh[nf][1] = h1;
            bl[nf][0] = f2tf(v0 - __uint_as_float(h0));
            bl[nf][1] = f2tf(v1 - __uint_as_float(h1));
        }
        uint32_t ah[4][4], al[4][4];
#pragma unroll
        for (int mf = 0; mf < 4; mf++) {
            int r0 = (wm + mf * 16 + g) * K1_APAD + kb + tig;
            int r1 = r0 + 8 * K1_APAD;
            ah[mf][0] = Ahi[r0]; ah[mf][1] = Ahi[r1];
            ah[mf][2] = Ahi[r0 + 4]; ah[mf][3] = Ahi[r1 + 4];
            al[mf][0] = Alo[r0]; al[mf][1] = Alo[r1];
            al[mf][2] = Alo[r0 + 4]; al[mf][3] = Alo[r1 + 4];
        }
#pragma unroll
        for (int mf = 0; mf < 4; mf++)
#pragma unroll
            for (int nf = 0; nf < 4; nf++) {
                MMA(c[mf][nf], ah[mf], bh[nf]);
                MMA(c[mf][nf], ah[mf], bl[nf]);
                MMA(c[mf][nf], al[mf], bh[nf]);
            }
    }

    float* op = g_qkv + ((size_t)b * O3 + mt * 128 + wm) * NPOS + n0 + wn;
#pragma unroll
    for (int mf = 0; mf < 4; mf++)
#pragma unroll
        for (int nf = 0; nf < 4; nf++) {
            int col = nf * 8 + tig * 2;
            *(float2*)(op + (size_t)(mf * 16 + g) * NPOS + col) =
                make_float2(c[mf][nf][0], c[mf][nf][1]);
            *(float2*)(op + (size_t)(mf * 16 + g + 8) * NPOS + col) =
                make_float2(c[mf][nf][2], c[mf][nf][3]);
        }
}

// ---------------------------------------------------------------------------
// ATT2: partial (unnormalized) A over 128 positions. grid (9, 32, 8), 128 thr.
// ---------------------------------------------------------------------------
#define A2_PAD 132
#define A2_ARR (DHEAD * A2_PAD)
#define A2_SMEM (4 * A2_ARR * 4)

__global__ __launch_bounds__(128, 3) void att_a_kernel() {
    extern __shared__ uint32_t sm2[];
    uint32_t* Eqh = sm2;
    uint32_t* Eql = Eqh + A2_ARR;
    uint32_t* Ksh = Eql + A2_ARR;
    uint32_t* Ksl = Ksh + A2_ARR;
    float* Apart = (float*)sm2;   // alias after mma: [4][32][33]

    const int ch = blockIdx.x, g = blockIdx.y, sub = blockIdx.z;
    const int gc = g * NCH + ch;
    const int b = g >> 2, head = g & 3;
    const int tid = threadIdx.x, lane = tid & 31, wrp = tid >> 5;
    const int j = tid;

    const float* qbase = g_qkv + ((size_t)(b * O3 + head * DHEAD)) * NPOS + ch * CHUNK + sub * 128;
    const float* kbase = qbase + (size_t)INNER * NPOS;

    float kr[DHEAD];
#pragma unroll
    for (int d = 0; d < DHEAD; d++) kr[d] = kbase[(size_t)d * NPOS + j];
    float km = -1e30f;
#pragma unroll
    for (int d = 0; d < DHEAD; d++) km = fmaxf(km, kr[d]);
    float ks = 0.f;
#pragma unroll
    for (int d = 0; d < DHEAD; d++) { kr[d] = __expf(kr[d] - km); ks += kr[d]; }
    float kinv = 1.0f / ks;
#pragma unroll
    for (int d = 0; d < DHEAD; d++) {
        float v = kr[d] * kinv;
        uint32_t h = f2tf(v);
        Ksh[d * A2_PAD + j] = h;
        Ksl[d * A2_PAD + j] = f2tf(v - __uint_as_float(h));
    }

    float qr[DHEAD];
#pragma unroll
    for (int d = 0; d < DHEAD; d++) qr[d] = qbase[(size_t)d * NPOS + j];
#pragma unroll
    for (int d = 0; d < DHEAD; d++) {
        float v = __expf(qr[d]);
        uint32_t h = f2tf(v);
        Eqh[d * A2_PAD + j] = h;
        Eql[d * A2_PAD + j] = f2tf(v - __uint_as_float(h));
    }
    __syncthreads();

    const int gq = lane >> 2, tig = lane & 3;
    float acc[2][4][4];
#pragma unroll
    for (int i = 0; i < 2; i++)
#pragma unroll
        for (int jj = 0; jj < 4; jj++)
#pragma unroll
            for (int q = 0; q < 4; q++) acc[i][jj][q] = 0.f;

#pragma unroll
    for (int kk = 0; kk < 4; kk++) {
        const int kb = (wrp * 4 + kk) * 8;
        uint32_t ah[2][4], al[2][4];
#pragma unroll
        for (int mf = 0; mf < 2; mf++) {
            int r0 = (mf * 16 + gq) * A2_PAD + kb + tig;
            int r1 = r0 + 8 * A2_PAD;
            ah[mf][0] = Eqh[r0]; ah[mf][1] = Eqh[r1];
            ah[mf][2] = Eqh[r0 + 4]; ah[mf][3] = Eqh[r1 + 4];
            al[mf][0] = Eql[r0]; al[mf][1] = Eql[r1];
            al[mf][2] = Eql[r0 + 4]; al[mf][3] = Eql[r1 + 4];
        }
        uint32_t bh[4][2], bl[4][2];
#pragma unroll
        for (int nf = 0; nf < 4; nf++) {
            int c0 = (nf * 8 + gq) * A2_PAD + kb + tig;
            bh[nf][0] = Ksh[c0]; bh[nf][1] = Ksh[c0 + 4];
            bl[nf][0] = Ksl[c0]; bl[nf][1] = Ksl[c0 + 4];
        }
#pragma unroll
        for (int mf = 0; mf < 2; mf++)
#pragma unroll
            for (int nf = 0; nf < 4; nf++) {
                MMA(acc[mf][nf], ah[mf], bh[nf]);
                MMA(acc[mf][nf], ah[mf], bl[nf]);
                MMA(acc[mf][nf], al[mf], bh[nf]);
            }
    }
    __syncthreads();

#pragma unroll
    for (int mf = 0; mf < 2; mf++)
#pragma unroll
        for (int nf = 0; nf < 4; nf++) {
            int row = mf * 16 + gq, col = nf * 8 + tig * 2;
            Apart[(wrp * 32 + row) * 33 + col]     = acc[mf][nf][0];
            Apart[(wrp * 32 + row) * 33 + col + 1] = acc[mf][nf][1];
            Apart[(wrp * 32 + row + 8) * 33 + col]     = acc[mf][nf][2];
            Apart[(wrp * 32 + row + 8) * 33 + col + 1] = acc[mf][nf][3];
        }
    __syncthreads();

    float* out = g_Apart[gc][sub];
#pragma unroll
    for (int r = 0; r < 8; r++) {
        int idx = tid + 128 * r;
        int d = idx >> 5, dp = idx & 31;
        float s = 0.f;
#pragma unroll
        for (int w = 0; w < 4; w++) s += Apart[(w * 32 + d) * 33 + dp];
        out[idx] = s;
    }
}

// ---------------------------------------------------------------------------
// WEFF (fused, all heads): per (ch, b): reduce A partials, 1/Zq from row sums,
// Weff = Wout @ blockdiag(A), W2 = Weff @ Wv, split hi/lo. grid (9, 8), 256 thr.
// ---------------------------------------------------------------------------
#define WF_A    0                     // [4*32*33] = 4224
#define WF_WO   4224                  // [64][132] = 8448
#define WF_WEFF 12672                 // [64][132] = 8448
#define WF_WV   0                     // alias over A+Wo: [128][68] = 8704
#define WF_SMEM_WORDS 21120
#define WF_SMEM (WF_SMEM_WORDS * 4)

__global__ __launch_bounds__(256, 2) void weff_kernel(const float* __restrict__ Wqkv,
                                                      const float* __restrict__ Wout) {
    extern __shared__ float wsm[];
    __shared__ float rinv_s[128];
    const int ch = blockIdx.x, b = blockIdx.y;
    const int cc = b * NCH + ch;
    const int tid = threadIdx.x;

#pragma unroll
    for (int r = 0; r < 16; r++) {
        int idx = tid + 256 * r;
        int head = idx >> 10, e = idx & 1023;
        int d = e >> 5, dp = e & 31;
        const float* ap = g_Apart[(b * HEADS + head) * NCH + ch][0] + e;
        float s = 0.f;
#pragma unroll
        for (int sub = 0; sub < 8; sub++) s += ap[sub * DHEAD * DHEAD];
        wsm[WF_A + (head * 32 + d) * 33 + dp] = s;
    }
#pragma unroll
    for (int r = 0; r < 8; r++) {
        int idx = tid + 256 * r;
        int o = idx >> 5, ic4 = (idx & 31) * 4;
        float4 v = *(const float4*)(Wout + (size_t)o * INNER + ic4);
        float* d = wsm + WF_WO + o * 132 + ic4;
        d[0] = v.x; d[1] = v.y; d[2] = v.z; d[3] = v.w;
    }
    __syncthreads();

    if (tid < 128) {
        float s = 0.f;
#pragma unroll
        for (int dp = 0; dp < DHEAD; dp++) s += wsm[WF_A + tid * 33 + dp];
        rinv_s[tid] = 1.0f / s;
    }
    __syncthreads();
#pragma unroll
    for (int r = 0; r < 16; r++) {
        int idx = tid + 256 * r;
        int row = idx >> 5, dp = idx & 31;
        wsm[WF_A + row * 33 + dp] *= rinv_s[row];
    }
    __syncthreads();

#pragma unroll
    for (int r = 0; r < 32; r++) {
        int idx = tid + 256 * r;
        int o = idx >> 7, ic = idx & 127, head = ic >> 5, dp = ic & 31;
        float acc = 0.f;
#pragma unroll
        for (int d = 0; d < DHEAD; d++)
            acc += wsm[WF_WO + o * 132 + head * 32 + d] * wsm[WF_A + (head * 32 + d) * 33 + dp];
        wsm[WF_WEFF + o * 132 + ic] = acc;
    }
    __syncthreads();

#pragma unroll
    for (int r = 0; r < 8; r++) {
        int idx = tid + 256 * r;
        int ic = idx >> 4, c4 = (idx & 15) * 4;
        float4 v = *(const float4*)(Wqkv + (size_t)(2 * INNER + ic) * CDIM + c4);
        float* d = wsm + WF_WV + ic * 68 + c4;
        d[0] = v.x; d[1] = v.y; d[2] = v.z; d[3] = v.w;
    }
    __syncthreads();

    const int o = tid >> 2, c0 = (tid & 3) * 16;
    float w2[16];
#pragma unroll
    for (int i = 0; i < 16; i++) w2[i] = 0.f;
#pragma unroll
    for (int ic = 0; ic < INNER; ic++) {
        float we = wsm[WF_WEFF + o * 132 + ic];
#pragma unroll
        for (int i = 0; i < 16; i++) w2[i] += we * wsm[WF_WV + ic * 68 + c0 + i];
    }
#pragma unroll
    for (int i = 0; i < 16; i++) {
        uint32_t h = f2tf(w2[i]);
        *(uint32_t*)&g_W2[cc][0][o][c0 + i] = h;
        *(uint32_t*)&g_W2[cc][1][o][c0 + i] = f2tf(w2[i] - __uint_as_float(h));
    }
}

// ---------------------------------------------------------------------------
// K3'' (fused): y = W2(b,ch) @ x + b_out, groupnorm partials.
// CTA tile [64 M x 128 N], K=64. grid (72, 8), 256 threads, occ 2.
// ---------------------------------------------------------------------------
#define K3_PAD 68
#define K3_SMEM (64 * K3_PAD * 2 * 4)

__global__ __launch_bounds__(256, 2) void outproj_mma_kernel(const float* __restrict__ x,
                                                             const float* __restrict__ bout,
                                                             float* __restrict__ y) {
    extern __shared__ uint32_t smu[];
    uint32_t* Ahi = smu;
    uint32_t* Alo = Ahi + 64 * K3_PAD;
    __shared__ float swp[8][8][2];

    const int b = blockIdx.y, n0 = blockIdx.x * 128, tid = threadIdx.x;
    const int cc = b * NCH + (n0 / CHUNK);

    for (int idx = tid; idx < 64 * 16; idx += 256) {
        int row = idx >> 4, c4 = (idx & 15) * 4;
        float4 h4 = *(const float4*)(&g_W2[cc][0][row][c4]);
        float4 l4 = *(const float4*)(&g_W2[cc][1][row][c4]);
        Ahi[row * K3_PAD + c4]     = __float_as_uint(h4.x);
        Ahi[row * K3_PAD + c4 + 1] = __float_as_uint(h4.y);
        Ahi[row * K3_PAD + c4 + 2] = __float_as_uint(h4.z);
        Ahi[row * K3_PAD + c4 + 3] = __float_as_uint(h4.w);
        Alo[row * K3_PAD + c4]     = __float_as_uint(l4.x);
        Alo[row * K3_PAD + c4 + 1] = __float_as_uint(l4.y);
        Alo[row * K3_PAD + c4 + 2] = __float_as_uint(l4.z);
        Alo[row * K3_PAD + c4 + 3] = __float_as_uint(l4.w);
    }
    __syncthreads();

    const int wid = tid >> 5, lane = tid & 31, g = lane >> 2, tig = lane & 3;
    const int wn = wid * 16;
    const float* xb = x + (size_t)b * CDIM * NPOS + n0;

    float acc[4][2][4];
#pragma unroll
    for (int i = 0; i < 4; i++)
#pragma unroll
        for (int j = 0; j < 2; j++)
#pragma unroll
            for (int q = 0; q < 4; q++) acc[i][j][q] = 0.f;

#pragma unroll
    for (int k8 = 0; k8 < 8; k8++) {
        const int kb = k8 * 8;
        const float* xr0 = xb + (size_t)(kb + tig) * NPOS;
        const float* xr1 = xr0 + 4 * NPOS;
        uint32_t bh[2][2], bl[2][2];
#pragma unroll
        for (int nf = 0; nf < 2; nf++) {
            int col = wn + nf * 8 + g;
            float v0 = __ldg(xr0 + col);
            float v1 = __ldg(xr1 + col);
            uint32_t h0 = f2tf(v0), h1 = f2tf(v1);
            bh[nf][0] = h0; bh[nf][1] = h1;
            bl[nf][0] = f2tf(v0 - __uint_as_float(h0));
            bl[nf][1] = f2tf(v1 - __uint_as_float(h1));
        }
        uint32_t ah[4][4], al[4][4];
#pragma unroll
        for (int mf = 0; mf < 4; mf++) {
            int r0 = (mf * 16 + g) * K3_PAD + kb + tig;
            int r1 = r0 + 8 * K3_PAD;
            ah[mf][0] = Ahi[r0]; ah[mf][1] = Ahi[r1];
            ah[mf][2] = Ahi[r0 + 4]; ah[mf][3] = Ahi[r1 + 4];
            al[mf][0] = Alo[r0]; al[mf][1] = Alo[r1];
            al[mf][2] = Alo[r0 + 4]; al[mf][3] = Alo[r1 + 4];
        }
#pragma unroll
        for (int mf = 0; mf < 4; mf++)
#pragma unroll
            for (int nf = 0; nf < 2; nf++) {
                MMA(acc[mf][nf], ah[mf], bh[nf]);
                MMA(acc[mf][nf], ah[mf], bl[nf]);
                MMA(acc[mf][nf], al[mf], bh[nf]);
            }
    }

    float gs[8], gq[8];
#pragma unroll
    for (int i = 0; i < 8; i++) { gs[i] = 0.f; gq[i] = 0.f; }

    float* yp = y + (size_t)b * CDIM * NPOS + n0 + wn;
#pragma unroll
    for (int mf = 0; mf < 4; mf++) {
        float bias0 = __ldg(bout + mf * 16 + g);
        float bias1 = __ldg(bout + mf * 16 + g + 8);
#pragma unroll
        for (int nf = 0; nf < 2; nf++) {
            int col = nf * 8 + tig * 2;
            float v0 = acc[mf][nf][0] + bias0, v1 = acc[mf][nf][1] + bias0;
            float v2 = acc[mf][nf][2] + bias1, v3 = acc[mf][nf][3] + bias1;
            *(float2*)(yp + (size_t)(mf * 16 + g) * NPOS + col) = make_float2(v0, v1);
            *(float2*)(yp + (size_t)(mf * 16 + g + 8) * NPOS + col) = make_float2(v2, v3);
            gs[2 * mf]     += v0 + v1;
            gq[2 * mf]     += v0 * v0 + v1 * v1;
            gs[2 * mf + 1] += v2 + v3;
            gq[2 * mf + 1] += v2 * v2 + v3 * v3;
        }
    }

#pragma unroll
    for (int gr = 0; gr < 8; gr++) {
        float s = gs[gr], q = gq[gr];
        for (int off = 16; off; off >>= 1) {
            s += __shfl_xor_sync(0xffffffffu, s, off);
            q += __shfl_xor_sync(0xffffffffu, q, off);
        }
        if (lane == 0) { swp[wid][gr][0] = s; swp[wid][gr][1] = q; }
    }
    __syncthreads();
    if (tid < 16) {
        int gr = tid >> 1, qq = tid & 1;
        float s = 0.f;
#pragma unroll
        for (int w = 0; w < 8; w++) s += swp[w][gr][qq];
        g_part[b][gr][blockIdx.x][qq] = s;
    }
}

// ---------------------------------------------------------------------------
// K4: groupnorm finalize. grid (36, 8) = 288 CTAs, 256 threads; 256-wide tiles,
// warp-contiguous float4 traffic, 16 independent LD/ST pairs per thread.
// ---------------------------------------------------------------------------
__global__ __launch_bounds__(256, 4) void gnorm_kernel(float* __restrict__ y,
                                                       const float* __restrict__ gamma,
                                                       const float* __restrict__ beta) {
    __shared__ float tmp[8][2];
    __shared__ float mu[8], rs[8];
    const int b = blockIdx.y, n0 = blockIdx.x * 256, tid = threadIdx.x;

    if (tid < 16) {
        int g = tid >> 1, qq = tid & 1;
        float s = 0.f;
        for (int t = 0; t < GN_TILES; t++) s += g_part[b][g][t][qq];
        tmp[g][qq] = s;
    }
    __syncthreads();
    if (tid < 8) {
        const float invn = 1.0f / (8.0f * NPOS);
        float m = tmp[tid][0] * invn;
        float v = tmp[tid][1] * invn - m * m;
        mu[tid] = m;
        rs[tid] = rsqrtf(v + 1e-5f);
    }
    __syncthreads();

    const int col4 = tid & 63, crow = tid >> 6;   // 64 float4 columns, 4 channel-lanes
    float* yb = y + (size_t)b * CDIM * NPOS + n0 + col4 * 4;
#pragma unroll
    for (int c = crow; c < CDIM; c += 4) {
        float4* p = (float4*)(yb + (size_t)c * NPOS);
        float4 v = *p;
        int g = c >> 3;
        float sc = rs[g] * __ldg(gamma + c);
        float sh = __ldg(beta + c) - mu[g] * sc;
        v.x = v.x * sc + sh;
        v.y = v.y * sc + sh;
        v.z = v.z * sc + sh;
        v.w = v.w * sc + sh;
        *p = v;
    }
}

// ---------------------------------------------------------------------------
extern "C" void kernel_launch(void* const* d_in, const int* in_sizes, int n_in,
                              void* d_out, int out_size) {
    const float* x     = (const float*)d_in[0];
    const float* Wqkv  = (const float*)d_in[1];
    const float* Wout  = (const float*)d_in[2];
    const float* bout  = (const float*)d_in[3];
    const float* gamma = (const float*)d_in[4];
    const float* beta  = (const float*)d_in[5];
    float* y = (float*)d_out;

    cudaFuncSetAttribute(qkv_mma_kernel, cudaFuncAttributeMaxDynamicSharedMemorySize, K1_SMEM);
    cudaFuncSetAttribute(att_a_kernel, cudaFuncAttributeMaxDynamicSharedMemorySize, A2_SMEM);
    cudaFuncSetAttribute(weff_kernel, cudaFuncAttributeMaxDynamicSharedMemorySize, WF_SMEM);
    cudaFuncSetAttribute(outproj_mma_kernel, cudaFuncAttributeMaxDynamicSharedMemorySize, K3_SMEM);

    qkv_mma_kernel<<<dim3(72, 2, B_), 256, K1_SMEM>>>(x, Wqkv);
    att_a_kernel<<<dim3(NCH, 32, 8), 128, A2_SMEM>>>();
    weff_kernel<<<dim3(NCH, B_), 256, WF_SMEM>>>(Wqkv, Wout);
    outproj_mma_kernel<<<dim3(GN_TILES, B_), 256, K3_SMEM>>>(x, bout, y);
    gnorm_kernel<<<dim3(36, B_), 256>>>(y, gamma, beta);
}

// round 11
// speedup vs baseline: 1.2175x; 1.1494x over previous
#include <cuda_runtime.h>
#include <cuda_fp16.h>
#include <cstdint>

// Problem constants
#define B_     8
#define CDIM   64
#define NPOS   9216      // 96*96
#define INNER  128
#define O3     384       // 3*INNER
#define HEADS  4
#define DHEAD  32
#define NCH    9
#define CHUNK  1024
#define NGC    (32 * NCH)   // 288 (g, ch) pairs
#define GN_TILES 72

// Scratch (device globals — no allocations allowed)
__device__ __align__(16) __half g_qk[(size_t)B_ * 256 * NPOS];      // [b][o][n], o<256 (q,k), fp16
__device__ float g_part[B_][8][GN_TILES][2];                        // groupnorm partials
__device__ __align__(16) float g_Apart[NGC][8][DHEAD * DHEAD];      // partial A (unnormalized)
__device__ __align__(16) float g_W2[B_ * NCH][2][CDIM][CDIM];       // fused weights hi/lo

// ---------------------------------------------------------------------------
__device__ __forceinline__ uint32_t f2tf(float x) {
    uint32_t r;
    asm("cvt.rna.tf32.f32 %0, %1;" : "=r"(r) : "f"(x));
    return r;
}

#define MMA(d, a, b)                                                          \
    asm volatile(                                                             \
        "mma.sync.aligned.m16n8k8.row.col.f32.tf32.tf32.f32 "                 \
        "{%0,%1,%2,%3},{%4,%5,%6,%7},{%8,%9},{%0,%1,%2,%3};"                  \
        : "+f"((d)[0]), "+f"((d)[1]), "+f"((d)[2]), "+f"((d)[3])              \
        : "r"((a)[0]), "r"((a)[1]), "r"((a)[2]), "r"((a)[3]),                 \
          "r"((b)[0]), "r"((b)[1]))

// ---------------------------------------------------------------------------
// K1 (mma): qk[b][o][n] = sum_c W_qkv[o][c] * x[b][c][n], o in [0, 256).
// Output stored fp16 (half2). CTA tile [128 M x 128 N], K=64.
// grid (72, 2, 8), 256 threads, occ 2.
// ---------------------------------------------------------------------------
#define K1_APAD 68
#define K1_SMEM (128 * K1_APAD * 2 * 4)

__global__ __launch_bounds__(256, 2) void qkv_mma_kernel(const float* __restrict__ x,
                                                         const float* __restrict__ Wq) {
    extern __shared__ uint32_t smu[];
    uint32_t* Ahi = smu;
    uint32_t* Alo = Ahi + 128 * K1_APAD;

    const int b = blockIdx.z, mt = blockIdx.y, n0 = blockIdx.x * 128;
    const int tid = threadIdx.x;

    for (int idx = tid; idx < 128 * 16; idx += 256) {
        int row = idx >> 4, c4 = (idx & 15) * 4;
        float4 w = *(const float4*)(Wq + (size_t)(mt * 128 + row) * CDIM + c4);
        float v[4] = {w.x, w.y, w.z, w.w};
#pragma unroll
        for (int j = 0; j < 4; j++) {
            uint32_t h = f2tf(v[j]);
            Ahi[row * K1_APAD + c4 + j] = h;
            Alo[row * K1_APAD + c4 + j] = f2tf(v[j] - __uint_as_float(h));
        }
    }
    __syncthreads();

    const int wid = tid >> 5, lane = tid & 31, g = lane >> 2, tig = lane & 3;
    const int wm = (wid >> 2) * 64, wn = (wid & 3) * 32;

    const float* xb = x + (size_t)b * CDIM * NPOS + n0;

    float c[4][4][4];
#pragma unroll
    for (int i = 0; i < 4; i++)
#pragma unroll
        for (int j = 0; j < 4; j++)
#pragma unroll
            for (int q = 0; q < 4; q++) c[i][j][q] = 0.f;

#pragma unroll
    for (int k8 = 0; k8 < 8; k8++) {
        const int kb = k8 * 8;
        const float* xr0 = xb + (size_t)(kb + tig) * NPOS;
        const float* xr1 = xr0 + 4 * NPOS;
        uint32_t bh[4][2], bl[4][2];
#pragma unroll
        for (int nf = 0; nf < 4; nf++) {
            int col = wn + nf * 8 + g;
            float v0 = __ldg(xr0 + col);
            float v1 = __ldg(xr1 + col);
            uint32_t h0 = f2tf(v0), h1 = f2tf(v1);
            bh[nf][0] = h0; bh[nf][1] = h1;
            bl[nf][0] = f2tf(v0 - __uint_as_float(h0));
            bl[nf][1] = f2tf(v1 - __uint_as_float(h1));
        }
        uint32_t ah[4][4], al[4][4];
#pragma unroll
        for (int mf = 0; mf < 4; mf++) {
            int r0 = (wm + mf * 16 + g) * K1_APAD + kb + tig;
            int r1 = r0 + 8 * K1_APAD;
            ah[mf][0] = Ahi[r0]; ah[mf][1] = Ahi[r1];
            ah[mf][2] = Ahi[r0 + 4]; ah[mf][3] = Ahi[r1 + 4];
            al[mf][0] = Alo[r0]; al[mf][1] = Alo[r1];
            al[mf][2] = Alo[r0 + 4]; al[mf][3] = Alo[r1 + 4];
        }
#pragma unroll
        for (int mf = 0; mf < 4; mf++)
#pragma unroll
            for (int nf = 0; nf < 4; nf++) {
                MMA(c[mf][nf], ah[mf], bh[nf]);
                MMA(c[mf][nf], ah[mf], bl[nf]);
                MMA(c[mf][nf], al[mf], bh[nf]);
            }
    }

    __half* op = g_qk + ((size_t)b * 256 + mt * 128 + wm) * NPOS + n0 + wn;
#pragma unroll
    for (int mf = 0; mf < 4; mf++)
#pragma unroll
        for (int nf = 0; nf < 4; nf++) {
            int col = nf * 8 + tig * 2;
            *(__half2*)(op + (size_t)(mf * 16 + g) * NPOS + col) =
                __floats2half2_rn(c[mf][nf][0], c[mf][nf][1]);
            *(__half2*)(op + (size_t)(mf * 16 + g + 8) * NPOS + col) =
                __floats2half2_rn(c[mf][nf][2], c[mf][nf][3]);
        }
}

// ---------------------------------------------------------------------------
// ATT2: partial (unnormalized) A over 128 positions. grid (9, 32, 8), 128 thr.
// q,k read as fp16.
// ---------------------------------------------------------------------------
#define A2_PAD 132
#define A2_ARR (DHEAD * A2_PAD)
#define A2_SMEM (4 * A2_ARR * 4)

__global__ __launch_bounds__(128, 3) void att_a_kernel() {
    extern __shared__ uint32_t sm2[];
    uint32_t* Eqh = sm2;
    uint32_t* Eql = Eqh + A2_ARR;
    uint32_t* Ksh = Eql + A2_ARR;
    uint32_t* Ksl = Ksh + A2_ARR;
    float* Apart = (float*)sm2;   // alias after mma: [4][32][33]

    const int ch = blockIdx.x, g = blockIdx.y, sub = blockIdx.z;
    const int gc = g * NCH + ch;
    const int b = g >> 2, head = g & 3;
    const int tid = threadIdx.x, lane = tid & 31, wrp = tid >> 5;
    const int j = tid;

    const __half* qbase = g_qk + ((size_t)(b * 256 + head * DHEAD)) * NPOS + ch * CHUNK + sub * 128;
    const __half* kbase = qbase + (size_t)128 * NPOS;

    float kr[DHEAD];
#pragma unroll
    for (int d = 0; d < DHEAD; d++) kr[d] = __half2float(kbase[(size_t)d * NPOS + j]);
    float km = -1e30f;
#pragma unroll
    for (int d = 0; d < DHEAD; d++) km = fmaxf(km, kr[d]);
    float ks = 0.f;
#pragma unroll
    for (int d = 0; d < DHEAD; d++) { kr[d] = __expf(kr[d] - km); ks += kr[d]; }
    float kinv = 1.0f / ks;
#pragma unroll
    for (int d = 0; d < DHEAD; d++) {
        float v = kr[d] * kinv;
        uint32_t h = f2tf(v);
        Ksh[d * A2_PAD + j] = h;
        Ksl[d * A2_PAD + j] = f2tf(v - __uint_as_float(h));
    }

    float qr[DHEAD];
#pragma unroll
    for (int d = 0; d < DHEAD; d++) qr[d] = __half2float(qbase[(size_t)d * NPOS + j]);
#pragma unroll
    for (int d = 0; d < DHEAD; d++) {
        float v = __expf(qr[d]);
        uint32_t h = f2tf(v);
        Eqh[d * A2_PAD + j] = h;
        Eql[d * A2_PAD + j] = f2tf(v - __uint_as_float(h));
    }
    __syncthreads();

    const int gq = lane >> 2, tig = lane & 3;
    float acc[2][4][4];
#pragma unroll
    for (int i = 0; i < 2; i++)
#pragma unroll
        for (int jj = 0; jj < 4; jj++)
#pragma unroll
            for (int q = 0; q < 4; q++) acc[i][jj][q] = 0.f;

#pragma unroll
    for (int kk = 0; kk < 4; kk++) {
        const int kb = (wrp * 4 + kk) * 8;
        uint32_t ah[2][4], al[2][4];
#pragma unroll
        for (int mf = 0; mf < 2; mf++) {
            int r0 = (mf * 16 + gq) * A2_PAD + kb + tig;
            int r1 = r0 + 8 * A2_PAD;
            ah[mf][0] = Eqh[r0]; ah[mf][1] = Eqh[r1];
            ah[mf][2] = Eqh[r0 + 4]; ah[mf][3] = Eqh[r1 + 4];
            al[mf][0] = Eql[r0]; al[mf][1] = Eql[r1];
            al[mf][2] = Eql[r0 + 4]; al[mf][3] = Eql[r1 + 4];
        }
        uint32_t bh[4][2], bl[4][2];
#pragma unroll
        for (int nf = 0; nf < 4; nf++) {
            int c0 = (nf * 8 + gq) * A2_PAD + kb + tig;
            bh[nf][0] = Ksh[c0]; bh[nf][1] = Ksh[c0 + 4];
            bl[nf][0] = Ksl[c0]; bl[nf][1] = Ksl[c0 + 4];
        }
#pragma unroll
        for (int mf = 0; mf < 2; mf++)
#pragma unroll
            for (int nf = 0; nf < 4; nf++) {
                MMA(acc[mf][nf], ah[mf], bh[nf]);
                MMA(acc[mf][nf], ah[mf], bl[nf]);
                MMA(acc[mf][nf], al[mf], bh[nf]);
            }
    }
    __syncthreads();

#pragma unroll
    for (int mf = 0; mf < 2; mf++)
#pragma unroll
        for (int nf = 0; nf < 4; nf++) {
            int row = mf * 16 + gq, col = nf * 8 + tig * 2;
            Apart[(wrp * 32 + row) * 33 + col]     = acc[mf][nf][0];
            Apart[(wrp * 32 + row) * 33 + col + 1] = acc[mf][nf][1];
            Apart[(wrp * 32 + row + 8) * 33 + col]     = acc[mf][nf][2];
            Apart[(wrp * 32 + row + 8) * 33 + col + 1] = acc[mf][nf][3];
        }
    __syncthreads();

    float* out = g_Apart[gc][sub];
#pragma unroll
    for (int r = 0; r < 8; r++) {
        int idx = tid + 128 * r;
        int d = idx >> 5, dp = idx & 31;
        float s = 0.f;
#pragma unroll
        for (int w = 0; w < 4; w++) s += Apart[(w * 32 + d) * 33 + dp];
        out[idx] = s;
    }
}

// ---------------------------------------------------------------------------
// WEFF: per (ch, b, z): A-reduce (redundant), 1/Zq, scale; then this CTA's
// 16-row o-slice of Weff and W2, split hi/lo. grid (9, 8, 4), 256 threads.
// ---------------------------------------------------------------------------
#define W2_A    0                     // [4*32*33] = 4224
#define W2_WV   4224                  // [128][68] = 8704
#define W2_WO   12928                 // [16][132] = 2112
#define W2_WE   15040                 // [16][132] = 2112
#define W2_SMEM_WORDS 17152
#define W2_SMEM (W2_SMEM_WORDS * 4)

__global__ __launch_bounds__(256, 2) void weff_kernel(const float* __restrict__ Wqkv,
                                                      const float* __restrict__ Wout) {
    extern __shared__ float wsm[];
    __shared__ float rinv_s[128];
    const int ch = blockIdx.x, b = blockIdx.y, z = blockIdx.z;
    const int cc = b * NCH + ch;
    const int tid = threadIdx.x;

    // reduce A partials for all 4 heads (redundant across z — L2-hot)
#pragma unroll
    for (int r = 0; r < 16; r++) {
        int idx = tid + 256 * r;
        int head = idx >> 10, e = idx & 1023;
        int d = e >> 5, dp = e & 31;
        const float* ap = g_Apart[(b * HEADS + head) * NCH + ch][0] + e;
        float s = 0.f;
#pragma unroll
        for (int sub = 0; sub < 8; sub++) s += ap[sub * DHEAD * DHEAD];
        wsm[W2_A + (head * 32 + d) * 33 + dp] = s;
    }
    // stage Wv [128][64]
#pragma unroll
    for (int r = 0; r < 8; r++) {
        int idx = tid + 256 * r;
        int ic = idx >> 4, c4 = (idx & 15) * 4;
        float4 v = *(const float4*)(Wqkv + (size_t)(2 * INNER + ic) * CDIM + c4);
        float* d = wsm + W2_WV + ic * 68 + c4;
        d[0] = v.x; d[1] = v.y; d[2] = v.z; d[3] = v.w;
    }
    // stage Wout slice [16][128] for rows z*16..z*16+15
#pragma unroll
    for (int r = 0; r < 2; r++) {
        int idx = tid + 256 * r;
        int o = idx >> 5, ic4 = (idx & 31) * 4;
        float4 v = *(const float4*)(Wout + (size_t)(z * 16 + o) * INNER + ic4);
        float* d = wsm + W2_WO + o * 132 + ic4;
        d[0] = v.x; d[1] = v.y; d[2] = v.z; d[3] = v.w;
    }
    __syncthreads();

    // 1/Zq per (head, d)
    if (tid < 128) {
        float s = 0.f;
#pragma unroll
        for (int dp = 0; dp < DHEAD; dp++) s += wsm[W2_A + tid * 33 + dp];
        rinv_s[tid] = 1.0f / s;
    }
    __syncthreads();
#pragma unroll
    for (int r = 0; r < 16; r++) {
        int idx = tid + 256 * r;
        int row = idx >> 5, dp = idx & 31;
        wsm[W2_A + row * 33 + dp] *= rinv_s[row];
    }
    __syncthreads();

    // Weff slice: [16][128]
#pragma unroll
    for (int r = 0; r < 8; r++) {
        int idx = tid + 256 * r;
        int o = idx >> 7, ic = idx & 127, head = ic >> 5, dp = ic & 31;
        float acc = 0.f;
#pragma unroll
        for (int d = 0; d < DHEAD; d++)
            acc += wsm[W2_WO + o * 132 + head * 32 + d] * wsm[W2_A + (head * 32 + d) * 33 + dp];
        wsm[W2_WE + o * 132 + ic] = acc;
    }
    __syncthreads();

    // W2 slice: [16][64]; thread -> (o_local = tid>>4, 4 cols at (tid&15)*4)
    const int ol = tid >> 4, c0 = (tid & 15) * 4;
    float w2[4] = {0.f, 0.f, 0.f, 0.f};
#pragma unroll
    for (int ic = 0; ic < INNER; ic++) {
        float we = wsm[W2_WE + ol * 132 + ic];
        const float* wv = wsm + W2_WV + ic * 68 + c0;
        w2[0] += we * wv[0];
        w2[1] += we * wv[1];
        w2[2] += we * wv[2];
        w2[3] += we * wv[3];
    }
    const int og = z * 16 + ol;
#pragma unroll
    for (int i = 0; i < 4; i++) {
        uint32_t h = f2tf(w2[i]);
        *(uint32_t*)&g_W2[cc][0][og][c0 + i] = h;
        *(uint32_t*)&g_W2[cc][1][og][c0 + i] = f2tf(w2[i] - __uint_as_float(h));
    }
}

// ---------------------------------------------------------------------------
// K3'' (fused): y = W2(b,ch) @ x + b_out, groupnorm partials. (unchanged R10)
// CTA tile [64 M x 128 N], K=64. grid (72, 8), 256 threads, occ 2.
// ---------------------------------------------------------------------------
#define K3_PAD 68
#define K3_SMEM (64 * K3_PAD * 2 * 4)

__global__ __launch_bounds__(256, 2) void outproj_mma_kernel(const float* __restrict__ x,
                                                             const float* __restrict__ bout,
                                                             float* __restrict__ y) {
    extern __shared__ uint32_t smu[];
    uint32_t* Ahi = smu;
    uint32_t* Alo = Ahi + 64 * K3_PAD;
    __shared__ float swp[8][8][2];

    const int b = blockIdx.y, n0 = blockIdx.x * 128, tid = threadIdx.x;
    const int cc = b * NCH + (n0 / CHUNK);

    for (int idx = tid; idx < 64 * 16; idx += 256) {
        int row = idx >> 4, c4 = (idx & 15) * 4;
        float4 h4 = *(const float4*)(&g_W2[cc][0][row][c4]);
        float4 l4 = *(const float4*)(&g_W2[cc][1][row][c4]);
        Ahi[row * K3_PAD + c4]     = __float_as_uint(h4.x);
        Ahi[row * K3_PAD + c4 + 1] = __float_as_uint(h4.y);
        Ahi[row * K3_PAD + c4 + 2] = __float_as_uint(h4.z);
        Ahi[row * K3_PAD + c4 + 3] = __float_as_uint(h4.w);
        Alo[row * K3_PAD + c4]     = __float_as_uint(l4.x);
        Alo[row * K3_PAD + c4 + 1] = __float_as_uint(l4.y);
        Alo[row * K3_PAD + c4 + 2] = __float_as_uint(l4.z);
        Alo[row * K3_PAD + c4 + 3] = __float_as_uint(l4.w);
    }
    __syncthreads();

    const int wid = tid >> 5, lane = tid & 31, g = lane >> 2, tig = lane & 3;
    const int wn = wid * 16;
    const float* xb = x + (size_t)b * CDIM * NPOS + n0;

    float acc[4][2][4];
#pragma unroll
    for (int i = 0; i < 4; i++)
#pragma unroll
        for (int j = 0; j < 2; j++)
#pragma unroll
            for (int q = 0; q < 4; q++) acc[i][j][q] = 0.f;

#pragma unroll
    for (int k8 = 0; k8 < 8; k8++) {
        const int kb = k8 * 8;
        const float* xr0 = xb + (size_t)(kb + tig) * NPOS;
        const float* xr1 = xr0 + 4 * NPOS;
        uint32_t bh[2][2], bl[2][2];
#pragma unroll
        for (int nf = 0; nf < 2; nf++) {
            int col = wn + nf * 8 + g;
            float v0 = __ldg(xr0 + col);
            float v1 = __ldg(xr1 + col);
            uint32_t h0 = f2tf(v0), h1 = f2tf(v1);
            bh[nf][0] = h0; bh[nf][1] = h1;
            bl[nf][0] = f2tf(v0 - __uint_as_float(h0));
            bl[nf][1] = f2tf(v1 - __uint_as_float(h1));
        }
        uint32_t ah[4][4], al[4][4];
#pragma unroll
        for (int mf = 0; mf < 4; mf++) {
            int r0 = (mf * 16 + g) * K3_PAD + kb + tig;
            int r1 = r0 + 8 * K3_PAD;
            ah[mf][0] = Ahi[r0]; ah[mf][1] = Ahi[r1];
            ah[mf][2] = Ahi[r0 + 4]; ah[mf][3] = Ahi[r1 + 4];
            al[mf][0] = Alo[r0]; al[mf][1] = Alo[r1];
            al[mf][2] = Alo[r0 + 4]; al[mf][3] = Alo[r1 + 4];
        }
#pragma unroll
        for (int mf = 0; mf < 4; mf++)
#pragma unroll
            for (int nf = 0; nf < 2; nf++) {
                MMA(acc[mf][nf], ah[mf], bh[nf]);
                MMA(acc[mf][nf], ah[mf], bl[nf]);
                MMA(acc[mf][nf], al[mf], bh[nf]);
            }
    }

    float gs[8], gq[8];
#pragma unroll
    for (int i = 0; i < 8; i++) { gs[i] = 0.f; gq[i] = 0.f; }

    float* yp = y + (size_t)b * CDIM * NPOS + n0 + wn;
#pragma unroll
    for (int mf = 0; mf < 4; mf++) {
        float bias0 = __ldg(bout + mf * 16 + g);
        float bias1 = __ldg(bout + mf * 16 + g + 8);
#pragma unroll
        for (int nf = 0; nf < 2; nf++) {
            int col = nf * 8 + tig * 2;
            float v0 = acc[mf][nf][0] + bias0, v1 = acc[mf][nf][1] + bias0;
            float v2 = acc[mf][nf][2] + bias1, v3 = acc[mf][nf][3] + bias1;
            *(float2*)(yp + (size_t)(mf * 16 + g) * NPOS + col) = make_float2(v0, v1);
            *(float2*)(yp + (size_t)(mf * 16 + g + 8) * NPOS + col) = make_float2(v2, v3);
            gs[2 * mf]     += v0 + v1;
            gq[2 * mf]     += v0 * v0 + v1 * v1;
            gs[2 * mf + 1] += v2 + v3;
            gq[2 * mf + 1] += v2 * v2 + v3 * v3;
        }
    }

#pragma unroll
    for (int gr = 0; gr < 8; gr++) {
        float s = gs[gr], q = gq[gr];
        for (int off = 16; off; off >>= 1) {
            s += __shfl_xor_sync(0xffffffffu, s, off);
            q += __shfl_xor_sync(0xffffffffu, q, off);
        }
        if (lane == 0) { swp[wid][gr][0] = s; swp[wid][gr][1] = q; }
    }
    __syncthreads();
    if (tid < 16) {
        int gr = tid >> 1, qq = tid & 1;
        float s = 0.f;
#pragma unroll
        for (int w = 0; w < 8; w++) s += swp[w][gr][qq];
        g_part[b][gr][blockIdx.x][qq] = s;
    }
}

// ---------------------------------------------------------------------------
// K4: groupnorm finalize. grid (36, 8), 256 threads. (unchanged R10)
// ---------------------------------------------------------------------------
__global__ __launch_bounds__(256, 4) void gnorm_kernel(float* __restrict__ y,
                                                       const float* __restrict__ gamma,
                                                       const float* __restrict__ beta) {
    __shared__ float tmp[8][2];
    __shared__ float mu[8], rs[8];
    const int b = blockIdx.y, n0 = blockIdx.x * 256, tid = threadIdx.x;

    if (tid < 16) {
        int g = tid >> 1, qq = tid & 1;
        float s = 0.f;
        for (int t = 0; t < GN_TILES; t++) s += g_part[b][g][t][qq];
        tmp[g][qq] = s;
    }
    __syncthreads();
    if (tid < 8) {
        const float invn = 1.0f / (8.0f * NPOS);
        float m = tmp[tid][0] * invn;
        float v = tmp[tid][1] * invn - m * m;
        mu[tid] = m;
        rs[tid] = rsqrtf(v + 1e-5f);
    }
    __syncthreads();

    const int col4 = tid & 63, crow = tid >> 6;
    float* yb = y + (size_t)b * CDIM * NPOS + n0 + col4 * 4;
#pragma unroll
    for (int c = crow; c < CDIM; c += 4) {
        float4* p = (float4*)(yb + (size_t)c * NPOS);
        float4 v = *p;
        int g = c >> 3;
        float sc = rs[g] * __ldg(gamma + c);
        float sh = __ldg(beta + c) - mu[g] * sc;
        v.x = v.x * sc + sh;
        v.y = v.y * sc + sh;
        v.z = v.z * sc + sh;
        v.w = v.w * sc + sh;
        *p = v;
    }
}

// ---------------------------------------------------------------------------
extern "C" void kernel_launch(void* const* d_in, const int* in_sizes, int n_in,
                              void* d_out, int out_size) {
    const float* x     = (const float*)d_in[0];
    const float* Wqkv  = (const float*)d_in[1];
    const float* Wout  = (const float*)d_in[2];
    const float* bout  = (const float*)d_in[3];
    const float* gamma = (const float*)d_in[4];
    const float* beta  = (const float*)d_in[5];
    float* y = (float*)d_out;

    cudaFuncSetAttribute(qkv_mma_kernel, cudaFuncAttributeMaxDynamicSharedMemorySize, K1_SMEM);
    cudaFuncSetAttribute(att_a_kernel, cudaFuncAttributeMaxDynamicSharedMemorySize, A2_SMEM);
    cudaFuncSetAttribute(weff_kernel, cudaFuncAttributeMaxDynamicSharedMemorySize, W2_SMEM);
    cudaFuncSetAttribute(outproj_mma_kernel, cudaFuncAttributeMaxDynamicSharedMemorySize, K3_SMEM);

    qkv_mma_kernel<<<dim3(72, 2, B_), 256, K1_SMEM>>>(x, Wqkv);
    att_a_kernel<<<dim3(NCH, 32, 8), 128, A2_SMEM>>>();
    weff_kernel<<<dim3(NCH, B_, 4), 256, W2_SMEM>>>(Wqkv, Wout);
    outproj_mma_kernel<<<dim3(GN_TILES, B_), 256, K3_SMEM>>>(x, bout, y);
    gnorm_kernel<<<dim3(36, B_), 256>>>(y, gamma, beta);
}

// round 12
// speedup vs baseline: 1.4228x; 1.1686x over previous
#include <cuda_runtime.h>
#include <cuda_fp16.h>
#include <cstdint>

// Problem constants
#define B_     8
#define CDIM   64
#define NPOS   9216      // 96*96
#define INNER  128
#define O3     384       // 3*INNER
#define HEADS  4
#define DHEAD  32
#define NCH    9
#define CHUNK  1024
#define NGC    (32 * NCH)   // 288 (g, ch) pairs
#define GN_TILES 72

// Scratch (device globals — no allocations allowed)
__device__ __align__(16) __half g_qk[(size_t)B_ * 256 * NPOS];      // [b][o][n], o<256 (q,k), fp16
__device__ float g_part[B_][8][GN_TILES][2];                        // groupnorm partials
__device__ __align__(16) float g_Apart[NGC][8][DHEAD * DHEAD];      // partial A (unnormalized)
__device__ __align__(16) float g_W2[B_ * NCH][2][CDIM][CDIM];       // fused weights hi/lo

// ---------------------------------------------------------------------------
__device__ __forceinline__ uint32_t f2tf(float x) {
    uint32_t r;
    asm("cvt.rna.tf32.f32 %0, %1;" : "=r"(r) : "f"(x));
    return r;
}

// tf32 m16n8k8 (used by outproj)
#define MMA(d, a, b)                                                          \
    asm volatile(                                                             \
        "mma.sync.aligned.m16n8k8.row.col.f32.tf32.tf32.f32 "                 \
        "{%0,%1,%2,%3},{%4,%5,%6,%7},{%8,%9},{%0,%1,%2,%3};"                  \
        : "+f"((d)[0]), "+f"((d)[1]), "+f"((d)[2]), "+f"((d)[3])              \
        : "r"((a)[0]), "r"((a)[1]), "r"((a)[2]), "r"((a)[3]),                 \
          "r"((b)[0]), "r"((b)[1]))

// fp16 m16n8k16, f32 accum
#define MMA16(d, a, b)                                                        \
    asm volatile(                                                             \
        "mma.sync.aligned.m16n8k16.row.col.f32.f16.f16.f32 "                  \
        "{%0,%1,%2,%3},{%4,%5,%6,%7},{%8,%9},{%0,%1,%2,%3};"                  \
        : "+f"((d)[0]), "+f"((d)[1]), "+f"((d)[2]), "+f"((d)[3])              \
        : "r"((a)[0]), "r"((a)[1]), "r"((a)[2]), "r"((a)[3]),                 \
          "r"((b)[0]), "r"((b)[1]))

__device__ __forceinline__ uint32_t pack_h2(float v0, float v1) {
    __half2 h = __floats2half2_rn(v0, v1);
    return *(uint32_t*)&h;
}
// hi/lo fp16 split of a float pair (hi = rn(x), lo = rn(x - hi))
__device__ __forceinline__ void split2(float v0, float v1, uint32_t& hi, uint32_t& lo) {
    __half h0 = __float2half_rn(v0), h1 = __float2half_rn(v1);
    hi = (uint32_t)__half_as_ushort(h0) | ((uint32_t)__half_as_ushort(h1) << 16);
    float l0 = v0 - __half2float(h0);
    float l1 = v1 - __half2float(h1);
    lo = (uint32_t)__half_as_ushort(__float2half_rn(l0)) |
         ((uint32_t)__half_as_ushort(__float2half_rn(l1)) << 16);
}

// ---------------------------------------------------------------------------
// K1 (fp16x3 mma): qk[b][o][n] = sum_c W_qkv[o][c] * x[b][c][n], o < 256.
// A (W, hi/lo half2) in smem [128][36 half2-words]; B (x) streamed, split.
// CTA tile [128 M x 128 N], K=64 (4 x k16). grid (72, 2, 8), 256 thr, occ 2.
// ---------------------------------------------------------------------------
#define K1_PADW 36
#define K1_SMEM (128 * K1_PADW * 2 * 4)

__global__ __launch_bounds__(256, 2) void qkv_mma_kernel(const float* __restrict__ x,
                                                         const float* __restrict__ Wq) {
    extern __shared__ uint32_t smu[];
    uint32_t* Ahi = smu;                  // [128][36] half2 words
    uint32_t* Alo = Ahi + 128 * K1_PADW;

    const int b = blockIdx.z, mt = blockIdx.y, n0 = blockIdx.x * 128;
    const int tid = threadIdx.x;

    // stage + split W tile [128 M x 64 K] as half2 words
    for (int idx = tid; idx < 128 * 16; idx += 256) {
        int row = idx >> 4, c4 = (idx & 15) * 4;
        float4 w = *(const float4*)(Wq + (size_t)(mt * 128 + row) * CDIM + c4);
        int w0 = c4 >> 1;
        uint32_t h, l;
        split2(w.x, w.y, h, l);
        Ahi[row * K1_PADW + w0] = h; Alo[row * K1_PADW + w0] = l;
        split2(w.z, w.w, h, l);
        Ahi[row * K1_PADW + w0 + 1] = h; Alo[row * K1_PADW + w0 + 1] = l;
    }
    __syncthreads();

    const int wid = tid >> 5, lane = tid & 31, g = lane >> 2, tig = lane & 3;
    const int wm = (wid >> 2) * 64, wn = (wid & 3) * 32;
    const float* xb = x + (size_t)b * CDIM * NPOS + n0;

    float c[4][4][4];
#pragma unroll
    for (int i = 0; i < 4; i++)
#pragma unroll
        for (int j = 0; j < 4; j++)
#pragma unroll
            for (int q = 0; q < 4; q++) c[i][j][q] = 0.f;

#pragma unroll
    for (int k16 = 0; k16 < 4; k16++) {
        const int kb = k16 * 16, kb2 = k16 * 8;
        // B fragments: rows kb+2tig, +1, +8, +9 ; cols wn+nf*8+g
        const float* r0 = xb + (size_t)(kb + 2 * tig) * NPOS;
        const float* r1 = r0 + NPOS;
        const float* r8 = r0 + 8 * NPOS;
        const float* r9 = r0 + 9 * NPOS;
        uint32_t bh[4][2], bl[4][2];
#pragma unroll
        for (int nf = 0; nf < 4; nf++) {
            int col = wn + nf * 8 + g;
            split2(__ldg(r0 + col), __ldg(r1 + col), bh[nf][0], bl[nf][0]);
            split2(__ldg(r8 + col), __ldg(r9 + col), bh[nf][1], bl[nf][1]);
        }
        uint32_t ah[4][4], al[4][4];
#pragma unroll
        for (int mf = 0; mf < 4; mf++) {
            int base = (wm + mf * 16 + g) * K1_PADW + kb2 + tig;
            int base8 = base + 8 * K1_PADW;
            ah[mf][0] = Ahi[base];     ah[mf][1] = Ahi[base8];
            ah[mf][2] = Ahi[base + 4]; ah[mf][3] = Ahi[base8 + 4];
            al[mf][0] = Alo[base];     al[mf][1] = Alo[base8];
            al[mf][2] = Alo[base + 4]; al[mf][3] = Alo[base8 + 4];
        }
#pragma unroll
        for (int mf = 0; mf < 4; mf++)
#pragma unroll
            for (int nf = 0; nf < 4; nf++) {
                MMA16(c[mf][nf], ah[mf], bh[nf]);
                MMA16(c[mf][nf], ah[mf], bl[nf]);
                MMA16(c[mf][nf], al[mf], bh[nf]);
            }
    }

    __half* op = g_qk + ((size_t)b * 256 + mt * 128 + wm) * NPOS + n0 + wn;
#pragma unroll
    for (int mf = 0; mf < 4; mf++)
#pragma unroll
        for (int nf = 0; nf < 4; nf++) {
            int col = nf * 8 + tig * 2;
            *(__half2*)(op + (size_t)(mf * 16 + g) * NPOS + col) =
                __floats2half2_rn(c[mf][nf][0], c[mf][nf][1]);
            *(__half2*)(op + (size_t)(mf * 16 + g + 8) * NPOS + col) =
                __floats2half2_rn(c[mf][nf][2], c[mf][nf][3]);
        }
}

// ---------------------------------------------------------------------------
// ATT2 (fp16 mma): partial A over 128 positions. grid (9, 32, 8), 128 threads.
// Eq, Ks staged as fp16 in smem ([32][68 half2-words] each); single fp16 mma.
// ---------------------------------------------------------------------------
#define A2_PADW 68
#define A2_WORDS (DHEAD * A2_PADW)            // 2176 per array
#define A2_SMEM_WORDS (2 * A2_WORDS)          // 4352 (Apart alias needs 4224)
#define A2_SMEM (A2_SMEM_WORDS * 4)

__global__ __launch_bounds__(128, 4) void att_a_kernel() {
    extern __shared__ uint32_t sm2[];
    uint32_t* Eq16 = sm2;                 // [32][68] half2 words
    uint32_t* Ks16 = sm2 + A2_WORDS;
    float* Apart = (float*)sm2;           // alias after mma: [4][32][33]

    const int ch = blockIdx.x, g = blockIdx.y, sub = blockIdx.z;
    const int gc = g * NCH + ch;
    const int b = g >> 2, head = g & 3;
    const int tid = threadIdx.x, lane = tid & 31, wrp = tid >> 5;
    const int j = tid;

    const __half* qbase = g_qk + ((size_t)(b * 256 + head * DHEAD)) * NPOS + ch * CHUNK + sub * 128;
    const __half* kbase = qbase + (size_t)128 * NPOS;

    __half* EqH = (__half*)Eq16;          // halves, row stride 136
    __half* KsH = (__half*)Ks16;

    float kr[DHEAD];
#pragma unroll
    for (int d = 0; d < DHEAD; d++) kr[d] = __half2float(kbase[(size_t)d * NPOS + j]);
    float km = -1e30f;
#pragma unroll
    for (int d = 0; d < DHEAD; d++) km = fmaxf(km, kr[d]);
    float ks = 0.f;
#pragma unroll
    for (int d = 0; d < DHEAD; d++) { kr[d] = __expf(kr[d] - km); ks += kr[d]; }
    float kinv = 1.0f / ks;
#pragma unroll
    for (int d = 0; d < DHEAD; d++)
        KsH[d * (2 * A2_PADW) + j] = __float2half_rn(kr[d] * kinv);

    float qr[DHEAD];
#pragma unroll
    for (int d = 0; d < DHEAD; d++) qr[d] = __half2float(qbase[(size_t)d * NPOS + j]);
#pragma unroll
    for (int d = 0; d < DHEAD; d++)
        EqH[d * (2 * A2_PADW) + j] = __float2half_rn(__expf(qr[d]));
    __syncthreads();

    const int gq = lane >> 2, tig = lane & 3;
    float acc[2][4][4];
#pragma unroll
    for (int i = 0; i < 2; i++)
#pragma unroll
        for (int jj = 0; jj < 4; jj++)
#pragma unroll
            for (int q = 0; q < 4; q++) acc[i][jj][q] = 0.f;

    // warp wrp covers K (positions) [wrp*32, wrp*32+32) = 2 k16 steps
#pragma unroll
    for (int s = 0; s < 2; s++) {
        const int kb2 = wrp * 16 + s * 8;   // half2-word base
        uint32_t a[2][4];
#pragma unroll
        for (int mf = 0; mf < 2; mf++) {
            int base = (mf * 16 + gq) * A2_PADW + kb2 + tig;
            int base8 = base + 8 * A2_PADW;
            a[mf][0] = Eq16[base];     a[mf][1] = Eq16[base8];
            a[mf][2] = Eq16[base + 4]; a[mf][3] = Eq16[base8 + 4];
        }
        uint32_t bfr[4][2];
#pragma unroll
        for (int nf = 0; nf < 4; nf++) {
            int base = (nf * 8 + gq) * A2_PADW + kb2 + tig;
            bfr[nf][0] = Ks16[base];
            bfr[nf][1] = Ks16[base + 4];
        }
#pragma unroll
        for (int mf = 0; mf < 2; mf++)
#pragma unroll
            for (int nf = 0; nf < 4; nf++)
                MMA16(acc[mf][nf], a[mf], bfr[nf]);
    }
    __syncthreads();

#pragma unroll
    for (int mf = 0; mf < 2; mf++)
#pragma unroll
        for (int nf = 0; nf < 4; nf++) {
            int row = mf * 16 + gq, col = nf * 8 + tig * 2;
            Apart[(wrp * 32 + row) * 33 + col]     = acc[mf][nf][0];
            Apart[(wrp * 32 + row) * 33 + col + 1] = acc[mf][nf][1];
            Apart[(wrp * 32 + row + 8) * 33 + col]     = acc[mf][nf][2];
            Apart[(wrp * 32 + row + 8) * 33 + col + 1] = acc[mf][nf][3];
        }
    __syncthreads();

    float* out = g_Apart[gc][sub];
#pragma unroll
    for (int r = 0; r < 8; r++) {
        int idx = tid + 128 * r;
        int d = idx >> 5, dp = idx & 31;
        float s = 0.f;
#pragma unroll
        for (int w = 0; w < 4; w++) s += Apart[(w * 32 + d) * 33 + dp];
        out[idx] = s;
    }
}

// ---------------------------------------------------------------------------
// WEFF: per (ch, b, z): A-reduce (redundant), 1/Zq, scale; 16-row o-slice of
// Weff and W2, split hi/lo. grid (9, 8, 4), 256 threads. (unchanged R11)
// ---------------------------------------------------------------------------
#define W2_A    0                     // [4*32*33] = 4224
#define W2_WV   4224                  // [128][68] = 8704
#define W2_WO   12928                 // [16][132] = 2112
#define W2_WE   15040                 // [16][132] = 2112
#define W2_SMEM_WORDS 17152
#define W2_SMEM (W2_SMEM_WORDS * 4)

__global__ __launch_bounds__(256, 2) void weff_kernel(const float* __restrict__ Wqkv,
                                                      const float* __restrict__ Wout) {
    extern __shared__ float wsm[];
    __shared__ float rinv_s[128];
    const int ch = blockIdx.x, b = blockIdx.y, z = blockIdx.z;
    const int cc = b * NCH + ch;
    const int tid = threadIdx.x;

#pragma unroll
    for (int r = 0; r < 16; r++) {
        int idx = tid + 256 * r;
        int head = idx >> 10, e = idx & 1023;
        int d = e >> 5, dp = e & 31;
        const float* ap = g_Apart[(b * HEADS + head) * NCH + ch][0] + e;
        float s = 0.f;
#pragma unroll
        for (int sub = 0; sub < 8; sub++) s += ap[sub * DHEAD * DHEAD];
        wsm[W2_A + (head * 32 + d) * 33 + dp] = s;
    }
#pragma unroll
    for (int r = 0; r < 8; r++) {
        int idx = tid + 256 * r;
        int ic = idx >> 4, c4 = (idx & 15) * 4;
        float4 v = *(const float4*)(Wqkv + (size_t)(2 * INNER + ic) * CDIM + c4);
        float* d = wsm + W2_WV + ic * 68 + c4;
        d[0] = v.x; d[1] = v.y; d[2] = v.z; d[3] = v.w;
    }
#pragma unroll
    for (int r = 0; r < 2; r++) {
        int idx = tid + 256 * r;
        int o = idx >> 5, ic4 = (idx & 31) * 4;
        float4 v = *(const float4*)(Wout + (size_t)(z * 16 + o) * INNER + ic4);
        float* d = wsm + W2_WO + o * 132 + ic4;
        d[0] = v.x; d[1] = v.y; d[2] = v.z; d[3] = v.w;
    }
    __syncthreads();

    if (tid < 128) {
        float s = 0.f;
#pragma unroll
        for (int dp = 0; dp < DHEAD; dp++) s += wsm[W2_A + tid * 33 + dp];
        rinv_s[tid] = 1.0f / s;
    }
    __syncthreads();
#pragma unroll
    for (int r = 0; r < 16; r++) {
        int idx = tid + 256 * r;
        int row = idx >> 5, dp = idx & 31;
        wsm[W2_A + row * 33 + dp] *= rinv_s[row];
    }
    __syncthreads();

#pragma unroll
    for (int r = 0; r < 8; r++) {
        int idx = tid + 256 * r;
        int o = idx >> 7, ic = idx & 127, head = ic >> 5, dp = ic & 31;
        float acc = 0.f;
#pragma unroll
        for (int d = 0; d < DHEAD; d++)
            acc += wsm[W2_WO + o * 132 + head * 32 + d] * wsm[W2_A + (head * 32 + d) * 33 + dp];
        wsm[W2_WE + o * 132 + ic] = acc;
    }
    __syncthreads();

    const int ol = tid >> 4, c0 = (tid & 15) * 4;
    float w2[4] = {0.f, 0.f, 0.f, 0.f};
#pragma unroll
    for (int ic = 0; ic < INNER; ic++) {
        float we = wsm[W2_WE + ol * 132 + ic];
        const float* wv = wsm + W2_WV + ic * 68 + c0;
        w2[0] += we * wv[0];
        w2[1] += we * wv[1];
        w2[2] += we * wv[2];
        w2[3] += we * wv[3];
    }
    const int og = z * 16 + ol;
#pragma unroll
    for (int i = 0; i < 4; i++) {
        uint32_t h = f2tf(w2[i]);
        *(uint32_t*)&g_W2[cc][0][og][c0 + i] = h;
        *(uint32_t*)&g_W2[cc][1][og][c0 + i] = f2tf(w2[i] - __uint_as_float(h));
    }
}

// ---------------------------------------------------------------------------
// K3'' (tf32x3 mma): y = W2(b,ch) @ x + b_out, groupnorm partials. (unchanged)
// CTA tile [64 M x 128 N], K=64. grid (72, 8), 256 threads, occ 2.
// ---------------------------------------------------------------------------
#define K3_PAD 68
#define K3_SMEM (64 * K3_PAD * 2 * 4)

__global__ __launch_bounds__(256, 2) void outproj_mma_kernel(const float* __restrict__ x,
                                                             const float* __restrict__ bout,
                                                             float* __restrict__ y) {
    extern __shared__ uint32_t smu[];
    uint32_t* Ahi = smu;
    uint32_t* Alo = Ahi + 64 * K3_PAD;
    __shared__ float swp[8][8][2];

    const int b = blockIdx.y, n0 = blockIdx.x * 128, tid = threadIdx.x;
    const int cc = b * NCH + (n0 / CHUNK);

    for (int idx = tid; idx < 64 * 16; idx += 256) {
        int row = idx >> 4, c4 = (idx & 15) * 4;
        float4 h4 = *(const float4*)(&g_W2[cc][0][row][c4]);
        float4 l4 = *(const float4*)(&g_W2[cc][1][row][c4]);
        Ahi[row * K3_PAD + c4]     = __float_as_uint(h4.x);
        Ahi[row * K3_PAD + c4 + 1] = __float_as_uint(h4.y);
        Ahi[row * K3_PAD + c4 + 2] = __float_as_uint(h4.z);
        Ahi[row * K3_PAD + c4 + 3] = __float_as_uint(h4.w);
        Alo[row * K3_PAD + c4]     = __float_as_uint(l4.x);
        Alo[row * K3_PAD + c4 + 1] = __float_as_uint(l4.y);
        Alo[row * K3_PAD + c4 + 2] = __float_as_uint(l4.z);
        Alo[row * K3_PAD + c4 + 3] = __float_as_uint(l4.w);
    }
    __syncthreads();

    const int wid = tid >> 5, lane = tid & 31, g = lane >> 2, tig = lane & 3;
    const int wn = wid * 16;
    const float* xb = x + (size_t)b * CDIM * NPOS + n0;

    float acc[4][2][4];
#pragma unroll
    for (int i = 0; i < 4; i++)
#pragma unroll
        for (int j = 0; j < 2; j++)
#pragma unroll
            for (int q = 0; q < 4; q++) acc[i][j][q] = 0.f;

#pragma unroll
    for (int k8 = 0; k8 < 8; k8++) {
        const int kb = k8 * 8;
        const float* xr0 = xb + (size_t)(kb + tig) * NPOS;
        const float* xr1 = xr0 + 4 * NPOS;
        uint32_t bh[2][2], bl[2][2];
#pragma unroll
        for (int nf = 0; nf < 2; nf++) {
            int col = wn + nf * 8 + g;
            float v0 = __ldg(xr0 + col);
            float v1 = __ldg(xr1 + col);
            uint32_t h0 = f2tf(v0), h1 = f2tf(v1);
            bh[nf][0] = h0; bh[nf][1] = h1;
            bl[nf][0] = f2tf(v0 - __uint_as_float(h0));
            bl[nf][1] = f2tf(v1 - __uint_as_float(h1));
        }
        uint32_t ah[4][4], al[4][4];
#pragma unroll
        for (int mf = 0; mf < 4; mf++) {
            int r0 = (mf * 16 + g) * K3_PAD + kb + tig;
            int r1 = r0 + 8 * K3_PAD;
            ah[mf][0] = Ahi[r0]; ah[mf][1] = Ahi[r1];
            ah[mf][2] = Ahi[r0 + 4]; ah[mf][3] = Ahi[r1 + 4];
            al[mf][0] = Alo[r0]; al[mf][1] = Alo[r1];
            al[mf][2] = Alo[r0 + 4]; al[mf][3] = Alo[r1 + 4];
        }
#pragma unroll
        for (int mf = 0; mf < 4; mf++)
#pragma unroll
            for (int nf = 0; nf < 2; nf++) {
                MMA(acc[mf][nf], ah[mf], bh[nf]);
                MMA(acc[mf][nf], ah[mf], bl[nf]);
                MMA(acc[mf][nf], al[mf], bh[nf]);
            }
    }

    float gs[8], gq[8];
#pragma unroll
    for (int i = 0; i < 8; i++) { gs[i] = 0.f; gq[i] = 0.f; }

    float* yp = y + (size_t)b * CDIM * NPOS + n0 + wn;
#pragma unroll
    for (int mf = 0; mf < 4; mf++) {
        float bias0 = __ldg(bout + mf * 16 + g);
        float bias1 = __ldg(bout + mf * 16 + g + 8);
#pragma unroll
        for (int nf = 0; nf < 2; nf++) {
            int col = nf * 8 + tig * 2;
            float v0 = acc[mf][nf][0] + bias0, v1 = acc[mf][nf][1] + bias0;
            float v2 = acc[mf][nf][2] + bias1, v3 = acc[mf][nf][3] + bias1;
            *(float2*)(yp + (size_t)(mf * 16 + g) * NPOS + col) = make_float2(v0, v1);
            *(float2*)(yp + (size_t)(mf * 16 + g + 8) * NPOS + col) = make_float2(v2, v3);
            gs[2 * mf]     += v0 + v1;
            gq[2 * mf]     += v0 * v0 + v1 * v1;
            gs[2 * mf + 1] += v2 + v3;
            gq[2 * mf + 1] += v2 * v2 + v3 * v3;
        }
    }

#pragma unroll
    for (int gr = 0; gr < 8; gr++) {
        float s = gs[gr], q = gq[gr];
        for (int off = 16; off; off >>= 1) {
            s += __shfl_xor_sync(0xffffffffu, s, off);
            q += __shfl_xor_sync(0xffffffffu, q, off);
        }
        if (lane == 0) { swp[wid][gr][0] = s; swp[wid][gr][1] = q; }
    }
    __syncthreads();
    if (tid < 16) {
        int gr = tid >> 1, qq = tid & 1;
        float s = 0.f;
#pragma unroll
        for (int w = 0; w < 8; w++) s += swp[w][gr][qq];
        g_part[b][gr][blockIdx.x][qq] = s;
    }
}

// ---------------------------------------------------------------------------
// K4: groupnorm finalize. grid (36, 8), 256 threads. (unchanged R11)
// ---------------------------------------------------------------------------
__global__ __launch_bounds__(256, 4) void gnorm_kernel(float* __restrict__ y,
                                                       const float* __restrict__ gamma,
                                                       const float* __restrict__ beta) {
    __shared__ float tmp[8][2];
    __shared__ float mu[8], rs[8];
    const int b = blockIdx.y, n0 = blockIdx.x * 256, tid = threadIdx.x;

    if (tid < 16) {
        int g = tid >> 1, qq = tid & 1;
        float s = 0.f;
        for (int t = 0; t < GN_TILES; t++) s += g_part[b][g][t][qq];
        tmp[g][qq] = s;
    }
    __syncthreads();
    if (tid < 8) {
        const float invn = 1.0f / (8.0f * NPOS);
        float m = tmp[tid][0] * invn;
        float v = tmp[tid][1] * invn - m * m;
        mu[tid] = m;
        rs[tid] = rsqrtf(v + 1e-5f);
    }
    __syncthreads();

    const int col4 = tid & 63, crow = tid >> 6;
    float* yb = y + (size_t)b * CDIM * NPOS + n0 + col4 * 4;
#pragma unroll
    for (int c = crow; c < CDIM; c += 4) {
        float4* p = (float4*)(yb + (size_t)c * NPOS);
        float4 v = *p;
        int g = c >> 3;
        float sc = rs[g] * __ldg(gamma + c);
        float sh = __ldg(beta + c) - mu[g] * sc;
        v.x = v.x * sc + sh;
        v.y = v.y * sc + sh;
        v.z = v.z * sc + sh;
        v.w = v.w * sc + sh;
        *p = v;
    }
}

// ---------------------------------------------------------------------------
extern "C" void kernel_launch(void* const* d_in, const int* in_sizes, int n_in,
                              void* d_out, int out_size) {
    const float* x     = (const float*)d_in[0];
    const float* Wqkv  = (const float*)d_in[1];
    const float* Wout  = (const float*)d_in[2];
    const float* bout  = (const float*)d_in[3];
    const float* gamma = (const float*)d_in[4];
    const float* beta  = (const float*)d_in[5];
    float* y = (float*)d_out;

    cudaFuncSetAttribute(qkv_mma_kernel, cudaFuncAttributeMaxDynamicSharedMemorySize, K1_SMEM);
    cudaFuncSetAttribute(att_a_kernel, cudaFuncAttributeMaxDynamicSharedMemorySize, A2_SMEM);
    cudaFuncSetAttribute(weff_kernel, cudaFuncAttributeMaxDynamicSharedMemorySize, W2_SMEM);
    cudaFuncSetAttribute(outproj_mma_kernel, cudaFuncAttributeMaxDynamicSharedMemorySize, K3_SMEM);

    qkv_mma_kernel<<<dim3(72, 2, B_), 256, K1_SMEM>>>(x, Wqkv);
    att_a_kernel<<<dim3(NCH, 32, 8), 128, A2_SMEM>>>();
    weff_kernel<<<dim3(NCH, B_, 4), 256, W2_SMEM>>>(Wqkv, Wout);
    outproj_mma_kernel<<<dim3(GN_TILES, B_), 256, K3_SMEM>>>(x, bout, y);
    gnorm_kernel<<<dim3(36, B_), 256>>>(y, gamma, beta);
}

// round 13
// speedup vs baseline: 1.4816x; 1.0413x over previous
#include <cuda_runtime.h>
#include <cuda_fp16.h>
#include <cstdint>

// Problem constants
#define B_     8
#define CDIM   64
#define NPOS   9216      // 96*96
#define INNER  128
#define O3     384       // 3*INNER
#define HEADS  4
#define DHEAD  32
#define NCH    9
#define CHUNK  1024
#define NGC    (32 * NCH)   // 288 (g, ch) pairs
#define GN_TILES 72

// Scratch (device globals — no allocations allowed)
__device__ __align__(16) __half g_qk[(size_t)B_ * 256 * NPOS];      // [b][o][n], o<256 (q,k), fp16
__device__ float g_part[B_][8][GN_TILES][2];                        // groupnorm partials
__device__ __align__(16) float g_Apart[NGC][8][DHEAD * DHEAD];      // partial A (unnormalized)
__device__ __align__(16) uint32_t g_W2h[B_ * NCH][2][CDIM][CDIM / 2]; // fused weights fp16 hi/lo (half2)

// ---------------------------------------------------------------------------
// fp16 m16n8k16, f32 accum
#define MMA16(d, a, b)                                                        \
    asm volatile(                                                             \
        "mma.sync.aligned.m16n8k16.row.col.f32.f16.f16.f32 "                  \
        "{%0,%1,%2,%3},{%4,%5,%6,%7},{%8,%9},{%0,%1,%2,%3};"                  \
        : "+f"((d)[0]), "+f"((d)[1]), "+f"((d)[2]), "+f"((d)[3])              \
        : "r"((a)[0]), "r"((a)[1]), "r"((a)[2]), "r"((a)[3]),                 \
          "r"((b)[0]), "r"((b)[1]))

// hi/lo fp16 split of a float pair (hi = rn(x), lo = rn(x - hi))
__device__ __forceinline__ void split2(float v0, float v1, uint32_t& hi, uint32_t& lo) {
    __half h0 = __float2half_rn(v0), h1 = __float2half_rn(v1);
    hi = (uint32_t)__half_as_ushort(h0) | ((uint32_t)__half_as_ushort(h1) << 16);
    float l0 = v0 - __half2float(h0);
    float l1 = v1 - __half2float(h1);
    lo = (uint32_t)__half_as_ushort(__float2half_rn(l0)) |
         ((uint32_t)__half_as_ushort(__float2half_rn(l1)) << 16);
}

// ---------------------------------------------------------------------------
// K1 (fp16x3 mma): qk[b][o][n] = sum_c W_qkv[o][c] * x[b][c][n], o < 256.
// (unchanged R12)
// ---------------------------------------------------------------------------
#define K1_PADW 36
#define K1_SMEM (128 * K1_PADW * 2 * 4)

__global__ __launch_bounds__(256, 2) void qkv_mma_kernel(const float* __restrict__ x,
                                                         const float* __restrict__ Wq) {
    extern __shared__ uint32_t smu[];
    uint32_t* Ahi = smu;                  // [128][36] half2 words
    uint32_t* Alo = Ahi + 128 * K1_PADW;

    const int b = blockIdx.z, mt = blockIdx.y, n0 = blockIdx.x * 128;
    const int tid = threadIdx.x;

    for (int idx = tid; idx < 128 * 16; idx += 256) {
        int row = idx >> 4, c4 = (idx & 15) * 4;
        float4 w = *(const float4*)(Wq + (size_t)(mt * 128 + row) * CDIM + c4);
        int w0 = c4 >> 1;
        uint32_t h, l;
        split2(w.x, w.y, h, l);
        Ahi[row * K1_PADW + w0] = h; Alo[row * K1_PADW + w0] = l;
        split2(w.z, w.w, h, l);
        Ahi[row * K1_PADW + w0 + 1] = h; Alo[row * K1_PADW + w0 + 1] = l;
    }
    __syncthreads();

    const int wid = tid >> 5, lane = tid & 31, g = lane >> 2, tig = lane & 3;
    const int wm = (wid >> 2) * 64, wn = (wid & 3) * 32;
    const float* xb = x + (size_t)b * CDIM * NPOS + n0;

    float c[4][4][4];
#pragma unroll
    for (int i = 0; i < 4; i++)
#pragma unroll
        for (int j = 0; j < 4; j++)
#pragma unroll
            for (int q = 0; q < 4; q++) c[i][j][q] = 0.f;

#pragma unroll
    for (int k16 = 0; k16 < 4; k16++) {
        const int kb = k16 * 16, kb2 = k16 * 8;
        const float* r0 = xb + (size_t)(kb + 2 * tig) * NPOS;
        const float* r1 = r0 + NPOS;
        const float* r8 = r0 + 8 * NPOS;
        const float* r9 = r0 + 9 * NPOS;
        uint32_t bh[4][2], bl[4][2];
#pragma unroll
        for (int nf = 0; nf < 4; nf++) {
            int col = wn + nf * 8 + g;
            split2(__ldg(r0 + col), __ldg(r1 + col), bh[nf][0], bl[nf][0]);
            split2(__ldg(r8 + col), __ldg(r9 + col), bh[nf][1], bl[nf][1]);
        }
        uint32_t ah[4][4], al[4][4];
#pragma unroll
        for (int mf = 0; mf < 4; mf++) {
            int base = (wm + mf * 16 + g) * K1_PADW + kb2 + tig;
            int base8 = base + 8 * K1_PADW;
            ah[mf][0] = Ahi[base];     ah[mf][1] = Ahi[base8];
            ah[mf][2] = Ahi[base + 4]; ah[mf][3] = Ahi[base8 + 4];
            al[mf][0] = Alo[base];     al[mf][1] = Alo[base8];
            al[mf][2] = Alo[base + 4]; al[mf][3] = Alo[base8 + 4];
        }
#pragma unroll
        for (int mf = 0; mf < 4; mf++)
#pragma unroll
            for (int nf = 0; nf < 4; nf++) {
                MMA16(c[mf][nf], ah[mf], bh[nf]);
                MMA16(c[mf][nf], ah[mf], bl[nf]);
                MMA16(c[mf][nf], al[mf], bh[nf]);
            }
    }

    __half* op = g_qk + ((size_t)b * 256 + mt * 128 + wm) * NPOS + n0 + wn;
#pragma unroll
    for (int mf = 0; mf < 4; mf++)
#pragma unroll
        for (int nf = 0; nf < 4; nf++) {
            int col = nf * 8 + tig * 2;
            *(__half2*)(op + (size_t)(mf * 16 + g) * NPOS + col) =
                __floats2half2_rn(c[mf][nf][0], c[mf][nf][1]);
            *(__half2*)(op + (size_t)(mf * 16 + g + 8) * NPOS + col) =
                __floats2half2_rn(c[mf][nf][2], c[mf][nf][3]);
        }
}

// ---------------------------------------------------------------------------
// ATT2 (fp16 mma): partial A over 128 positions. grid (9, 32, 8), 128 threads.
// (unchanged R12)
// ---------------------------------------------------------------------------
#define A2_PADW 68
#define A2_WORDS (DHEAD * A2_PADW)
#define A2_SMEM_WORDS (2 * A2_WORDS)
#define A2_SMEM (A2_SMEM_WORDS * 4)

__global__ __launch_bounds__(128, 4) void att_a_kernel() {
    extern __shared__ uint32_t sm2[];
    uint32_t* Eq16 = sm2;                 // [32][68] half2 words
    uint32_t* Ks16 = sm2 + A2_WORDS;
    float* Apart = (float*)sm2;           // alias after mma: [4][32][33]

    const int ch = blockIdx.x, g = blockIdx.y, sub = blockIdx.z;
    const int gc = g * NCH + ch;
    const int b = g >> 2, head = g & 3;
    const int tid = threadIdx.x, lane = tid & 31, wrp = tid >> 5;
    const int j = tid;

    const __half* qbase = g_qk + ((size_t)(b * 256 + head * DHEAD)) * NPOS + ch * CHUNK + sub * 128;
    const __half* kbase = qbase + (size_t)128 * NPOS;

    __half* EqH = (__half*)Eq16;
    __half* KsH = (__half*)Ks16;

    float kr[DHEAD];
#pragma unroll
    for (int d = 0; d < DHEAD; d++) kr[d] = __half2float(kbase[(size_t)d * NPOS + j]);
    float km = -1e30f;
#pragma unroll
    for (int d = 0; d < DHEAD; d++) km = fmaxf(km, kr[d]);
    float ks = 0.f;
#pragma unroll
    for (int d = 0; d < DHEAD; d++) { kr[d] = __expf(kr[d] - km); ks += kr[d]; }
    float kinv = 1.0f / ks;
#pragma unroll
    for (int d = 0; d < DHEAD; d++)
        KsH[d * (2 * A2_PADW) + j] = __float2half_rn(kr[d] * kinv);

    float qr[DHEAD];
#pragma unroll
    for (int d = 0; d < DHEAD; d++) qr[d] = __half2float(qbase[(size_t)d * NPOS + j]);
#pragma unroll
    for (int d = 0; d < DHEAD; d++)
        EqH[d * (2 * A2_PADW) + j] = __float2half_rn(__expf(qr[d]));
    __syncthreads();

    const int gq = lane >> 2, tig = lane & 3;
    float acc[2][4][4];
#pragma unroll
    for (int i = 0; i < 2; i++)
#pragma unroll
        for (int jj = 0; jj < 4; jj++)
#pragma unroll
            for (int q = 0; q < 4; q++) acc[i][jj][q] = 0.f;

#pragma unroll
    for (int s = 0; s < 2; s++) {
        const int kb2 = wrp * 16 + s * 8;
        uint32_t a[2][4];
#pragma unroll
        for (int mf = 0; mf < 2; mf++) {
            int base = (mf * 16 + gq) * A2_PADW + kb2 + tig;
            int base8 = base + 8 * A2_PADW;
            a[mf][0] = Eq16[base];     a[mf][1] = Eq16[base8];
            a[mf][2] = Eq16[base + 4]; a[mf][3] = Eq16[base8 + 4];
        }
        uint32_t bfr[4][2];
#pragma unroll
        for (int nf = 0; nf < 4; nf++) {
            int base = (nf * 8 + gq) * A2_PADW + kb2 + tig;
            bfr[nf][0] = Ks16[base];
            bfr[nf][1] = Ks16[base + 4];
        }
#pragma unroll
        for (int mf = 0; mf < 2; mf++)
#pragma unroll
            for (int nf = 0; nf < 4; nf++)
                MMA16(acc[mf][nf], a[mf], bfr[nf]);
    }
    __syncthreads();

#pragma unroll
    for (int mf = 0; mf < 2; mf++)
#pragma unroll
        for (int nf = 0; nf < 4; nf++) {
            int row = mf * 16 + gq, col = nf * 8 + tig * 2;
            Apart[(wrp * 32 + row) * 33 + col]     = acc[mf][nf][0];
            Apart[(wrp * 32 + row) * 33 + col + 1] = acc[mf][nf][1];
            Apart[(wrp * 32 + row + 8) * 33 + col]     = acc[mf][nf][2];
            Apart[(wrp * 32 + row + 8) * 33 + col + 1] = acc[mf][nf][3];
        }
    __syncthreads();

    float* out = g_Apart[gc][sub];
#pragma unroll
    for (int r = 0; r < 8; r++) {
        int idx = tid + 128 * r;
        int d = idx >> 5, dp = idx & 31;
        float s = 0.f;
#pragma unroll
        for (int w = 0; w < 4; w++) s += Apart[(w * 32 + d) * 33 + dp];
        out[idx] = s;
    }
}

// ---------------------------------------------------------------------------
// WEFF: per (ch, b, z): A-reduce (redundant), 1/Zq, scale; 16-row o-slice of
// Weff and W2 (fp16 hi/lo output). grid (9, 8, 4), 256 threads.
// ---------------------------------------------------------------------------
#define W2_A    0                     // [4*32*33] = 4224
#define W2_WV   4224                  // [128][68] = 8704
#define W2_WO   12928                 // [16][132] = 2112
#define W2_WE   15040                 // [16][132] = 2112
#define W2_SMEM_WORDS 17152
#define W2_SMEM (W2_SMEM_WORDS * 4)

__global__ __launch_bounds__(256, 2) void weff_kernel(const float* __restrict__ Wqkv,
                                                      const float* __restrict__ Wout) {
    extern __shared__ float wsm[];
    __shared__ float rinv_s[128];
    const int ch = blockIdx.x, b = blockIdx.y, z = blockIdx.z;
    const int cc = b * NCH + ch;
    const int tid = threadIdx.x;

#pragma unroll
    for (int r = 0; r < 16; r++) {
        int idx = tid + 256 * r;
        int head = idx >> 10, e = idx & 1023;
        int d = e >> 5, dp = e & 31;
        const float* ap = g_Apart[(b * HEADS + head) * NCH + ch][0] + e;
        float s = 0.f;
#pragma unroll
        for (int sub = 0; sub < 8; sub++) s += ap[sub * DHEAD * DHEAD];
        wsm[W2_A + (head * 32 + d) * 33 + dp] = s;
    }
#pragma unroll
    for (int r = 0; r < 8; r++) {
        int idx = tid + 256 * r;
        int ic = idx >> 4, c4 = (idx & 15) * 4;
        float4 v = *(const float4*)(Wqkv + (size_t)(2 * INNER + ic) * CDIM + c4);
        float* d = wsm + W2_WV + ic * 68 + c4;
        d[0] = v.x; d[1] = v.y; d[2] = v.z; d[3] = v.w;
    }
#pragma unroll
    for (int r = 0; r < 2; r++) {
        int idx = tid + 256 * r;
        int o = idx >> 5, ic4 = (idx & 31) * 4;
        float4 v = *(const float4*)(Wout + (size_t)(z * 16 + o) * INNER + ic4);
        float* d = wsm + W2_WO + o * 132 + ic4;
        d[0] = v.x; d[1] = v.y; d[2] = v.z; d[3] = v.w;
    }
    __syncthreads();

    if (tid < 128) {
        float s = 0.f;
#pragma unroll
        for (int dp = 0; dp < DHEAD; dp++) s += wsm[W2_A + tid * 33 + dp];
        rinv_s[tid] = 1.0f / s;
    }
    __syncthreads();
#pragma unroll
    for (int r = 0; r < 16; r++) {
        int idx = tid + 256 * r;
        int row = idx >> 5, dp = idx & 31;
        wsm[W2_A + row * 33 + dp] *= rinv_s[row];
    }
    __syncthreads();

#pragma unroll
    for (int r = 0; r < 8; r++) {
        int idx = tid + 256 * r;
        int o = idx >> 7, ic = idx & 127, head = ic >> 5, dp = ic & 31;
        float acc = 0.f;
#pragma unroll
        for (int d = 0; d < DHEAD; d++)
            acc += wsm[W2_WO + o * 132 + head * 32 + d] * wsm[W2_A + (head * 32 + d) * 33 + dp];
        wsm[W2_WE + o * 132 + ic] = acc;
    }
    __syncthreads();

    const int ol = tid >> 4, c0 = (tid & 15) * 4;
    float w2[4] = {0.f, 0.f, 0.f, 0.f};
#pragma unroll
    for (int ic = 0; ic < INNER; ic++) {
        float we = wsm[W2_WE + ol * 132 + ic];
        const float* wv = wsm + W2_WV + ic * 68 + c0;
        w2[0] += we * wv[0];
        w2[1] += we * wv[1];
        w2[2] += we * wv[2];
        w2[3] += we * wv[3];
    }
    const int og = z * 16 + ol, w0 = c0 >> 1;
    uint32_t h, l;
    split2(w2[0], w2[1], h, l);
    g_W2h[cc][0][og][w0] = h;
    g_W2h[cc][1][og][w0] = l;
    split2(w2[2], w2[3], h, l);
    g_W2h[cc][0][og][w0 + 1] = h;
    g_W2h[cc][1][og][w0 + 1] = l;
}

// ---------------------------------------------------------------------------
// K3'' (fp16x3 mma): y = W2(b,ch) @ x + b_out, groupnorm partials.
// A (W2 fp16 hi/lo half2) in smem [64][36]; B (x) streamed + split.
// CTA tile [64 M x 128 N], K=64 (4 x k16). grid (72, 8), 256 threads, occ 2.
// ---------------------------------------------------------------------------
#define K3_PADW 36
#define K3_SMEM (64 * K3_PADW * 2 * 4)   // 18432 B

__global__ __launch_bounds__(256, 2) void outproj_mma_kernel(const float* __restrict__ x,
                                                             const float* __restrict__ bout,
                                                             float* __restrict__ y) {
    extern __shared__ uint32_t smu[];
    uint32_t* Ahi = smu;                  // [64][36] half2 words
    uint32_t* Alo = Ahi + 64 * K3_PADW;
    __shared__ float swp[8][8][2];

    const int b = blockIdx.y, n0 = blockIdx.x * 128, tid = threadIdx.x;
    const int cc = b * NCH + (n0 / CHUNK);

    // stage W2 hi/lo (uint4 = 8 halves per load)
    for (int idx = tid; idx < 64 * 8; idx += 256) {
        int row = idx >> 3, w4 = (idx & 7) * 4;
        uint4 h4 = *(const uint4*)(&g_W2h[cc][0][row][w4]);
        uint4 l4 = *(const uint4*)(&g_W2h[cc][1][row][w4]);
        Ahi[row * K3_PADW + w4]     = h4.x;
        Ahi[row * K3_PADW + w4 + 1] = h4.y;
        Ahi[row * K3_PADW + w4 + 2] = h4.z;
        Ahi[row * K3_PADW + w4 + 3] = h4.w;
        Alo[row * K3_PADW + w4]     = l4.x;
        Alo[row * K3_PADW + w4 + 1] = l4.y;
        Alo[row * K3_PADW + w4 + 2] = l4.z;
        Alo[row * K3_PADW + w4 + 3] = l4.w;
    }
    __syncthreads();

    const int wid = tid >> 5, lane = tid & 31, g = lane >> 2, tig = lane & 3;
    const int wn = wid * 16;
    const float* xb = x + (size_t)b * CDIM * NPOS + n0;

    float acc[4][2][4];
#pragma unroll
    for (int i = 0; i < 4; i++)
#pragma unroll
        for (int j = 0; j < 2; j++)
#pragma unroll
            for (int q = 0; q < 4; q++) acc[i][j][q] = 0.f;

#pragma unroll
    for (int k16 = 0; k16 < 4; k16++) {
        const int kb = k16 * 16, kb2 = k16 * 8;
        const float* r0 = xb + (size_t)(kb + 2 * tig) * NPOS;
        const float* r1 = r0 + NPOS;
        const float* r8 = r0 + 8 * NPOS;
        const float* r9 = r0 + 9 * NPOS;
        uint32_t bh[2][2], bl[2][2];
#pragma unroll
        for (int nf = 0; nf < 2; nf++) {
            int col = wn + nf * 8 + g;
            split2(__ldg(r0 + col), __ldg(r1 + col), bh[nf][0], bl[nf][0]);
            split2(__ldg(r8 + col), __ldg(r9 + col), bh[nf][1], bl[nf][1]);
        }
        uint32_t ah[4][4], al[4][4];
#pragma unroll
        for (int mf = 0; mf < 4; mf++) {
            int base = (mf * 16 + g) * K3_PADW + kb2 + tig;
            int base8 = base + 8 * K3_PADW;
            ah[mf][0] = Ahi[base];     ah[mf][1] = Ahi[base8];
            ah[mf][2] = Ahi[base + 4]; ah[mf][3] = Ahi[base8 + 4];
            al[mf][0] = Alo[base];     al[mf][1] = Alo[base8];
            al[mf][2] = Alo[base + 4]; al[mf][3] = Alo[base8 + 4];
        }
#pragma unroll
        for (int mf = 0; mf < 4; mf++)
#pragma unroll
            for (int nf = 0; nf < 2; nf++) {
                MMA16(acc[mf][nf], ah[mf], bh[nf]);
                MMA16(acc[mf][nf], ah[mf], bl[nf]);
                MMA16(acc[mf][nf], al[mf], bh[nf]);
            }
    }

    float gs[8], gq[8];
#pragma unroll
    for (int i = 0; i < 8; i++) { gs[i] = 0.f; gq[i] = 0.f; }

    float* yp = y + (size_t)b * CDIM * NPOS + n0 + wn;
#pragma unroll
    for (int mf = 0; mf < 4; mf++) {
        float bias0 = __ldg(bout + mf * 16 + g);
        float bias1 = __ldg(bout + mf * 16 + g + 8);
#pragma unroll
        for (int nf = 0; nf < 2; nf++) {
            int col = nf * 8 + tig * 2;
            float v0 = acc[mf][nf][0] + bias0, v1 = acc[mf][nf][1] + bias0;
            float v2 = acc[mf][nf][2] + bias1, v3 = acc[mf][nf][3] + bias1;
            *(float2*)(yp + (size_t)(mf * 16 + g) * NPOS + col) = make_float2(v0, v1);
            *(float2*)(yp + (size_t)(mf * 16 + g + 8) * NPOS + col) = make_float2(v2, v3);
            gs[2 * mf]     += v0 + v1;
            gq[2 * mf]     += v0 * v0 + v1 * v1;
            gs[2 * mf + 1] += v2 + v3;
            gq[2 * mf + 1] += v2 * v2 + v3 * v3;
        }
    }

#pragma unroll
    for (int gr = 0; gr < 8; gr++) {
        float s = gs[gr], q = gq[gr];
        for (int off = 16; off; off >>= 1) {
            s += __shfl_xor_sync(0xffffffffu, s, off);
            q += __shfl_xor_sync(0xffffffffu, q, off);
        }
        if (lane == 0) { swp[wid][gr][0] = s; swp[wid][gr][1] = q; }
    }
    __syncthreads();
    if (tid < 16) {
        int gr = tid >> 1, qq = tid & 1;
        float s = 0.f;
#pragma unroll
        for (int w = 0; w < 8; w++) s += swp[w][gr][qq];
        g_part[b][gr][blockIdx.x][qq] = s;
    }
}

// ---------------------------------------------------------------------------
// K4: groupnorm finalize. grid (36, 8), 256 threads. (unchanged R12)
// ---------------------------------------------------------------------------
__global__ __launch_bounds__(256, 4) void gnorm_kernel(float* __restrict__ y,
                                                       const float* __restrict__ gamma,
                                                       const float* __restrict__ beta) {
    __shared__ float tmp[8][2];
    __shared__ float mu[8], rs[8];
    const int b = blockIdx.y, n0 = blockIdx.x * 256, tid = threadIdx.x;

    if (tid < 16) {
        int g = tid >> 1, qq = tid & 1;
        float s = 0.f;
        for (int t = 0; t < GN_TILES; t++) s += g_part[b][g][t][qq];
        tmp[g][qq] = s;
    }
    __syncthreads();
    if (tid < 8) {
        const float invn = 1.0f / (8.0f * NPOS);
        float m = tmp[tid][0] * invn;
        float v = tmp[tid][1] * invn - m * m;
        mu[tid] = m;
        rs[tid] = rsqrtf(v + 1e-5f);
    }
    __syncthreads();

    const int col4 = tid & 63, crow = tid >> 6;
    float* yb = y + (size_t)b * CDIM * NPOS + n0 + col4 * 4;
#pragma unroll
    for (int c = crow; c < CDIM; c += 4) {
        float4* p = (float4*)(yb + (size_t)c * NPOS);
        float4 v = *p;
        int g = c >> 3;
        float sc = rs[g] * __ldg(gamma + c);
        float sh = __ldg(beta + c) - mu[g] * sc;
        v.x = v.x * sc + sh;
        v.y = v.y * sc + sh;
        v.z = v.z * sc + sh;
        v.w = v.w * sc + sh;
        *p = v;
    }
}

// ---------------------------------------------------------------------------
extern "C" void kernel_launch(void* const* d_in, const int* in_sizes, int n_in,
                              void* d_out, int out_size) {
    const float* x     = (const float*)d_in[0];
    const float* Wqkv  = (const float*)d_in[1];
    const float* Wout  = (const float*)d_in[2];
    const float* bout  = (const float*)d_in[3];
    const float* gamma = (const float*)d_in[4];
    const float* beta  = (const float*)d_in[5];
    float* y = (float*)d_out;

    cudaFuncSetAttribute(qkv_mma_kernel, cudaFuncAttributeMaxDynamicSharedMemorySize, K1_SMEM);
    cudaFuncSetAttribute(att_a_kernel, cudaFuncAttributeMaxDynamicSharedMemorySize, A2_SMEM);
    cudaFuncSetAttribute(weff_kernel, cudaFuncAttributeMaxDynamicSharedMemorySize, W2_SMEM);
    cudaFuncSetAttribute(outproj_mma_kernel, cudaFuncAttributeMaxDynamicSharedMemorySize, K3_SMEM);

    qkv_mma_kernel<<<dim3(72, 2, B_), 256, K1_SMEM>>>(x, Wqkv);
    att_a_kernel<<<dim3(NCH, 32, 8), 128, A2_SMEM>>>();
    weff_kernel<<<dim3(NCH, B_, 4), 256, W2_SMEM>>>(Wqkv, Wout);
    outproj_mma_kernel<<<dim3(GN_TILES, B_), 256, K3_SMEM>>>(x, bout, y);
    gnorm_kernel<<<dim3(36, B_), 256>>>(y, gamma, beta);
}

// round 14
// speedup vs baseline: 1.5203x; 1.0261x over previous
#include <cuda_runtime.h>
#include <cuda_fp16.h>
#include <cstdint>

// Problem constants
#define B_     8
#define CDIM   64
#define NPOS   9216      // 96*96
#define INNER  128
#define O3     384       // 3*INNER
#define HEADS  4
#define DHEAD  32
#define NCH    9
#define CHUNK  1024
#define NGC    (32 * NCH)   // 288 (g, ch) pairs
#define GN_TILES 72
#define NSUB   4            // A-partial sub-blocks (each covers 256 positions)

// Scratch (device globals — no allocations allowed)
__device__ __align__(16) __half g_qk[(size_t)B_ * 256 * NPOS];      // [b][o][n], o<256 (q,k), fp16
__device__ float g_part[B_][8][GN_TILES][2];                        // groupnorm partials
__device__ __align__(16) float g_Apart[NGC][NSUB][DHEAD * DHEAD];   // partial A (unnormalized)
__device__ __align__(16) uint32_t g_W2h[B_ * NCH][2][CDIM][CDIM / 2]; // fused weights fp16 hi/lo (half2)

// ---------------------------------------------------------------------------
// fp16 m16n8k16, f32 accum
#define MMA16(d, a, b)                                                        \
    asm volatile(                                                             \
        "mma.sync.aligned.m16n8k16.row.col.f32.f16.f16.f32 "                  \
        "{%0,%1,%2,%3},{%4,%5,%6,%7},{%8,%9},{%0,%1,%2,%3};"                  \
        : "+f"((d)[0]), "+f"((d)[1]), "+f"((d)[2]), "+f"((d)[3])              \
        : "r"((a)[0]), "r"((a)[1]), "r"((a)[2]), "r"((a)[3]),                 \
          "r"((b)[0]), "r"((b)[1]))

// hi/lo fp16 split of a float pair (hi = rn(x), lo = rn(x - hi))
__device__ __forceinline__ void split2(float v0, float v1, uint32_t& hi, uint32_t& lo) {
    __half h0 = __float2half_rn(v0), h1 = __float2half_rn(v1);
    hi = (uint32_t)__half_as_ushort(h0) | ((uint32_t)__half_as_ushort(h1) << 16);
    float l0 = v0 - __half2float(h0);
    float l1 = v1 - __half2float(h1);
    lo = (uint32_t)__half_as_ushort(__float2half_rn(l0)) |
         ((uint32_t)__half_as_ushort(__float2half_rn(l1)) << 16);
}

// ---------------------------------------------------------------------------
// K1 (fp16x3 mma): qk[b][o][n] = sum_c W_qkv[o][c] * x[b][c][n], o < 256.
// (unchanged R13)
// ---------------------------------------------------------------------------
#define K1_PADW 36
#define K1_SMEM (128 * K1_PADW * 2 * 4)

__global__ __launch_bounds__(256, 2) void qkv_mma_kernel(const float* __restrict__ x,
                                                         const float* __restrict__ Wq) {
    extern __shared__ uint32_t smu[];
    uint32_t* Ahi = smu;                  // [128][36] half2 words
    uint32_t* Alo = Ahi + 128 * K1_PADW;

    const int b = blockIdx.z, mt = blockIdx.y, n0 = blockIdx.x * 128;
    const int tid = threadIdx.x;

    for (int idx = tid; idx < 128 * 16; idx += 256) {
        int row = idx >> 4, c4 = (idx & 15) * 4;
        float4 w = *(const float4*)(Wq + (size_t)(mt * 128 + row) * CDIM + c4);
        int w0 = c4 >> 1;
        uint32_t h, l;
        split2(w.x, w.y, h, l);
        Ahi[row * K1_PADW + w0] = h; Alo[row * K1_PADW + w0] = l;
        split2(w.z, w.w, h, l);
        Ahi[row * K1_PADW + w0 + 1] = h; Alo[row * K1_PADW + w0 + 1] = l;
    }
    __syncthreads();

    const int wid = tid >> 5, lane = tid & 31, g = lane >> 2, tig = lane & 3;
    const int wm = (wid >> 2) * 64, wn = (wid & 3) * 32;
    const float* xb = x + (size_t)b * CDIM * NPOS + n0;

    float c[4][4][4];
#pragma unroll
    for (int i = 0; i < 4; i++)
#pragma unroll
        for (int j = 0; j < 4; j++)
#pragma unroll
            for (int q = 0; q < 4; q++) c[i][j][q] = 0.f;

#pragma unroll
    for (int k16 = 0; k16 < 4; k16++) {
        const int kb = k16 * 16, kb2 = k16 * 8;
        const float* r0 = xb + (size_t)(kb + 2 * tig) * NPOS;
        const float* r1 = r0 + NPOS;
        const float* r8 = r0 + 8 * NPOS;
        const float* r9 = r0 + 9 * NPOS;
        uint32_t bh[4][2], bl[4][2];
#pragma unroll
        for (int nf = 0; nf < 4; nf++) {
            int col = wn + nf * 8 + g;
            split2(__ldg(r0 + col), __ldg(r1 + col), bh[nf][0], bl[nf][0]);
            split2(__ldg(r8 + col), __ldg(r9 + col), bh[nf][1], bl[nf][1]);
        }
        uint32_t ah[4][4], al[4][4];
#pragma unroll
        for (int mf = 0; mf < 4; mf++) {
            int base = (wm + mf * 16 + g) * K1_PADW + kb2 + tig;
            int base8 = base + 8 * K1_PADW;
            ah[mf][0] = Ahi[base];     ah[mf][1] = Ahi[base8];
            ah[mf][2] = Ahi[base + 4]; ah[mf][3] = Ahi[base8 + 4];
            al[mf][0] = Alo[base];     al[mf][1] = Alo[base8];
            al[mf][2] = Alo[base + 4]; al[mf][3] = Alo[base8 + 4];
        }
#pragma unroll
        for (int mf = 0; mf < 4; mf++)
#pragma unroll
            for (int nf = 0; nf < 4; nf++) {
                MMA16(c[mf][nf], ah[mf], bh[nf]);
                MMA16(c[mf][nf], ah[mf], bl[nf]);
                MMA16(c[mf][nf], al[mf], bh[nf]);
            }
    }

    __half* op = g_qk + ((size_t)b * 256 + mt * 128 + wm) * NPOS + n0 + wn;
#pragma unroll
    for (int mf = 0; mf < 4; mf++)
#pragma unroll
        for (int nf = 0; nf < 4; nf++) {
            int col = nf * 8 + tig * 2;
            *(__half2*)(op + (size_t)(mf * 16 + g) * NPOS + col) =
                __floats2half2_rn(c[mf][nf][0], c[mf][nf][1]);
            *(__half2*)(op + (size_t)(mf * 16 + g + 8) * NPOS + col) =
                __floats2half2_rn(c[mf][nf][2], c[mf][nf][3]);
        }
}

// ---------------------------------------------------------------------------
// ATT2 (fp16 mma): partial A over 256 positions (2 x 128-chunks folded).
// grid (9, 32, 4), 128 threads.
// ---------------------------------------------------------------------------
#define A2_PADW 68
#define A2_WORDS (DHEAD * A2_PADW)
#define A2_SMEM_WORDS (2 * A2_WORDS)
#define A2_SMEM (A2_SMEM_WORDS * 4)

__global__ __launch_bounds__(128, 4) void att_a_kernel() {
    extern __shared__ uint32_t sm2[];
    uint32_t* Eq16 = sm2;                 // [32][68] half2 words
    uint32_t* Ks16 = sm2 + A2_WORDS;
    float* Apart = (float*)sm2;           // alias after mma: [4][32][33]

    const int ch = blockIdx.x, g = blockIdx.y, sub = blockIdx.z;
    const int gc = g * NCH + ch;
    const int b = g >> 2, head = g & 3;
    const int tid = threadIdx.x, lane = tid & 31, wrp = tid >> 5;
    const int j = tid;

    const __half* qbase0 = g_qk + ((size_t)(b * 256 + head * DHEAD)) * NPOS + ch * CHUNK + sub * 256;
    const __half* kbase0 = qbase0 + (size_t)128 * NPOS;

    __half* EqH = (__half*)Eq16;
    __half* KsH = (__half*)Ks16;

    const int gq = lane >> 2, tig = lane & 3;
    float acc[2][4][4];
#pragma unroll
    for (int i = 0; i < 2; i++)
#pragma unroll
        for (int jj = 0; jj < 4; jj++)
#pragma unroll
            for (int q = 0; q < 4; q++) acc[i][jj][q] = 0.f;

#pragma unroll
    for (int t = 0; t < 2; t++) {
        const __half* qbase = qbase0 + t * 128;
        const __half* kbase = kbase0 + t * 128;

        float kr[DHEAD];
#pragma unroll
        for (int d = 0; d < DHEAD; d++) kr[d] = __half2float(kbase[(size_t)d * NPOS + j]);
        float km = -1e30f;
#pragma unroll
        for (int d = 0; d < DHEAD; d++) km = fmaxf(km, kr[d]);
        float ks = 0.f;
#pragma unroll
        for (int d = 0; d < DHEAD; d++) { kr[d] = __expf(kr[d] - km); ks += kr[d]; }
        float kinv = 1.0f / ks;
#pragma unroll
        for (int d = 0; d < DHEAD; d++)
            KsH[d * (2 * A2_PADW) + j] = __float2half_rn(kr[d] * kinv);

        float qr[DHEAD];
#pragma unroll
        for (int d = 0; d < DHEAD; d++) qr[d] = __half2float(qbase[(size_t)d * NPOS + j]);
#pragma unroll
        for (int d = 0; d < DHEAD; d++)
            EqH[d * (2 * A2_PADW) + j] = __float2half_rn(__expf(qr[d]));
        __syncthreads();

        // mma accumulate: warp wrp covers K positions [wrp*32, wrp*32+32)
#pragma unroll
        for (int s = 0; s < 2; s++) {
            const int kb2 = wrp * 16 + s * 8;
            uint32_t a[2][4];
#pragma unroll
            for (int mf = 0; mf < 2; mf++) {
                int base = (mf * 16 + gq) * A2_PADW + kb2 + tig;
                int base8 = base + 8 * A2_PADW;
                a[mf][0] = Eq16[base];     a[mf][1] = Eq16[base8];
                a[mf][2] = Eq16[base + 4]; a[mf][3] = Eq16[base8 + 4];
            }
            uint32_t bfr[4][2];
#pragma unroll
            for (int nf = 0; nf < 4; nf++) {
                int base = (nf * 8 + gq) * A2_PADW + kb2 + tig;
                bfr[nf][0] = Ks16[base];
                bfr[nf][1] = Ks16[base + 4];
            }
#pragma unroll
            for (int mf = 0; mf < 2; mf++)
#pragma unroll
                for (int nf = 0; nf < 4; nf++)
                    MMA16(acc[mf][nf], a[mf], bfr[nf]);
        }
        __syncthreads();   // done reading before next iteration restages
    }

#pragma unroll
    for (int mf = 0; mf < 2; mf++)
#pragma unroll
        for (int nf = 0; nf < 4; nf++) {
            int row = mf * 16 + gq, col = nf * 8 + tig * 2;
            Apart[(wrp * 32 + row) * 33 + col]     = acc[mf][nf][0];
            Apart[(wrp * 32 + row) * 33 + col + 1] = acc[mf][nf][1];
            Apart[(wrp * 32 + row + 8) * 33 + col]     = acc[mf][nf][2];
            Apart[(wrp * 32 + row + 8) * 33 + col + 1] = acc[mf][nf][3];
        }
    __syncthreads();

    float* out = g_Apart[gc][sub];
#pragma unroll
    for (int r = 0; r < 8; r++) {
        int idx = tid + 128 * r;
        int d = idx >> 5, dp = idx & 31;
        float s = 0.f;
#pragma unroll
        for (int w = 0; w < 4; w++) s += Apart[(w * 32 + d) * 33 + dp];
        out[idx] = s;
    }
}

// ---------------------------------------------------------------------------
// WEFF: per (ch, b, z): A-reduce over NSUB (redundant), 1/Zq, scale; 16-row
// o-slice of Weff and W2 (fp16 hi/lo output). grid (9, 8, 4), 256 threads.
// ---------------------------------------------------------------------------
#define W2_A    0                     // [4*32*33] = 4224
#define W2_WV   4224                  // [128][68] = 8704
#define W2_WO   12928                 // [16][132] = 2112
#define W2_WE   15040                 // [16][132] = 2112
#define W2_SMEM_WORDS 17152
#define W2_SMEM (W2_SMEM_WORDS * 4)

__global__ __launch_bounds__(256, 2) void weff_kernel(const float* __restrict__ Wqkv,
                                                      const float* __restrict__ Wout) {
    extern __shared__ float wsm[];
    __shared__ float rinv_s[128];
    const int ch = blockIdx.x, b = blockIdx.y, z = blockIdx.z;
    const int cc = b * NCH + ch;
    const int tid = threadIdx.x;

#pragma unroll
    for (int r = 0; r < 16; r++) {
        int idx = tid + 256 * r;
        int head = idx >> 10, e = idx & 1023;
        int d = e >> 5, dp = e & 31;
        const float* ap = g_Apart[(b * HEADS + head) * NCH + ch][0] + e;
        float s = 0.f;
#pragma unroll
        for (int sub = 0; sub < NSUB; sub++) s += ap[sub * DHEAD * DHEAD];
        wsm[W2_A + (head * 32 + d) * 33 + dp] = s;
    }
#pragma unroll
    for (int r = 0; r < 8; r++) {
        int idx = tid + 256 * r;
        int ic = idx >> 4, c4 = (idx & 15) * 4;
        float4 v = *(const float4*)(Wqkv + (size_t)(2 * INNER + ic) * CDIM + c4);
        float* d = wsm + W2_WV + ic * 68 + c4;
        d[0] = v.x; d[1] = v.y; d[2] = v.z; d[3] = v.w;
    }
#pragma unroll
    for (int r = 0; r < 2; r++) {
        int idx = tid + 256 * r;
        int o = idx >> 5, ic4 = (idx & 31) * 4;
        float4 v = *(const float4*)(Wout + (size_t)(z * 16 + o) * INNER + ic4);
        float* d = wsm + W2_WO + o * 132 + ic4;
        d[0] = v.x; d[1] = v.y; d[2] = v.z; d[3] = v.w;
    }
    __syncthreads();

    if (tid < 128) {
        float s = 0.f;
#pragma unroll
        for (int dp = 0; dp < DHEAD; dp++) s += wsm[W2_A + tid * 33 + dp];
        rinv_s[tid] = 1.0f / s;
    }
    __syncthreads();
#pragma unroll
    for (int r = 0; r < 16; r++) {
        int idx = tid + 256 * r;
        int row = idx >> 5, dp = idx & 31;
        wsm[W2_A + row * 33 + dp] *= rinv_s[row];
    }
    __syncthreads();

#pragma unroll
    for (int r = 0; r < 8; r++) {
        int idx = tid + 256 * r;
        int o = idx >> 7, ic = idx & 127, head = ic >> 5, dp = ic & 31;
        float acc = 0.f;
#pragma unroll
        for (int d = 0; d < DHEAD; d++)
            acc += wsm[W2_WO + o * 132 + head * 32 + d] * wsm[W2_A + (head * 32 + d) * 33 + dp];
        wsm[W2_WE + o * 132 + ic] = acc;
    }
    __syncthreads();

    const int ol = tid >> 4, c0 = (tid & 15) * 4;
    float w2[4] = {0.f, 0.f, 0.f, 0.f};
#pragma unroll
    for (int ic = 0; ic < INNER; ic++) {
        float we = wsm[W2_WE + ol * 132 + ic];
        const float* wv = wsm + W2_WV + ic * 68 + c0;
        w2[0] += we * wv[0];
        w2[1] += we * wv[1];
        w2[2] += we * wv[2];
        w2[3] += we * wv[3];
    }
    const int og = z * 16 + ol, w0 = c0 >> 1;
    uint32_t h, l;
    split2(w2[0], w2[1], h, l);
    g_W2h[cc][0][og][w0] = h;
    g_W2h[cc][1][og][w0] = l;
    split2(w2[2], w2[3], h, l);
    g_W2h[cc][0][og][w0 + 1] = h;
    g_W2h[cc][1][og][w0 + 1] = l;
}

// ---------------------------------------------------------------------------
// K3'' (fp16x3 mma): y = W2(b,ch) @ x + b_out, groupnorm partials.
// CTA tile [64 M x 128 N], K=64. grid (72, 8), 256 threads, occ 3.
// ---------------------------------------------------------------------------
#define K3_PADW 36
#define K3_SMEM (64 * K3_PADW * 2 * 4)   // 18432 B

__global__ __launch_bounds__(256, 3) void outproj_mma_kernel(const float* __restrict__ x,
                                                             const float* __restrict__ bout,
                                                             float* __restrict__ y) {
    extern __shared__ uint32_t smu[];
    uint32_t* Ahi = smu;                  // [64][36] half2 words
    uint32_t* Alo = Ahi + 64 * K3_PADW;
    __shared__ float swp[8][8][2];

    const int b = blockIdx.y, n0 = blockIdx.x * 128, tid = threadIdx.x;
    const int cc = b * NCH + (n0 / CHUNK);

    for (int idx = tid; idx < 64 * 8; idx += 256) {
        int row = idx >> 3, w4 = (idx & 7) * 4;
        uint4 h4 = *(const uint4*)(&g_W2h[cc][0][row][w4]);
        uint4 l4 = *(const uint4*)(&g_W2h[cc][1][row][w4]);
        Ahi[row * K3_PADW + w4]     = h4.x;
        Ahi[row * K3_PADW + w4 + 1] = h4.y;
        Ahi[row * K3_PADW + w4 + 2] = h4.z;
        Ahi[row * K3_PADW + w4 + 3] = h4.w;
        Alo[row * K3_PADW + w4]     = l4.x;
        Alo[row * K3_PADW + w4 + 1] = l4.y;
        Alo[row * K3_PADW + w4 + 2] = l4.z;
        Alo[row * K3_PADW + w4 + 3] = l4.w;
    }
    __syncthreads();

    const int wid = tid >> 5, lane = tid & 31, g = lane >> 2, tig = lane & 3;
    const int wn = wid * 16;
    const float* xb = x + (size_t)b * CDIM * NPOS + n0;

    float acc[4][2][4];
#pragma unroll
    for (int i = 0; i < 4; i++)
#pragma unroll
        for (int j = 0; j < 2; j++)
#pragma unroll
            for (int q = 0; q < 4; q++) acc[i][j][q] = 0.f;

#pragma unroll
    for (int k16 = 0; k16 < 4; k16++) {
        const int kb = k16 * 16, kb2 = k16 * 8;
        const float* r0 = xb + (size_t)(kb + 2 * tig) * NPOS;
        const float* r1 = r0 + NPOS;
        const float* r8 = r0 + 8 * NPOS;
        const float* r9 = r0 + 9 * NPOS;
        uint32_t bh[2][2], bl[2][2];
#pragma unroll
        for (int nf = 0; nf < 2; nf++) {
            int col = wn + nf * 8 + g;
            split2(__ldg(r0 + col), __ldg(r1 + col), bh[nf][0], bl[nf][0]);
            split2(__ldg(r8 + col), __ldg(r9 + col), bh[nf][1], bl[nf][1]);
        }
        uint32_t ah[4][4], al[4][4];
#pragma unroll
        for (int mf = 0; mf < 4; mf++) {
            int base = (mf * 16 + g) * K3_PADW + kb2 + tig;
            int base8 = base + 8 * K3_PADW;
            ah[mf][0] = Ahi[base];     ah[mf][1] = Ahi[base8];
            ah[mf][2] = Ahi[base + 4]; ah[mf][3] = Ahi[base8 + 4];
            al[mf][0] = Alo[base];     al[mf][1] = Alo[base8];
            al[mf][2] = Alo[base + 4]; al[mf][3] = Alo[base8 + 4];
        }
#pragma unroll
        for (int mf = 0; mf < 4; mf++)
#pragma unroll
            for (int nf = 0; nf < 2; nf++) {
                MMA16(acc[mf][nf], ah[mf], bh[nf]);
                MMA16(acc[mf][nf], ah[mf], bl[nf]);
                MMA16(acc[mf][nf], al[mf], bh[nf]);
            }
    }

    float gs[8], gq[8];
#pragma unroll
    for (int i = 0; i < 8; i++) { gs[i] = 0.f; gq[i] = 0.f; }

    float* yp = y + (size_t)b * CDIM * NPOS + n0 + wn;
#pragma unroll
    for (int mf = 0; mf < 4; mf++) {
        float bias0 = __ldg(bout + mf * 16 + g);
        float bias1 = __ldg(bout + mf * 16 + g + 8);
#pragma unroll
        for (int nf = 0; nf < 2; nf++) {
            int col = nf * 8 + tig * 2;
            float v0 = acc[mf][nf][0] + bias0, v1 = acc[mf][nf][1] + bias0;
            float v2 = acc[mf][nf][2] + bias1, v3 = acc[mf][nf][3] + bias1;
            *(float2*)(yp + (size_t)(mf * 16 + g) * NPOS + col) = make_float2(v0, v1);
            *(float2*)(yp + (size_t)(mf * 16 + g + 8) * NPOS + col) = make_float2(v2, v3);
            gs[2 * mf]     += v0 + v1;
            gq[2 * mf]     += v0 * v0 + v1 * v1;
            gs[2 * mf + 1] += v2 + v3;
            gq[2 * mf + 1] += v2 * v2 + v3 * v3;
        }
    }

#pragma unroll
    for (int gr = 0; gr < 8; gr++) {
        float s = gs[gr], q = gq[gr];
        for (int off = 16; off; off >>= 1) {
            s += __shfl_xor_sync(0xffffffffu, s, off);
            q += __shfl_xor_sync(0xffffffffu, q, off);
        }
        if (lane == 0) { swp[wid][gr][0] = s; swp[wid][gr][1] = q; }
    }
    __syncthreads();
    if (tid < 16) {
        int gr = tid >> 1, qq = tid & 1;
        float s = 0.f;
#pragma unroll
        for (int w = 0; w < 8; w++) s += swp[w][gr][qq];
        g_part[b][gr][blockIdx.x][qq] = s;
    }
}

// ---------------------------------------------------------------------------
// K4: groupnorm finalize. grid (36, 8), 256 threads. (unchanged R13)
// ---------------------------------------------------------------------------
__global__ __launch_bounds__(256, 4) void gnorm_kernel(float* __restrict__ y,
                                                       const float* __restrict__ gamma,
                                                       const float* __restrict__ beta) {
    __shared__ float tmp[8][2];
    __shared__ float mu[8], rs[8];
    const int b = blockIdx.y, n0 = blockIdx.x * 256, tid = threadIdx.x;

    if (tid < 16) {
        int g = tid >> 1, qq = tid & 1;
        float s = 0.f;
        for (int t = 0; t < GN_TILES; t++) s += g_part[b][g][t][qq];
        tmp[g][qq] = s;
    }
    __syncthreads();
    if (tid < 8) {
        const float invn = 1.0f / (8.0f * NPOS);
        float m = tmp[tid][0] * invn;
        float v = tmp[tid][1] * invn - m * m;
        mu[tid] = m;
        rs[tid] = rsqrtf(v + 1e-5f);
    }
    __syncthreads();

    const int col4 = tid & 63, crow = tid >> 6;
    float* yb = y + (size_t)b * CDIM * NPOS + n0 + col4 * 4;
#pragma unroll
    for (int c = crow; c < CDIM; c += 4) {
        float4* p = (float4*)(yb + (size_t)c * NPOS);
        float4 v = *p;
        int g = c >> 3;
        float sc = rs[g] * __ldg(gamma + c);
        float sh = __ldg(beta + c) - mu[g] * sc;
        v.x = v.x * sc + sh;
        v.y = v.y * sc + sh;
        v.z = v.z * sc + sh;
        v.w = v.w * sc + sh;
        *p = v;
    }
}

// ---------------------------------------------------------------------------
extern "C" void kernel_launch(void* const* d_in, const int* in_sizes, int n_in,
                              void* d_out, int out_size) {
    const float* x     = (const float*)d_in[0];
    const float* Wqkv  = (const float*)d_in[1];
    const float* Wout  = (const float*)d_in[2];
    const float* bout  = (const float*)d_in[3];
    const float* gamma = (const float*)d_in[4];
    const float* beta  = (const float*)d_in[5];
    float* y = (float*)d_out;

    cudaFuncSetAttribute(qkv_mma_kernel, cudaFuncAttributeMaxDynamicSharedMemorySize, K1_SMEM);
    cudaFuncSetAttribute(att_a_kernel, cudaFuncAttributeMaxDynamicSharedMemorySize, A2_SMEM);
    cudaFuncSetAttribute(weff_kernel, cudaFuncAttributeMaxDynamicSharedMemorySize, W2_SMEM);
    cudaFuncSetAttribute(outproj_mma_kernel, cudaFuncAttributeMaxDynamicSharedMemorySize, K3_SMEM);

    qkv_mma_kernel<<<dim3(72, 2, B_), 256, K1_SMEM>>>(x, Wqkv);
    att_a_kernel<<<dim3(NCH, 32, NSUB), 128, A2_SMEM>>>();
    weff_kernel<<<dim3(NCH, B_, 4), 256, W2_SMEM>>>(Wqkv, Wout);
    outproj_mma_kernel<<<dim3(GN_TILES, B_), 256, K3_SMEM>>>(x, bout, y);
    gnorm_kernel<<<dim3(36, B_), 256>>>(y, gamma, beta);
}

// round 15
// speedup vs baseline: 1.5549x; 1.0228x over previous
#include <cuda_runtime.h>
#include <cuda_fp16.h>
#include <cstdint>

// Problem constants
#define B_     8
#define CDIM   64
#define NPOS   9216      // 96*96
#define INNER  128
#define O3     384       // 3*INNER
#define HEADS  4
#define DHEAD  32
#define NCH    9
#define CHUNK  1024
#define NGC    (32 * NCH)   // 288 (g, ch) pairs
#define GN_TILES 36
#define NSUB   4            // A-partial sub-blocks (each covers 256 positions)

// Scratch (device globals — no allocations allowed)
__device__ __align__(16) __half g_qk[(size_t)B_ * 256 * NPOS];      // [b][o][n], o<256 (q,k), fp16
__device__ float g_part[B_][8][GN_TILES][2];                        // groupnorm partials
__device__ __align__(16) float g_Apart[NGC][NSUB][DHEAD * DHEAD];   // partial A (unnormalized)
__device__ __align__(16) uint32_t g_W2h[B_ * NCH][2][CDIM][CDIM / 2]; // fused weights fp16 hi/lo (half2)

// ---------------------------------------------------------------------------
// fp16 m16n8k16, f32 accum
#define MMA16(d, a, b)                                                        \
    asm volatile(                                                             \
        "mma.sync.aligned.m16n8k16.row.col.f32.f16.f16.f32 "                  \
        "{%0,%1,%2,%3},{%4,%5,%6,%7},{%8,%9},{%0,%1,%2,%3};"                  \
        : "+f"((d)[0]), "+f"((d)[1]), "+f"((d)[2]), "+f"((d)[3])              \
        : "r"((a)[0]), "r"((a)[1]), "r"((a)[2]), "r"((a)[3]),                 \
          "r"((b)[0]), "r"((b)[1]))

// hi/lo fp16 split of a float pair (hi = rn(x), lo = rn(x - hi))
__device__ __forceinline__ void split2(float v0, float v1, uint32_t& hi, uint32_t& lo) {
    __half h0 = __float2half_rn(v0), h1 = __float2half_rn(v1);
    hi = (uint32_t)__half_as_ushort(h0) | ((uint32_t)__half_as_ushort(h1) << 16);
    float l0 = v0 - __half2float(h0);
    float l1 = v1 - __half2float(h1);
    lo = (uint32_t)__half_as_ushort(__float2half_rn(l0)) |
         ((uint32_t)__half_as_ushort(__float2half_rn(l1)) << 16);
}

// ---------------------------------------------------------------------------
// K1 (fp16x3 mma): qk[b][o][n] = sum_c W_qkv[o][c] * x[b][c][n], o < 256.
// (unchanged)
// ---------------------------------------------------------------------------
#define K1_PADW 36
#define K1_SMEM (128 * K1_PADW * 2 * 4)

__global__ __launch_bounds__(256, 2) void qkv_mma_kernel(const float* __restrict__ x,
                                                         const float* __restrict__ Wq) {
    extern __shared__ uint32_t smu[];
    uint32_t* Ahi = smu;                  // [128][36] half2 words
    uint32_t* Alo = Ahi + 128 * K1_PADW;

    const int b = blockIdx.z, mt = blockIdx.y, n0 = blockIdx.x * 128;
    const int tid = threadIdx.x;

    for (int idx = tid; idx < 128 * 16; idx += 256) {
        int row = idx >> 4, c4 = (idx & 15) * 4;
        float4 w = *(const float4*)(Wq + (size_t)(mt * 128 + row) * CDIM + c4);
        int w0 = c4 >> 1;
        uint32_t h, l;
        split2(w.x, w.y, h, l);
        Ahi[row * K1_PADW + w0] = h; Alo[row * K1_PADW + w0] = l;
        split2(w.z, w.w, h, l);
        Ahi[row * K1_PADW + w0 + 1] = h; Alo[row * K1_PADW + w0 + 1] = l;
    }
    __syncthreads();

    const int wid = tid >> 5, lane = tid & 31, g = lane >> 2, tig = lane & 3;
    const int wm = (wid >> 2) * 64, wn = (wid & 3) * 32;
    const float* xb = x + (size_t)b * CDIM * NPOS + n0;

    float c[4][4][4];
#pragma unroll
    for (int i = 0; i < 4; i++)
#pragma unroll
        for (int j = 0; j < 4; j++)
#pragma unroll
            for (int q = 0; q < 4; q++) c[i][j][q] = 0.f;

#pragma unroll
    for (int k16 = 0; k16 < 4; k16++) {
        const int kb = k16 * 16, kb2 = k16 * 8;
        const float* r0 = xb + (size_t)(kb + 2 * tig) * NPOS;
        const float* r1 = r0 + NPOS;
        const float* r8 = r0 + 8 * NPOS;
        const float* r9 = r0 + 9 * NPOS;
        uint32_t bh[4][2], bl[4][2];
#pragma unroll
        for (int nf = 0; nf < 4; nf++) {
            int col = wn + nf * 8 + g;
            split2(__ldg(r0 + col), __ldg(r1 + col), bh[nf][0], bl[nf][0]);
            split2(__ldg(r8 + col), __ldg(r9 + col), bh[nf][1], bl[nf][1]);
        }
        uint32_t ah[4][4], al[4][4];
#pragma unroll
        for (int mf = 0; mf < 4; mf++) {
            int base = (wm + mf * 16 + g) * K1_PADW + kb2 + tig;
            int base8 = base + 8 * K1_PADW;
            ah[mf][0] = Ahi[base];     ah[mf][1] = Ahi[base8];
            ah[mf][2] = Ahi[base + 4]; ah[mf][3] = Ahi[base8 + 4];
            al[mf][0] = Alo[base];     al[mf][1] = Alo[base8];
            al[mf][2] = Alo[base + 4]; al[mf][3] = Alo[base8 + 4];
        }
#pragma unroll
        for (int mf = 0; mf < 4; mf++)
#pragma unroll
            for (int nf = 0; nf < 4; nf++) {
                MMA16(c[mf][nf], ah[mf], bh[nf]);
                MMA16(c[mf][nf], ah[mf], bl[nf]);
                MMA16(c[mf][nf], al[mf], bh[nf]);
            }
    }

    __half* op = g_qk + ((size_t)b * 256 + mt * 128 + wm) * NPOS + n0 + wn;
#pragma unroll
    for (int mf = 0; mf < 4; mf++)
#pragma unroll
        for (int nf = 0; nf < 4; nf++) {
            int col = nf * 8 + tig * 2;
            *(__half2*)(op + (size_t)(mf * 16 + g) * NPOS + col) =
                __floats2half2_rn(c[mf][nf][0], c[mf][nf][1]);
            *(__half2*)(op + (size_t)(mf * 16 + g + 8) * NPOS + col) =
                __floats2half2_rn(c[mf][nf][2], c[mf][nf][3]);
        }
}

// ---------------------------------------------------------------------------
// ATT2 (fp16 mma): partial A over 256 positions (2 x 128-chunks folded).
// grid (9, 32, 4), 128 threads. (unchanged R14)
// ---------------------------------------------------------------------------
#define A2_PADW 68
#define A2_WORDS (DHEAD * A2_PADW)
#define A2_SMEM_WORDS (2 * A2_WORDS)
#define A2_SMEM (A2_SMEM_WORDS * 4)

__global__ __launch_bounds__(128, 4) void att_a_kernel() {
    extern __shared__ uint32_t sm2[];
    uint32_t* Eq16 = sm2;                 // [32][68] half2 words
    uint32_t* Ks16 = sm2 + A2_WORDS;
    float* Apart = (float*)sm2;           // alias after mma: [4][32][33]

    const int ch = blockIdx.x, g = blockIdx.y, sub = blockIdx.z;
    const int gc = g * NCH + ch;
    const int b = g >> 2, head = g & 3;
    const int tid = threadIdx.x, lane = tid & 31, wrp = tid >> 5;
    const int j = tid;

    const __half* qbase0 = g_qk + ((size_t)(b * 256 + head * DHEAD)) * NPOS + ch * CHUNK + sub * 256;
    const __half* kbase0 = qbase0 + (size_t)128 * NPOS;

    __half* EqH = (__half*)Eq16;
    __half* KsH = (__half*)Ks16;

    const int gq = lane >> 2, tig = lane & 3;
    float acc[2][4][4];
#pragma unroll
    for (int i = 0; i < 2; i++)
#pragma unroll
        for (int jj = 0; jj < 4; jj++)
#pragma unroll
            for (int q = 0; q < 4; q++) acc[i][jj][q] = 0.f;

#pragma unroll
    for (int t = 0; t < 2; t++) {
        const __half* qbase = qbase0 + t * 128;
        const __half* kbase = kbase0 + t * 128;

        float kr[DHEAD];
#pragma unroll
        for (int d = 0; d < DHEAD; d++) kr[d] = __half2float(kbase[(size_t)d * NPOS + j]);
        float km = -1e30f;
#pragma unroll
        for (int d = 0; d < DHEAD; d++) km = fmaxf(km, kr[d]);
        float ks = 0.f;
#pragma unroll
        for (int d = 0; d < DHEAD; d++) { kr[d] = __expf(kr[d] - km); ks += kr[d]; }
        float kinv = 1.0f / ks;
#pragma unroll
        for (int d = 0; d < DHEAD; d++)
            KsH[d * (2 * A2_PADW) + j] = __float2half_rn(kr[d] * kinv);

        float qr[DHEAD];
#pragma unroll
        for (int d = 0; d < DHEAD; d++) qr[d] = __half2float(qbase[(size_t)d * NPOS + j]);
#pragma unroll
        for (int d = 0; d < DHEAD; d++)
            EqH[d * (2 * A2_PADW) + j] = __float2half_rn(__expf(qr[d]));
        __syncthreads();

#pragma unroll
        for (int s = 0; s < 2; s++) {
            const int kb2 = wrp * 16 + s * 8;
            uint32_t a[2][4];
#pragma unroll
            for (int mf = 0; mf < 2; mf++) {
                int base = (mf * 16 + gq) * A2_PADW + kb2 + tig;
                int base8 = base + 8 * A2_PADW;
                a[mf][0] = Eq16[base];     a[mf][1] = Eq16[base8];
                a[mf][2] = Eq16[base + 4]; a[mf][3] = Eq16[base8 + 4];
            }
            uint32_t bfr[4][2];
#pragma unroll
            for (int nf = 0; nf < 4; nf++) {
                int base = (nf * 8 + gq) * A2_PADW + kb2 + tig;
                bfr[nf][0] = Ks16[base];
                bfr[nf][1] = Ks16[base + 4];
            }
#pragma unroll
            for (int mf = 0; mf < 2; mf++)
#pragma unroll
                for (int nf = 0; nf < 4; nf++)
                    MMA16(acc[mf][nf], a[mf], bfr[nf]);
        }
        __syncthreads();
    }

#pragma unroll
    for (int mf = 0; mf < 2; mf++)
#pragma unroll
        for (int nf = 0; nf < 4; nf++) {
            int row = mf * 16 + gq, col = nf * 8 + tig * 2;
            Apart[(wrp * 32 + row) * 33 + col]     = acc[mf][nf][0];
            Apart[(wrp * 32 + row) * 33 + col + 1] = acc[mf][nf][1];
            Apart[(wrp * 32 + row + 8) * 33 + col]     = acc[mf][nf][2];
            Apart[(wrp * 32 + row + 8) * 33 + col + 1] = acc[mf][nf][3];
        }
    __syncthreads();

    float* out = g_Apart[gc][sub];
#pragma unroll
    for (int r = 0; r < 8; r++) {
        int idx = tid + 128 * r;
        int d = idx >> 5, dp = idx & 31;
        float s = 0.f;
#pragma unroll
        for (int w = 0; w < 4; w++) s += Apart[(w * 32 + d) * 33 + dp];
        out[idx] = s;
    }
}

// ---------------------------------------------------------------------------
// WEFF: per (ch, b, z): A-reduce over NSUB (redundant), 1/Zq, scale; 16-row
// o-slice of Weff and W2 (fp16 hi/lo output). grid (9, 8, 4), 256 threads.
// (unchanged R14)
// ---------------------------------------------------------------------------
#define W2_A    0                     // [4*32*33] = 4224
#define W2_WV   4224                  // [128][68] = 8704
#define W2_WO   12928                 // [16][132] = 2112
#define W2_WE   15040                 // [16][132] = 2112
#define W2_SMEM_WORDS 17152
#define W2_SMEM (W2_SMEM_WORDS * 4)

__global__ __launch_bounds__(256, 2) void weff_kernel(const float* __restrict__ Wqkv,
                                                      const float* __restrict__ Wout) {
    extern __shared__ float wsm[];
    __shared__ float rinv_s[128];
    const int ch = blockIdx.x, b = blockIdx.y, z = blockIdx.z;
    const int cc = b * NCH + ch;
    const int tid = threadIdx.x;

#pragma unroll
    for (int r = 0; r < 16; r++) {
        int idx = tid + 256 * r;
        int head = idx >> 10, e = idx & 1023;
        int d = e >> 5, dp = e & 31;
        const float* ap = g_Apart[(b * HEADS + head) * NCH + ch][0] + e;
        float s = 0.f;
#pragma unroll
        for (int sub = 0; sub < NSUB; sub++) s += ap[sub * DHEAD * DHEAD];
        wsm[W2_A + (head * 32 + d) * 33 + dp] = s;
    }
#pragma unroll
    for (int r = 0; r < 8; r++) {
        int idx = tid + 256 * r;
        int ic = idx >> 4, c4 = (idx & 15) * 4;
        float4 v = *(const float4*)(Wqkv + (size_t)(2 * INNER + ic) * CDIM + c4);
        float* d = wsm + W2_WV + ic * 68 + c4;
        d[0] = v.x; d[1] = v.y; d[2] = v.z; d[3] = v.w;
    }
#pragma unroll
    for (int r = 0; r < 2; r++) {
        int idx = tid + 256 * r;
        int o = idx >> 5, ic4 = (idx & 31) * 4;
        float4 v = *(const float4*)(Wout + (size_t)(z * 16 + o) * INNER + ic4);
        float* d = wsm + W2_WO + o * 132 + ic4;
        d[0] = v.x; d[1] = v.y; d[2] = v.z; d[3] = v.w;
    }
    __syncthreads();

    if (tid < 128) {
        float s = 0.f;
#pragma unroll
        for (int dp = 0; dp < DHEAD; dp++) s += wsm[W2_A + tid * 33 + dp];
        rinv_s[tid] = 1.0f / s;
    }
    __syncthreads();
#pragma unroll
    for (int r = 0; r < 16; r++) {
        int idx = tid + 256 * r;
        int row = idx >> 5, dp = idx & 31;
        wsm[W2_A + row * 33 + dp] *= rinv_s[row];
    }
    __syncthreads();

#pragma unroll
    for (int r = 0; r < 8; r++) {
        int idx = tid + 256 * r;
        int o = idx >> 7, ic = idx & 127, head = ic >> 5, dp = ic & 31;
        float acc = 0.f;
#pragma unroll
        for (int d = 0; d < DHEAD; d++)
            acc += wsm[W2_WO + o * 132 + head * 32 + d] * wsm[W2_A + (head * 32 + d) * 33 + dp];
        wsm[W2_WE + o * 132 + ic] = acc;
    }
    __syncthreads();

    const int ol = tid >> 4, c0 = (tid & 15) * 4;
    float w2[4] = {0.f, 0.f, 0.f, 0.f};
#pragma unroll
    for (int ic = 0; ic < INNER; ic++) {
        float we = wsm[W2_WE + ol * 132 + ic];
        const float* wv = wsm + W2_WV + ic * 68 + c0;
        w2[0] += we * wv[0];
        w2[1] += we * wv[1];
        w2[2] += we * wv[2];
        w2[3] += we * wv[3];
    }
    const int og = z * 16 + ol, w0 = c0 >> 1;
    uint32_t h, l;
    split2(w2[0], w2[1], h, l);
    g_W2h[cc][0][og][w0] = h;
    g_W2h[cc][1][og][w0] = l;
    split2(w2[2], w2[3], h, l);
    g_W2h[cc][0][og][w0 + 1] = h;
    g_W2h[cc][1][og][w0 + 1] = l;
}

// ---------------------------------------------------------------------------
// K3'' (fp16x3 mma): y = W2(b,ch) @ x + b_out, groupnorm partials.
// CTA tile [64 M x 256 N], K=64. grid (36, 8) = 288 CTAs (~1 wave), occ 2.
// ---------------------------------------------------------------------------
#define K3_PADW 36
#define K3_SMEM (64 * K3_PADW * 2 * 4)   // 18432 B

__global__ __launch_bounds__(256, 2) void outproj_mma_kernel(const float* __restrict__ x,
                                                             const float* __restrict__ bout,
                                                             float* __restrict__ y) {
    extern __shared__ uint32_t smu[];
    uint32_t* Ahi = smu;                  // [64][36] half2 words
    uint32_t* Alo = Ahi + 64 * K3_PADW;
    __shared__ float swp[8][8][2];

    const int b = blockIdx.y, n0 = blockIdx.x * 256, tid = threadIdx.x;
    const int cc = b * NCH + (n0 / CHUNK);

    for (int idx = tid; idx < 64 * 8; idx += 256) {
        int row = idx >> 3, w4 = (idx & 7) * 4;
        uint4 h4 = *(const uint4*)(&g_W2h[cc][0][row][w4]);
        uint4 l4 = *(const uint4*)(&g_W2h[cc][1][row][w4]);
        Ahi[row * K3_PADW + w4]     = h4.x;
        Ahi[row * K3_PADW + w4 + 1] = h4.y;
        Ahi[row * K3_PADW + w4 + 2] = h4.z;
        Ahi[row * K3_PADW + w4 + 3] = h4.w;
        Alo[row * K3_PADW + w4]     = l4.x;
        Alo[row * K3_PADW + w4 + 1] = l4.y;
        Alo[row * K3_PADW + w4 + 2] = l4.z;
        Alo[row * K3_PADW + w4 + 3] = l4.w;
    }
    __syncthreads();

    const int wid = tid >> 5, lane = tid & 31, g = lane >> 2, tig = lane & 3;
    const int wn = wid * 32;   // warp tile [64 M x 32 N]
    const float* xb = x + (size_t)b * CDIM * NPOS + n0;

    float acc[4][4][4];
#pragma unroll
    for (int i = 0; i < 4; i++)
#pragma unroll
        for (int j = 0; j < 4; j++)
#pragma unroll
            for (int q = 0; q < 4; q++) acc[i][j][q] = 0.f;

#pragma unroll
    for (int k16 = 0; k16 < 4; k16++) {
        const int kb = k16 * 16, kb2 = k16 * 8;
        const float* r0 = xb + (size_t)(kb + 2 * tig) * NPOS;
        const float* r1 = r0 + NPOS;
        const float* r8 = r0 + 8 * NPOS;
        const float* r9 = r0 + 9 * NPOS;
        uint32_t bh[4][2], bl[4][2];
#pragma unroll
        for (int nf = 0; nf < 4; nf++) {
            int col = wn + nf * 8 + g;
            split2(__ldg(r0 + col), __ldg(r1 + col), bh[nf][0], bl[nf][0]);
            split2(__ldg(r8 + col), __ldg(r9 + col), bh[nf][1], bl[nf][1]);
        }
        uint32_t ah[4][4], al[4][4];
#pragma unroll
        for (int mf = 0; mf < 4; mf++) {
            int base = (mf * 16 + g) * K3_PADW + kb2 + tig;
            int base8 = base + 8 * K3_PADW;
            ah[mf][0] = Ahi[base];     ah[mf][1] = Ahi[base8];
            ah[mf][2] = Ahi[base + 4]; ah[mf][3] = Ahi[base8 + 4];
            al[mf][0] = Alo[base];     al[mf][1] = Alo[base8];
            al[mf][2] = Alo[base + 4]; al[mf][3] = Alo[base8 + 4];
        }
#pragma unroll
        for (int mf = 0; mf < 4; mf++)
#pragma unroll
            for (int nf = 0; nf < 4; nf++) {
                MMA16(acc[mf][nf], ah[mf], bh[nf]);
                MMA16(acc[mf][nf], ah[mf], bl[nf]);
                MMA16(acc[mf][nf], al[mf], bh[nf]);
            }
    }

    float gs[8], gq[8];
#pragma unroll
    for (int i = 0; i < 8; i++) { gs[i] = 0.f; gq[i] = 0.f; }

    float* yp = y + (size_t)b * CDIM * NPOS + n0 + wn;
#pragma unroll
    for (int mf = 0; mf < 4; mf++) {
        float bias0 = __ldg(bout + mf * 16 + g);
        float bias1 = __ldg(bout + mf * 16 + g + 8);
#pragma unroll
        for (int nf = 0; nf < 4; nf++) {
            int col = nf * 8 + tig * 2;
            float v0 = acc[mf][nf][0] + bias0, v1 = acc[mf][nf][1] + bias0;
            float v2 = acc[mf][nf][2] + bias1, v3 = acc[mf][nf][3] + bias1;
            *(float2*)(yp + (size_t)(mf * 16 + g) * NPOS + col) = make_float2(v0, v1);
            *(float2*)(yp + (size_t)(mf * 16 + g + 8) * NPOS + col) = make_float2(v2, v3);
            gs[2 * mf]     += v0 + v1;
            gq[2 * mf]     += v0 * v0 + v1 * v1;
            gs[2 * mf + 1] += v2 + v3;
            gq[2 * mf + 1] += v2 * v2 + v3 * v3;
        }
    }

#pragma unroll
    for (int gr = 0; gr < 8; gr++) {
        float s = gs[gr], q = gq[gr];
        for (int off = 16; off; off >>= 1) {
            s += __shfl_xor_sync(0xffffffffu, s, off);
            q += __shfl_xor_sync(0xffffffffu, q, off);
        }
        if (lane == 0) { swp[wid][gr][0] = s; swp[wid][gr][1] = q; }
    }
    __syncthreads();
    if (tid < 16) {
        int gr = tid >> 1, qq = tid & 1;
        float s = 0.f;
#pragma unroll
        for (int w = 0; w < 8; w++) s += swp[w][gr][qq];
        g_part[b][gr][blockIdx.x][qq] = s;
    }
}

// ---------------------------------------------------------------------------
// K4: groupnorm finalize. grid (36, 8), 256 threads.
// ---------------------------------------------------------------------------
__global__ __launch_bounds__(256, 4) void gnorm_kernel(float* __restrict__ y,
                                                       const float* __restrict__ gamma,
                                                       const float* __restrict__ beta) {
    __shared__ float tmp[8][2];
    __shared__ float mu[8], rs[8];
    const int b = blockIdx.y, n0 = blockIdx.x * 256, tid = threadIdx.x;

    if (tid < 16) {
        int g = tid >> 1, qq = tid & 1;
        float s = 0.f;
        for (int t = 0; t < GN_TILES; t++) s += g_part[b][g][t][qq];
        tmp[g][qq] = s;
    }
    __syncthreads();
    if (tid < 8) {
        const float invn = 1.0f / (8.0f * NPOS);
        float m = tmp[tid][0] * invn;
        float v = tmp[tid][1] * invn - m * m;
        mu[tid] = m;
        rs[tid] = rsqrtf(v + 1e-5f);
    }
    __syncthreads();

    const int col4 = tid & 63, crow = tid >> 6;
    float* yb = y + (size_t)b * CDIM * NPOS + n0 + col4 * 4;
#pragma unroll
    for (int c = crow; c < CDIM; c += 4) {
        float4* p = (float4*)(yb + (size_t)c * NPOS);
        float4 v = *p;
        int g = c >> 3;
        float sc = rs[g] * __ldg(gamma + c);
        float sh = __ldg(beta + c) - mu[g] * sc;
        v.x = v.x * sc + sh;
        v.y = v.y * sc + sh;
        v.z = v.z * sc + sh;
        v.w = v.w * sc + sh;
        *p = v;
    }
}

// ---------------------------------------------------------------------------
extern "C" void kernel_launch(void* const* d_in, const int* in_sizes, int n_in,
                              void* d_out, int out_size) {
    const float* x     = (const float*)d_in[0];
    const float* Wqkv  = (const float*)d_in[1];
    const float* Wout  = (const float*)d_in[2];
    const float* bout  = (const float*)d_in[3];
    const float* gamma = (const float*)d_in[4];
    const float* beta  = (const float*)d_in[5];
    float* y = (float*)d_out;

    cudaFuncSetAttribute(qkv_mma_kernel, cudaFuncAttributeMaxDynamicSharedMemorySize, K1_SMEM);
    cudaFuncSetAttribute(att_a_kernel, cudaFuncAttributeMaxDynamicSharedMemorySize, A2_SMEM);
    cudaFuncSetAttribute(weff_kernel, cudaFuncAttributeMaxDynamicSharedMemorySize, W2_SMEM);
    cudaFuncSetAttribute(outproj_mma_kernel, cudaFuncAttributeMaxDynamicSharedMemorySize, K3_SMEM);

    qkv_mma_kernel<<<dim3(72, 2, B_), 256, K1_SMEM>>>(x, Wqkv);
    att_a_kernel<<<dim3(NCH, 32, NSUB), 128, A2_SMEM>>>();
    weff_kernel<<<dim3(NCH, B_, 4), 256, W2_SMEM>>>(Wqkv, Wout);
    outproj_mma_kernel<<<dim3(GN_TILES, B_), 256, K3_SMEM>>>(x, bout, y);
    gnorm_kernel<<<dim3(36, B_), 256>>>(y, gamma, beta);
}

// round 16
// speedup vs baseline: 1.7154x; 1.1032x over previous
#include <cuda_runtime.h>
#include <cuda_fp16.h>
#include <cstdint>

// Problem constants
#define B_     8
#define CDIM   64
#define NPOS   9216      // 96*96
#define INNER  128
#define O3     384       // 3*INNER
#define HEADS  4
#define DHEAD  32
#define NCH    9
#define CHUNK  1024
#define NGC    (32 * NCH)   // 288 (g, ch) pairs
#define GN_TILES 36
#define NSUB   2            // A-partial sub-blocks (each covers 512 positions)

// Scratch (device globals — no allocations allowed)
__device__ __align__(16) __half g_qk[(size_t)B_ * 256 * NPOS];      // [b][o][n], o<256 (q,k), fp16
__device__ float g_part[B_][8][GN_TILES][2];                        // groupnorm partials
__device__ __align__(16) float g_Apart[NGC][NSUB][DHEAD * DHEAD];   // partial A (unnormalized)
__device__ __align__(16) uint32_t g_W2h[B_ * NCH][2][CDIM][CDIM / 2]; // fused weights fp16 hi/lo (half2)

// ---------------------------------------------------------------------------
// fp16 m16n8k16, f32 accum
#define MMA16(d, a, b)                                                        \
    asm volatile(                                                             \
        "mma.sync.aligned.m16n8k16.row.col.f32.f16.f16.f32 "                  \
        "{%0,%1,%2,%3},{%4,%5,%6,%7},{%8,%9},{%0,%1,%2,%3};"                  \
        : "+f"((d)[0]), "+f"((d)[1]), "+f"((d)[2]), "+f"((d)[3])              \
        : "r"((a)[0]), "r"((a)[1]), "r"((a)[2]), "r"((a)[3]),                 \
          "r"((b)[0]), "r"((b)[1]))

// hi/lo fp16 split of a float pair (hi = rn(x), lo = rn(x - hi))
__device__ __forceinline__ void split2(float v0, float v1, uint32_t& hi, uint32_t& lo) {
    __half h0 = __float2half_rn(v0), h1 = __float2half_rn(v1);
    hi = (uint32_t)__half_as_ushort(h0) | ((uint32_t)__half_as_ushort(h1) << 16);
    float l0 = v0 - __half2float(h0);
    float l1 = v1 - __half2float(h1);
    lo = (uint32_t)__half_as_ushort(__float2half_rn(l0)) |
         ((uint32_t)__half_as_ushort(__float2half_rn(l1)) << 16);
}

// ---------------------------------------------------------------------------
// K1 (fp16x3 mma): qk[b][o][n] = sum_c W_qkv[o][c] * x[b][c][n], o < 256.
// Persistent-tile: each CTA stages W once, loops over 4 n-tiles of 128.
// grid (18, 2, 8) = 288 CTAs (~1 wave at occ 2), 256 threads.
// ---------------------------------------------------------------------------
#define K1_PADW 36
#define K1_SMEM (128 * K1_PADW * 2 * 4)

__global__ __launch_bounds__(256, 2) void qkv_mma_kernel(const float* __restrict__ x,
                                                         const float* __restrict__ Wq) {
    extern __shared__ uint32_t smu[];
    uint32_t* Ahi = smu;                  // [128][36] half2 words
    uint32_t* Alo = Ahi + 128 * K1_PADW;

    const int b = blockIdx.z, mt = blockIdx.y, n00 = blockIdx.x * 512;
    const int tid = threadIdx.x;

    // stage + split W tile [128 M x 64 K] once
    for (int idx = tid; idx < 128 * 16; idx += 256) {
        int row = idx >> 4, c4 = (idx & 15) * 4;
        float4 w = *(const float4*)(Wq + (size_t)(mt * 128 + row) * CDIM + c4);
        int w0 = c4 >> 1;
        uint32_t h, l;
        split2(w.x, w.y, h, l);
        Ahi[row * K1_PADW + w0] = h; Alo[row * K1_PADW + w0] = l;
        split2(w.z, w.w, h, l);
        Ahi[row * K1_PADW + w0 + 1] = h; Alo[row * K1_PADW + w0 + 1] = l;
    }
    __syncthreads();

    const int wid = tid >> 5, lane = tid & 31, g = lane >> 2, tig = lane & 3;
    const int wm = (wid >> 2) * 64, wn = (wid & 3) * 32;

    for (int nt = 0; nt < 4; nt++) {
        const int n0 = n00 + nt * 128;
        const float* xb = x + (size_t)b * CDIM * NPOS + n0;

        float c[4][4][4];
#pragma unroll
        for (int i = 0; i < 4; i++)
#pragma unroll
            for (int j = 0; j < 4; j++)
#pragma unroll
                for (int q = 0; q < 4; q++) c[i][j][q] = 0.f;

#pragma unroll
        for (int k16 = 0; k16 < 4; k16++) {
            const int kb = k16 * 16, kb2 = k16 * 8;
            const float* r0 = xb + (size_t)(kb + 2 * tig) * NPOS;
            const float* r1 = r0 + NPOS;
            const float* r8 = r0 + 8 * NPOS;
            const float* r9 = r0 + 9 * NPOS;
            uint32_t bh[4][2], bl[4][2];
#pragma unroll
            for (int nf = 0; nf < 4; nf++) {
                int col = wn + nf * 8 + g;
                split2(__ldg(r0 + col), __ldg(r1 + col), bh[nf][0], bl[nf][0]);
                split2(__ldg(r8 + col), __ldg(r9 + col), bh[nf][1], bl[nf][1]);
            }
            uint32_t ah[4][4], al[4][4];
#pragma unroll
            for (int mf = 0; mf < 4; mf++) {
                int base = (wm + mf * 16 + g) * K1_PADW + kb2 + tig;
                int base8 = base + 8 * K1_PADW;
                ah[mf][0] = Ahi[base];     ah[mf][1] = Ahi[base8];
                ah[mf][2] = Ahi[base + 4]; ah[mf][3] = Ahi[base8 + 4];
                al[mf][0] = Alo[base];     al[mf][1] = Alo[base8];
                al[mf][2] = Alo[base + 4]; al[mf][3] = Alo[base8 + 4];
            }
#pragma unroll
            for (int mf = 0; mf < 4; mf++)
#pragma unroll
                for (int nf = 0; nf < 4; nf++) {
                    MMA16(c[mf][nf], ah[mf], bh[nf]);
                    MMA16(c[mf][nf], ah[mf], bl[nf]);
                    MMA16(c[mf][nf], al[mf], bh[nf]);
                }
        }

        __half* op = g_qk + ((size_t)b * 256 + mt * 128 + wm) * NPOS + n0 + wn;
#pragma unroll
        for (int mf = 0; mf < 4; mf++)
#pragma unroll
            for (int nf = 0; nf < 4; nf++) {
                int col = nf * 8 + tig * 2;
                *(__half2*)(op + (size_t)(mf * 16 + g) * NPOS + col) =
                    __floats2half2_rn(c[mf][nf][0], c[mf][nf][1]);
                *(__half2*)(op + (size_t)(mf * 16 + g + 8) * NPOS + col) =
                    __floats2half2_rn(c[mf][nf][2], c[mf][nf][3]);
            }
    }
}

// ---------------------------------------------------------------------------
// ATT2 (fp16 mma): partial A over 512 positions (4 x 128-chunks folded).
// grid (9, 32, 2) = 576 CTAs (~1 wave at occ 4), 128 threads.
// ---------------------------------------------------------------------------
#define A2_PADW 68
#define A2_WORDS (DHEAD * A2_PADW)
#define A2_SMEM_WORDS (2 * A2_WORDS)
#define A2_SMEM (A2_SMEM_WORDS * 4)

__global__ __launch_bounds__(128, 4) void att_a_kernel() {
    extern __shared__ uint32_t sm2[];
    uint32_t* Eq16 = sm2;                 // [32][68] half2 words
    uint32_t* Ks16 = sm2 + A2_WORDS;
    float* Apart = (float*)sm2;           // alias after mma: [4][32][33]

    const int ch = blockIdx.x, g = blockIdx.y, sub = blockIdx.z;
    const int gc = g * NCH + ch;
    const int b = g >> 2, head = g & 3;
    const int tid = threadIdx.x, lane = tid & 31, wrp = tid >> 5;
    const int j = tid;

    const __half* qbase0 = g_qk + ((size_t)(b * 256 + head * DHEAD)) * NPOS + ch * CHUNK + sub * 512;
    const __half* kbase0 = qbase0 + (size_t)128 * NPOS;

    __half* EqH = (__half*)Eq16;
    __half* KsH = (__half*)Ks16;

    const int gq = lane >> 2, tig = lane & 3;
    float acc[2][4][4];
#pragma unroll
    for (int i = 0; i < 2; i++)
#pragma unroll
        for (int jj = 0; jj < 4; jj++)
#pragma unroll
            for (int q = 0; q < 4; q++) acc[i][jj][q] = 0.f;

#pragma unroll
    for (int t = 0; t < 4; t++) {
        const __half* qbase = qbase0 + t * 128;
        const __half* kbase = kbase0 + t * 128;

        float kr[DHEAD];
#pragma unroll
        for (int d = 0; d < DHEAD; d++) kr[d] = __half2float(kbase[(size_t)d * NPOS + j]);
        float km = -1e30f;
#pragma unroll
        for (int d = 0; d < DHEAD; d++) km = fmaxf(km, kr[d]);
        float ks = 0.f;
#pragma unroll
        for (int d = 0; d < DHEAD; d++) { kr[d] = __expf(kr[d] - km); ks += kr[d]; }
        float kinv = 1.0f / ks;
#pragma unroll
        for (int d = 0; d < DHEAD; d++)
            KsH[d * (2 * A2_PADW) + j] = __float2half_rn(kr[d] * kinv);

        float qr[DHEAD];
#pragma unroll
        for (int d = 0; d < DHEAD; d++) qr[d] = __half2float(qbase[(size_t)d * NPOS + j]);
#pragma unroll
        for (int d = 0; d < DHEAD; d++)
            EqH[d * (2 * A2_PADW) + j] = __float2half_rn(__expf(qr[d]));
        __syncthreads();

#pragma unroll
        for (int s = 0; s < 2; s++) {
            const int kb2 = wrp * 16 + s * 8;
            uint32_t a[2][4];
#pragma unroll
            for (int mf = 0; mf < 2; mf++) {
                int base = (mf * 16 + gq) * A2_PADW + kb2 + tig;
                int base8 = base + 8 * A2_PADW;
                a[mf][0] = Eq16[base];     a[mf][1] = Eq16[base8];
                a[mf][2] = Eq16[base + 4]; a[mf][3] = Eq16[base8 + 4];
            }
            uint32_t bfr[4][2];
#pragma unroll
            for (int nf = 0; nf < 4; nf++) {
                int base = (nf * 8 + gq) * A2_PADW + kb2 + tig;
                bfr[nf][0] = Ks16[base];
                bfr[nf][1] = Ks16[base + 4];
            }
#pragma unroll
            for (int mf = 0; mf < 2; mf++)
#pragma unroll
                for (int nf = 0; nf < 4; nf++)
                    MMA16(acc[mf][nf], a[mf], bfr[nf]);
        }
        __syncthreads();
    }

#pragma unroll
    for (int mf = 0; mf < 2; mf++)
#pragma unroll
        for (int nf = 0; nf < 4; nf++) {
            int row = mf * 16 + gq, col = nf * 8 + tig * 2;
            Apart[(wrp * 32 + row) * 33 + col]     = acc[mf][nf][0];
            Apart[(wrp * 32 + row) * 33 + col + 1] = acc[mf][nf][1];
            Apart[(wrp * 32 + row + 8) * 33 + col]     = acc[mf][nf][2];
            Apart[(wrp * 32 + row + 8) * 33 + col + 1] = acc[mf][nf][3];
        }
    __syncthreads();

    float* out = g_Apart[gc][sub];
#pragma unroll
    for (int r = 0; r < 8; r++) {
        int idx = tid + 128 * r;
        int d = idx >> 5, dp = idx & 31;
        float s = 0.f;
#pragma unroll
        for (int w = 0; w < 4; w++) s += Apart[(w * 32 + d) * 33 + dp];
        out[idx] = s;
    }
}

// ---------------------------------------------------------------------------
// WEFF: per (ch, b, z): A-reduce over NSUB (redundant), 1/Zq, scale; 16-row
// o-slice of Weff and W2 (fp16 hi/lo output). grid (9, 8, 4), 256 threads.
// ---------------------------------------------------------------------------
#define W2_A    0                     // [4*32*33] = 4224
#define W2_WV   4224                  // [128][68] = 8704
#define W2_WO   12928                 // [16][132] = 2112
#define W2_WE   15040                 // [16][132] = 2112
#define W2_SMEM_WORDS 17152
#define W2_SMEM (W2_SMEM_WORDS * 4)

__global__ __launch_bounds__(256, 2) void weff_kernel(const float* __restrict__ Wqkv,
                                                      const float* __restrict__ Wout) {
    extern __shared__ float wsm[];
    __shared__ float rinv_s[128];
    const int ch = blockIdx.x, b = blockIdx.y, z = blockIdx.z;
    const int cc = b * NCH + ch;
    const int tid = threadIdx.x;

#pragma unroll
    for (int r = 0; r < 16; r++) {
        int idx = tid + 256 * r;
        int head = idx >> 10, e = idx & 1023;
        int d = e >> 5, dp = e & 31;
        const float* ap = g_Apart[(b * HEADS + head) * NCH + ch][0] + e;
        float s = 0.f;
#pragma unroll
        for (int sub = 0; sub < NSUB; sub++) s += ap[sub * DHEAD * DHEAD];
        wsm[W2_A + (head * 32 + d) * 33 + dp] = s;
    }
#pragma unroll
    for (int r = 0; r < 8; r++) {
        int idx = tid + 256 * r;
        int ic = idx >> 4, c4 = (idx & 15) * 4;
        float4 v = *(const float4*)(Wqkv + (size_t)(2 * INNER + ic) * CDIM + c4);
        float* d = wsm + W2_WV + ic * 68 + c4;
        d[0] = v.x; d[1] = v.y; d[2] = v.z; d[3] = v.w;
    }
#pragma unroll
    for (int r = 0; r < 2; r++) {
        int idx = tid + 256 * r;
        int o = idx >> 5, ic4 = (idx & 31) * 4;
        float4 v = *(const float4*)(Wout + (size_t)(z * 16 + o) * INNER + ic4);
        float* d = wsm + W2_WO + o * 132 + ic4;
        d[0] = v.x; d[1] = v.y; d[2] = v.z; d[3] = v.w;
    }
    __syncthreads();

    if (tid < 128) {
        float s = 0.f;
#pragma unroll
        for (int dp = 0; dp < DHEAD; dp++) s += wsm[W2_A + tid * 33 + dp];
        rinv_s[tid] = 1.0f / s;
    }
    __syncthreads();
#pragma unroll
    for (int r = 0; r < 16; r++) {
        int idx = tid + 256 * r;
        int row = idx >> 5, dp = idx & 31;
        wsm[W2_A + row * 33 + dp] *= rinv_s[row];
    }
    __syncthreads();

#pragma unroll
    for (int r = 0; r < 8; r++) {
        int idx = tid + 256 * r;
        int o = idx >> 7, ic = idx & 127, head = ic >> 5, dp = ic & 31;
        float acc = 0.f;
#pragma unroll
        for (int d = 0; d < DHEAD; d++)
            acc += wsm[W2_WO + o * 132 + head * 32 + d] * wsm[W2_A + (head * 32 + d) * 33 + dp];
        wsm[W2_WE + o * 132 + ic] = acc;
    }
    __syncthreads();

    const int ol = tid >> 4, c0 = (tid & 15) * 4;
    float w2[4] = {0.f, 0.f, 0.f, 0.f};
#pragma unroll
    for (int ic = 0; ic < INNER; ic++) {
        float we = wsm[W2_WE + ol * 132 + ic];
        const float* wv = wsm + W2_WV + ic * 68 + c0;
        w2[0] += we * wv[0];
        w2[1] += we * wv[1];
        w2[2] += we * wv[2];
        w2[3] += we * wv[3];
    }
    const int og = z * 16 + ol, w0 = c0 >> 1;
    uint32_t h, l;
    split2(w2[0], w2[1], h, l);
    g_W2h[cc][0][og][w0] = h;
    g_W2h[cc][1][og][w0] = l;
    split2(w2[2], w2[3], h, l);
    g_W2h[cc][0][og][w0 + 1] = h;
    g_W2h[cc][1][og][w0 + 1] = l;
}

// ---------------------------------------------------------------------------
// K3'' (fp16x3 mma): y = W2(b,ch) @ x + b_out, groupnorm partials.
// CTA tile [64 M x 256 N], K=64. grid (36, 8) = 288 CTAs (~1 wave), occ 2.
// (unchanged R15)
// ---------------------------------------------------------------------------
#define K3_PADW 36
#define K3_SMEM (64 * K3_PADW * 2 * 4)   // 18432 B

__global__ __launch_bounds__(256, 2) void outproj_mma_kernel(const float* __restrict__ x,
                                                             const float* __restrict__ bout,
                                                             float* __restrict__ y) {
    extern __shared__ uint32_t smu[];
    uint32_t* Ahi = smu;                  // [64][36] half2 words
    uint32_t* Alo = Ahi + 64 * K3_PADW;
    __shared__ float swp[8][8][2];

    const int b = blockIdx.y, n0 = blockIdx.x * 256, tid = threadIdx.x;
    const int cc = b * NCH + (n0 / CHUNK);

    for (int idx = tid; idx < 64 * 8; idx += 256) {
        int row = idx >> 3, w4 = (idx & 7) * 4;
        uint4 h4 = *(const uint4*)(&g_W2h[cc][0][row][w4]);
        uint4 l4 = *(const uint4*)(&g_W2h[cc][1][row][w4]);
        Ahi[row * K3_PADW + w4]     = h4.x;
        Ahi[row * K3_PADW + w4 + 1] = h4.y;
        Ahi[row * K3_PADW + w4 + 2] = h4.z;
        Ahi[row * K3_PADW + w4 + 3] = h4.w;
        Alo[row * K3_PADW + w4]     = l4.x;
        Alo[row * K3_PADW + w4 + 1] = l4.y;
        Alo[row * K3_PADW + w4 + 2] = l4.z;
        Alo[row * K3_PADW + w4 + 3] = l4.w;
    }
    __syncthreads();

    const int wid = tid >> 5, lane = tid & 31, g = lane >> 2, tig = lane & 3;
    const int wn = wid * 32;   // warp tile [64 M x 32 N]
    const float* xb = x + (size_t)b * CDIM * NPOS + n0;

    float acc[4][4][4];
#pragma unroll
    for (int i = 0; i < 4; i++)
#pragma unroll
        for (int j = 0; j < 4; j++)
#pragma unroll
            for (int q = 0; q < 4; q++) acc[i][j][q] = 0.f;

#pragma unroll
    for (int k16 = 0; k16 < 4; k16++) {
        const int kb = k16 * 16, kb2 = k16 * 8;
        const float* r0 = xb + (size_t)(kb + 2 * tig) * NPOS;
        const float* r1 = r0 + NPOS;
        const float* r8 = r0 + 8 * NPOS;
        const float* r9 = r0 + 9 * NPOS;
        uint32_t bh[4][2], bl[4][2];
#pragma unroll
        for (int nf = 0; nf < 4; nf++) {
            int col = wn + nf * 8 + g;
            split2(__ldg(r0 + col), __ldg(r1 + col), bh[nf][0], bl[nf][0]);
            split2(__ldg(r8 + col), __ldg(r9 + col), bh[nf][1], bl[nf][1]);
        }
        uint32_t ah[4][4], al[4][4];
#pragma unroll
        for (int mf = 0; mf < 4; mf++) {
            int base = (mf * 16 + g) * K3_PADW + kb2 + tig;
            int base8 = base + 8 * K3_PADW;
            ah[mf][0] = Ahi[base];     ah[mf][1] = Ahi[base8];
            ah[mf][2] = Ahi[base + 4]; ah[mf][3] = Ahi[base8 + 4];
            al[mf][0] = Alo[base];     al[mf][1] = Alo[base8];
            al[mf][2] = Alo[base + 4]; al[mf][3] = Alo[base8 + 4];
        }
#pragma unroll
        for (int mf = 0; mf < 4; mf++)
#pragma unroll
            for (int nf = 0; nf < 4; nf++) {
                MMA16(acc[mf][nf], ah[mf], bh[nf]);
                MMA16(acc[mf][nf], ah[mf], bl[nf]);
                MMA16(acc[mf][nf], al[mf], bh[nf]);
            }
    }

    float gs[8], gq[8];
#pragma unroll
    for (int i = 0; i < 8; i++) { gs[i] = 0.f; gq[i] = 0.f; }

    float* yp = y + (size_t)b * CDIM * NPOS + n0 + wn;
#pragma unroll
    for (int mf = 0; mf < 4; mf++) {
        float bias0 = __ldg(bout + mf * 16 + g);
        float bias1 = __ldg(bout + mf * 16 + g + 8);
#pragma unroll
        for (int nf = 0; nf < 4; nf++) {
            int col = nf * 8 + tig * 2;
            float v0 = acc[mf][nf][0] + bias0, v1 = acc[mf][nf][1] + bias0;
            float v2 = acc[mf][nf][2] + bias1, v3 = acc[mf][nf][3] + bias1;
            *(float2*)(yp + (size_t)(mf * 16 + g) * NPOS + col) = make_float2(v0, v1);
            *(float2*)(yp + (size_t)(mf * 16 + g + 8) * NPOS + col) = make_float2(v2, v3);
            gs[2 * mf]     += v0 + v1;
            gq[2 * mf]     += v0 * v0 + v1 * v1;
            gs[2 * mf + 1] += v2 + v3;
            gq[2 * mf + 1] += v2 * v2 + v3 * v3;
        }
    }

#pragma unroll
    for (int gr = 0; gr < 8; gr++) {
        float s = gs[gr], q = gq[gr];
        for (int off = 16; off; off >>= 1) {
            s += __shfl_xor_sync(0xffffffffu, s, off);
            q += __shfl_xor_sync(0xffffffffu, q, off);
        }
        if (lane == 0) { swp[wid][gr][0] = s; swp[wid][gr][1] = q; }
    }
    __syncthreads();
    if (tid < 16) {
        int gr = tid >> 1, qq = tid & 1;
        float s = 0.f;
#pragma unroll
        for (int w = 0; w < 8; w++) s += swp[w][gr][qq];
        g_part[b][gr][blockIdx.x][qq] = s;
    }
}

// ---------------------------------------------------------------------------
// K4: groupnorm finalize. grid (36, 8), 256 threads. (unchanged R15)
// ---------------------------------------------------------------------------
__global__ __launch_bounds__(256, 4) void gnorm_kernel(float* __restrict__ y,
                                                       const float* __restrict__ gamma,
                                                       const float* __restrict__ beta) {
    __shared__ float tmp[8][2];
    __shared__ float mu[8], rs[8];
    const int b = blockIdx.y, n0 = blockIdx.x * 256, tid = threadIdx.x;

    if (tid < 16) {
        int g = tid >> 1, qq = tid & 1;
        float s = 0.f;
        for (int t = 0; t < GN_TILES; t++) s += g_part[b][g][t][qq];
        tmp[g][qq] = s;
    }
    __syncthreads();
    if (tid < 8) {
        const float invn = 1.0f / (8.0f * NPOS);
        float m = tmp[tid][0] * invn;
        float v = tmp[tid][1] * invn - m * m;
        mu[tid] = m;
        rs[tid] = rsqrtf(v + 1e-5f);
    }
    __syncthreads();

    const int col4 = tid & 63, crow = tid >> 6;
    float* yb = y + (size_t)b * CDIM * NPOS + n0 + col4 * 4;
#pragma unroll
    for (int c = crow; c < CDIM; c += 4) {
        float4* p = (float4*)(yb + (size_t)c * NPOS);
        float4 v = *p;
        int g = c >> 3;
        float sc = rs[g] * __ldg(gamma + c);
        float sh = __ldg(beta + c) - mu[g] * sc;
        v.x = v.x * sc + sh;
        v.y = v.y * sc + sh;
        v.z = v.z * sc + sh;
        v.w = v.w * sc + sh;
        *p = v;
    }
}

// ---------------------------------------------------------------------------
extern "C" void kernel_launch(void* const* d_in, const int* in_sizes, int n_in,
                              void* d_out, int out_size) {
    const float* x     = (const float*)d_in[0];
    const float* Wqkv  = (const float*)d_in[1];
    const float* Wout  = (const float*)d_in[2];
    const float* bout  = (const float*)d_in[3];
    const float* gamma = (const float*)d_in[4];
    const float* beta  = (const float*)d_in[5];
    float* y = (float*)d_out;

    cudaFuncSetAttribute(qkv_mma_kernel, cudaFuncAttributeMaxDynamicSharedMemorySize, K1_SMEM);
    cudaFuncSetAttribute(att_a_kernel, cudaFuncAttributeMaxDynamicSharedMemorySize, A2_SMEM);
    cudaFuncSetAttribute(weff_kernel, cudaFuncAttributeMaxDynamicSharedMemorySize, W2_SMEM);
    cudaFuncSetAttribute(outproj_mma_kernel, cudaFuncAttributeMaxDynamicSharedMemorySize, K3_SMEM);

    qkv_mma_kernel<<<dim3(18, 2, B_), 256, K1_SMEM>>>(x, Wqkv);
    att_a_kernel<<<dim3(NCH, 32, NSUB), 128, A2_SMEM>>>();
    weff_kernel<<<dim3(NCH, B_, 4), 256, W2_SMEM>>>(Wqkv, Wout);
    outproj_mma_kernel<<<dim3(GN_TILES, B_), 256, K3_SMEM>>>(x, bout, y);
    gnorm_kernel<<<dim3(36, B_), 256>>>(y, gamma, beta);
}

// round 17
// speedup vs baseline: 1.9019x; 1.1087x over previous
#include <cuda_runtime.h>
#include <cuda_fp16.h>
#include <cstdint>

// Problem constants
#define B_     8
#define CDIM   64
#define NPOS   9216      // 96*96
#define INNER  128
#define O3     384       // 3*INNER
#define HEADS  4
#define DHEAD  32
#define NCH    9
#define CHUNK  1024
#define NGC    (32 * NCH)   // 288 (g, ch) pairs
#define GN_TILES 36
#define NSUB   2            // A-partial sub-blocks (each covers 512 positions)

// Scratch (device globals — no allocations allowed)
__device__ __align__(16) __half g_qk[(size_t)B_ * 256 * NPOS];      // [b][o][n], o<256 (q,k), fp16
__device__ float g_part[B_][8][GN_TILES][2];                        // groupnorm partials
__device__ __align__(16) float g_Apart[NGC][NSUB][DHEAD * DHEAD];   // partial A (unnormalized)
__device__ __align__(16) uint32_t g_W2h[B_ * NCH][2][CDIM][CDIM / 2]; // fused weights fp16 hi/lo (half2)

// ---------------------------------------------------------------------------
// fp16 m16n8k16, f32 accum
#define MMA16(d, a, b)                                                        \
    asm volatile(                                                             \
        "mma.sync.aligned.m16n8k16.row.col.f32.f16.f16.f32 "                  \
        "{%0,%1,%2,%3},{%4,%5,%6,%7},{%8,%9},{%0,%1,%2,%3};"                  \
        : "+f"((d)[0]), "+f"((d)[1]), "+f"((d)[2]), "+f"((d)[3])              \
        : "r"((a)[0]), "r"((a)[1]), "r"((a)[2]), "r"((a)[3]),                 \
          "r"((b)[0]), "r"((b)[1]))

__device__ __forceinline__ uint32_t pack_h2(float v0, float v1) {
    __half2 h = __floats2half2_rn(v0, v1);
    return *(uint32_t*)&h;
}
// hi/lo fp16 split of a float pair (hi = rn(x), lo = rn(x - hi))
__device__ __forceinline__ void split2(float v0, float v1, uint32_t& hi, uint32_t& lo) {
    __half h0 = __float2half_rn(v0), h1 = __float2half_rn(v1);
    hi = (uint32_t)__half_as_ushort(h0) | ((uint32_t)__half_as_ushort(h1) << 16);
    float l0 = v0 - __half2float(h0);
    float l1 = v1 - __half2float(h1);
    lo = (uint32_t)__half_as_ushort(__float2half_rn(l0)) |
         ((uint32_t)__half_as_ushort(__float2half_rn(l1)) << 16);
}

// ---------------------------------------------------------------------------
// K1 (plain fp16 mma): qk[b][o][n] = sum_c W_qkv[o][c] * x[b][c][n], o < 256.
// Output is fp16 anyway; input rounding errors average out in A.
// Persistent-tile, grid (18, 2, 8) = 288 CTAs, 256 threads, occ 2.
// ---------------------------------------------------------------------------
#define K1_PADW 36
#define K1_SMEM (128 * K1_PADW * 4)

__global__ __launch_bounds__(256, 2) void qkv_mma_kernel(const float* __restrict__ x,
                                                         const float* __restrict__ Wq) {
    extern __shared__ uint32_t smu[];
    uint32_t* A16 = smu;                  // [128][36] half2 words

    const int b = blockIdx.z, mt = blockIdx.y, n00 = blockIdx.x * 512;
    const int tid = threadIdx.x;

    // stage W tile [128 M x 64 K] as fp16 half2 words
    for (int idx = tid; idx < 128 * 16; idx += 256) {
        int row = idx >> 4, c4 = (idx & 15) * 4;
        float4 w = *(const float4*)(Wq + (size_t)(mt * 128 + row) * CDIM + c4);
        int w0 = c4 >> 1;
        A16[row * K1_PADW + w0]     = pack_h2(w.x, w.y);
        A16[row * K1_PADW + w0 + 1] = pack_h2(w.z, w.w);
    }
    __syncthreads();

    const int wid = tid >> 5, lane = tid & 31, g = lane >> 2, tig = lane & 3;
    const int wm = (wid >> 2) * 64, wn = (wid & 3) * 32;

    for (int nt = 0; nt < 4; nt++) {
        const int n0 = n00 + nt * 128;
        const float* xb = x + (size_t)b * CDIM * NPOS + n0;

        float c[4][4][4];
#pragma unroll
        for (int i = 0; i < 4; i++)
#pragma unroll
            for (int j = 0; j < 4; j++)
#pragma unroll
                for (int q = 0; q < 4; q++) c[i][j][q] = 0.f;

#pragma unroll
        for (int k16 = 0; k16 < 4; k16++) {
            const int kb = k16 * 16, kb2 = k16 * 8;
            const float* r0 = xb + (size_t)(kb + 2 * tig) * NPOS;
            const float* r1 = r0 + NPOS;
            const float* r8 = r0 + 8 * NPOS;
            const float* r9 = r0 + 9 * NPOS;
            uint32_t bfr[4][2];
#pragma unroll
            for (int nf = 0; nf < 4; nf++) {
                int col = wn + nf * 8 + g;
                bfr[nf][0] = pack_h2(__ldg(r0 + col), __ldg(r1 + col));
                bfr[nf][1] = pack_h2(__ldg(r8 + col), __ldg(r9 + col));
            }
            uint32_t a[4][4];
#pragma unroll
            for (int mf = 0; mf < 4; mf++) {
                int base = (wm + mf * 16 + g) * K1_PADW + kb2 + tig;
                int base8 = base + 8 * K1_PADW;
                a[mf][0] = A16[base];     a[mf][1] = A16[base8];
                a[mf][2] = A16[base + 4]; a[mf][3] = A16[base8 + 4];
            }
#pragma unroll
            for (int mf = 0; mf < 4; mf++)
#pragma unroll
                for (int nf = 0; nf < 4; nf++)
                    MMA16(c[mf][nf], a[mf], bfr[nf]);
        }

        __half* op = g_qk + ((size_t)b * 256 + mt * 128 + wm) * NPOS + n0 + wn;
#pragma unroll
        for (int mf = 0; mf < 4; mf++)
#pragma unroll
            for (int nf = 0; nf < 4; nf++) {
                int col = nf * 8 + tig * 2;
                *(__half2*)(op + (size_t)(mf * 16 + g) * NPOS + col) =
                    __floats2half2_rn(c[mf][nf][0], c[mf][nf][1]);
                *(__half2*)(op + (size_t)(mf * 16 + g + 8) * NPOS + col) =
                    __floats2half2_rn(c[mf][nf][2], c[mf][nf][3]);
            }
    }
}

// ---------------------------------------------------------------------------
// ATT2 (fp16 mma): partial A over 512 positions (4 x 128-chunks folded).
// grid (9, 32, 2) = 576 CTAs, 128 threads, occ 4. (unchanged R16)
// ---------------------------------------------------------------------------
#define A2_PADW 68
#define A2_WORDS (DHEAD * A2_PADW)
#define A2_SMEM_WORDS (2 * A2_WORDS)
#define A2_SMEM (A2_SMEM_WORDS * 4)

__global__ __launch_bounds__(128, 4) void att_a_kernel() {
    extern __shared__ uint32_t sm2[];
    uint32_t* Eq16 = sm2;                 // [32][68] half2 words
    uint32_t* Ks16 = sm2 + A2_WORDS;
    float* Apart = (float*)sm2;           // alias after mma: [4][32][33]

    const int ch = blockIdx.x, g = blockIdx.y, sub = blockIdx.z;
    const int gc = g * NCH + ch;
    const int b = g >> 2, head = g & 3;
    const int tid = threadIdx.x, lane = tid & 31, wrp = tid >> 5;
    const int j = tid;

    const __half* qbase0 = g_qk + ((size_t)(b * 256 + head * DHEAD)) * NPOS + ch * CHUNK + sub * 512;
    const __half* kbase0 = qbase0 + (size_t)128 * NPOS;

    __half* EqH = (__half*)Eq16;
    __half* KsH = (__half*)Ks16;

    const int gq = lane >> 2, tig = lane & 3;
    float acc[2][4][4];
#pragma unroll
    for (int i = 0; i < 2; i++)
#pragma unroll
        for (int jj = 0; jj < 4; jj++)
#pragma unroll
            for (int q = 0; q < 4; q++) acc[i][jj][q] = 0.f;

#pragma unroll
    for (int t = 0; t < 4; t++) {
        const __half* qbase = qbase0 + t * 128;
        const __half* kbase = kbase0 + t * 128;

        float kr[DHEAD];
#pragma unroll
        for (int d = 0; d < DHEAD; d++) kr[d] = __half2float(kbase[(size_t)d * NPOS + j]);
        float km = -1e30f;
#pragma unroll
        for (int d = 0; d < DHEAD; d++) km = fmaxf(km, kr[d]);
        float ks = 0.f;
#pragma unroll
        for (int d = 0; d < DHEAD; d++) { kr[d] = __expf(kr[d] - km); ks += kr[d]; }
        float kinv = 1.0f / ks;
#pragma unroll
        for (int d = 0; d < DHEAD; d++)
            KsH[d * (2 * A2_PADW) + j] = __float2half_rn(kr[d] * kinv);

        float qr[DHEAD];
#pragma unroll
        for (int d = 0; d < DHEAD; d++) qr[d] = __half2float(qbase[(size_t)d * NPOS + j]);
#pragma unroll
        for (int d = 0; d < DHEAD; d++)
            EqH[d * (2 * A2_PADW) + j] = __float2half_rn(__expf(qr[d]));
        __syncthreads();

#pragma unroll
        for (int s = 0; s < 2; s++) {
            const int kb2 = wrp * 16 + s * 8;
            uint32_t a[2][4];
#pragma unroll
            for (int mf = 0; mf < 2; mf++) {
                int base = (mf * 16 + gq) * A2_PADW + kb2 + tig;
                int base8 = base + 8 * A2_PADW;
                a[mf][0] = Eq16[base];     a[mf][1] = Eq16[base8];
                a[mf][2] = Eq16[base + 4]; a[mf][3] = Eq16[base8 + 4];
            }
            uint32_t bfr[4][2];
#pragma unroll
            for (int nf = 0; nf < 4; nf++) {
                int base = (nf * 8 + gq) * A2_PADW + kb2 + tig;
                bfr[nf][0] = Ks16[base];
                bfr[nf][1] = Ks16[base + 4];
            }
#pragma unroll
            for (int mf = 0; mf < 2; mf++)
#pragma unroll
                for (int nf = 0; nf < 4; nf++)
                    MMA16(acc[mf][nf], a[mf], bfr[nf]);
        }
        __syncthreads();
    }

#pragma unroll
    for (int mf = 0; mf < 2; mf++)
#pragma unroll
        for (int nf = 0; nf < 4; nf++) {
            int row = mf * 16 + gq, col = nf * 8 + tig * 2;
            Apart[(wrp * 32 + row) * 33 + col]     = acc[mf][nf][0];
            Apart[(wrp * 32 + row) * 33 + col + 1] = acc[mf][nf][1];
            Apart[(wrp * 32 + row + 8) * 33 + col]     = acc[mf][nf][2];
            Apart[(wrp * 32 + row + 8) * 33 + col + 1] = acc[mf][nf][3];
        }
    __syncthreads();

    float* out = g_Apart[gc][sub];
#pragma unroll
    for (int r = 0; r < 8; r++) {
        int idx = tid + 128 * r;
        int d = idx >> 5, dp = idx & 31;
        float s = 0.f;
#pragma unroll
        for (int w = 0; w < 4; w++) s += Apart[(w * 32 + d) * 33 + dp];
        out[idx] = s;
    }
}

// ---------------------------------------------------------------------------
// WEFF: per (ch, b, z): A-reduce over NSUB (redundant), 1/Zq, scale; 16-row
// o-slice of Weff and W2 (fp16 hi/lo output). grid (9, 8, 4). (unchanged)
// ---------------------------------------------------------------------------
#define W2_A    0                     // [4*32*33] = 4224
#define W2_WV   4224                  // [128][68] = 8704
#define W2_WO   12928                 // [16][132] = 2112
#define W2_WE   15040                 // [16][132] = 2112
#define W2_SMEM_WORDS 17152
#define W2_SMEM (W2_SMEM_WORDS * 4)

__global__ __launch_bounds__(256, 2) void weff_kernel(const float* __restrict__ Wqkv,
                                                      const float* __restrict__ Wout) {
    extern __shared__ float wsm[];
    __shared__ float rinv_s[128];
    const int ch = blockIdx.x, b = blockIdx.y, z = blockIdx.z;
    const int cc = b * NCH + ch;
    const int tid = threadIdx.x;

#pragma unroll
    for (int r = 0; r < 16; r++) {
        int idx = tid + 256 * r;
        int head = idx >> 10, e = idx & 1023;
        int d = e >> 5, dp = e & 31;
        const float* ap = g_Apart[(b * HEADS + head) * NCH + ch][0] + e;
        float s = 0.f;
#pragma unroll
        for (int sub = 0; sub < NSUB; sub++) s += ap[sub * DHEAD * DHEAD];
        wsm[W2_A + (head * 32 + d) * 33 + dp] = s;
    }
#pragma unroll
    for (int r = 0; r < 8; r++) {
        int idx = tid + 256 * r;
        int ic = idx >> 4, c4 = (idx & 15) * 4;
        float4 v = *(const float4*)(Wqkv + (size_t)(2 * INNER + ic) * CDIM + c4);
        float* d = wsm + W2_WV + ic * 68 + c4;
        d[0] = v.x; d[1] = v.y; d[2] = v.z; d[3] = v.w;
    }
#pragma unroll
    for (int r = 0; r < 2; r++) {
        int idx = tid + 256 * r;
        int o = idx >> 5, ic4 = (idx & 31) * 4;
        float4 v = *(const float4*)(Wout + (size_t)(z * 16 + o) * INNER + ic4);
        float* d = wsm + W2_WO + o * 132 + ic4;
        d[0] = v.x; d[1] = v.y; d[2] = v.z; d[3] = v.w;
    }
    __syncthreads();

    if (tid < 128) {
        float s = 0.f;
#pragma unroll
        for (int dp = 0; dp < DHEAD; dp++) s += wsm[W2_A + tid * 33 + dp];
        rinv_s[tid] = 1.0f / s;
    }
    __syncthreads();
#pragma unroll
    for (int r = 0; r < 16; r++) {
        int idx = tid + 256 * r;
        int row = idx >> 5, dp = idx & 31;
        wsm[W2_A + row * 33 + dp] *= rinv_s[row];
    }
    __syncthreads();

#pragma unroll
    for (int r = 0; r < 8; r++) {
        int idx = tid + 256 * r;
        int o = idx >> 7, ic = idx & 127, head = ic >> 5, dp = ic & 31;
        float acc = 0.f;
#pragma unroll
        for (int d = 0; d < DHEAD; d++)
            acc += wsm[W2_WO + o * 132 + head * 32 + d] * wsm[W2_A + (head * 32 + d) * 33 + dp];
        wsm[W2_WE + o * 132 + ic] = acc;
    }
    __syncthreads();

    const int ol = tid >> 4, c0 = (tid & 15) * 4;
    float w2[4] = {0.f, 0.f, 0.f, 0.f};
#pragma unroll
    for (int ic = 0; ic < INNER; ic++) {
        float we = wsm[W2_WE + ol * 132 + ic];
        const float* wv = wsm + W2_WV + ic * 68 + c0;
        w2[0] += we * wv[0];
        w2[1] += we * wv[1];
        w2[2] += we * wv[2];
        w2[3] += we * wv[3];
    }
    const int og = z * 16 + ol, w0 = c0 >> 1;
    uint32_t h, l;
    split2(w2[0], w2[1], h, l);
    g_W2h[cc][0][og][w0] = h;
    g_W2h[cc][1][og][w0] = l;
    split2(w2[2], w2[3], h, l);
    g_W2h[cc][0][og][w0 + 1] = h;
    g_W2h[cc][1][og][w0 + 1] = l;
}

// ---------------------------------------------------------------------------
// K3'' (fp16x2 mma): y = W2(b,ch) @ x + b_out, groupnorm partials.
// W2 split hi/lo (full precision); x plain fp16 (error ~1.4e-4 on y).
// CTA tile [64 M x 256 N], K=64. grid (36, 8) = 288 CTAs, occ 2.
// ---------------------------------------------------------------------------
#define K3_PADW 36
#define K3_SMEM (64 * K3_PADW * 2 * 4)   // 18432 B

__global__ __launch_bounds__(256, 2) void outproj_mma_kernel(const float* __restrict__ x,
                                                             const float* __restrict__ bout,
                                                             float* __restrict__ y) {
    extern __shared__ uint32_t smu[];
    uint32_t* Ahi = smu;                  // [64][36] half2 words
    uint32_t* Alo = Ahi + 64 * K3_PADW;
    __shared__ float swp[8][8][2];

    const int b = blockIdx.y, n0 = blockIdx.x * 256, tid = threadIdx.x;
    const int cc = b * NCH + (n0 / CHUNK);

    for (int idx = tid; idx < 64 * 8; idx += 256) {
        int row = idx >> 3, w4 = (idx & 7) * 4;
        uint4 h4 = *(const uint4*)(&g_W2h[cc][0][row][w4]);
        uint4 l4 = *(const uint4*)(&g_W2h[cc][1][row][w4]);
        Ahi[row * K3_PADW + w4]     = h4.x;
        Ahi[row * K3_PADW + w4 + 1] = h4.y;
        Ahi[row * K3_PADW + w4 + 2] = h4.z;
        Ahi[row * K3_PADW + w4 + 3] = h4.w;
        Alo[row * K3_PADW + w4]     = l4.x;
        Alo[row * K3_PADW + w4 + 1] = l4.y;
        Alo[row * K3_PADW + w4 + 2] = l4.z;
        Alo[row * K3_PADW + w4 + 3] = l4.w;
    }
    __syncthreads();

    const int wid = tid >> 5, lane = tid & 31, g = lane >> 2, tig = lane & 3;
    const int wn = wid * 32;   // warp tile [64 M x 32 N]
    const float* xb = x + (size_t)b * CDIM * NPOS + n0;

    float acc[4][4][4];
#pragma unroll
    for (int i = 0; i < 4; i++)
#pragma unroll
        for (int j = 0; j < 4; j++)
#pragma unroll
            for (int q = 0; q < 4; q++) acc[i][j][q] = 0.f;

#pragma unroll
    for (int k16 = 0; k16 < 4; k16++) {
        const int kb = k16 * 16, kb2 = k16 * 8;
        const float* r0 = xb + (size_t)(kb + 2 * tig) * NPOS;
        const float* r1 = r0 + NPOS;
        const float* r8 = r0 + 8 * NPOS;
        const float* r9 = r0 + 9 * NPOS;
        uint32_t bfr[4][2];
#pragma unroll
        for (int nf = 0; nf < 4; nf++) {
            int col = wn + nf * 8 + g;
            bfr[nf][0] = pack_h2(__ldg(r0 + col), __ldg(r1 + col));
            bfr[nf][1] = pack_h2(__ldg(r8 + col), __ldg(r9 + col));
        }
        uint32_t ah[4][4], al[4][4];
#pragma unroll
        for (int mf = 0; mf < 4; mf++) {
            int base = (mf * 16 + g) * K3_PADW + kb2 + tig;
            int base8 = base + 8 * K3_PADW;
            ah[mf][0] = Ahi[base];     ah[mf][1] = Ahi[base8];
            ah[mf][2] = Ahi[base + 4]; ah[mf][3] = Ahi[base8 + 4];
            al[mf][0] = Alo[base];     al[mf][1] = Alo[base8];
            al[mf][2] = Alo[base + 4]; al[mf][3] = Alo[base8 + 4];
        }
#pragma unroll
        for (int mf = 0; mf < 4; mf++)
#pragma unroll
            for (int nf = 0; nf < 4; nf++) {
                MMA16(acc[mf][nf], ah[mf], bfr[nf]);
                MMA16(acc[mf][nf], al[mf], bfr[nf]);
            }
    }

    float gs[8], gq[8];
#pragma unroll
    for (int i = 0; i < 8; i++) { gs[i] = 0.f; gq[i] = 0.f; }

    float* yp = y + (size_t)b * CDIM * NPOS + n0 + wn;
#pragma unroll
    for (int mf = 0; mf < 4; mf++) {
        float bias0 = __ldg(bout + mf * 16 + g);
        float bias1 = __ldg(bout + mf * 16 + g + 8);
#pragma unroll
        for (int nf = 0; nf < 4; nf++) {
            int col = nf * 8 + tig * 2;
            float v0 = acc[mf][nf][0] + bias0, v1 = acc[mf][nf][1] + bias0;
            float v2 = acc[mf][nf][2] + bias1, v3 = acc[mf][nf][3] + bias1;
            *(float2*)(yp + (size_t)(mf * 16 + g) * NPOS + col) = make_float2(v0, v1);
            *(float2*)(yp + (size_t)(mf * 16 + g + 8) * NPOS + col) = make_float2(v2, v3);
            gs[2 * mf]     += v0 + v1;
            gq[2 * mf]     += v0 * v0 + v1 * v1;
            gs[2 * mf + 1] += v2 + v3;
            gq[2 * mf + 1] += v2 * v2 + v3 * v3;
        }
    }

#pragma unroll
    for (int gr = 0; gr < 8; gr++) {
        float s = gs[gr], q = gq[gr];
        for (int off = 16; off; off >>= 1) {
            s += __shfl_xor_sync(0xffffffffu, s, off);
            q += __shfl_xor_sync(0xffffffffu, q, off);
        }
        if (lane == 0) { swp[wid][gr][0] = s; swp[wid][gr][1] = q; }
    }
    __syncthreads();
    if (tid < 16) {
        int gr = tid >> 1, qq = tid & 1;
        float s = 0.f;
#pragma unroll
        for (int w = 0; w < 8; w++) s += swp[w][gr][qq];
        g_part[b][gr][blockIdx.x][qq] = s;
    }
}

// ---------------------------------------------------------------------------
// K4: groupnorm finalize. grid (36, 8), 256 threads. (unchanged)
// ---------------------------------------------------------------------------
__global__ __launch_bounds__(256, 4) void gnorm_kernel(float* __restrict__ y,
                                                       const float* __restrict__ gamma,
                                                       const float* __restrict__ beta) {
    __shared__ float tmp[8][2];
    __shared__ float mu[8], rs[8];
    const int b = blockIdx.y, n0 = blockIdx.x * 256, tid = threadIdx.x;

    if (tid < 16) {
        int g = tid >> 1, qq = tid & 1;
        float s = 0.f;
        for (int t = 0; t < GN_TILES; t++) s += g_part[b][g][t][qq];
        tmp[g][qq] = s;
    }
    __syncthreads();
    if (tid < 8) {
        const float invn = 1.0f / (8.0f * NPOS);
        float m = tmp[tid][0] * invn;
        float v = tmp[tid][1] * invn - m * m;
        mu[tid] = m;
        rs[tid] = rsqrtf(v + 1e-5f);
    }
    __syncthreads();

    const int col4 = tid & 63, crow = tid >> 6;
    float* yb = y + (size_t)b * CDIM * NPOS + n0 + col4 * 4;
#pragma unroll
    for (int c = crow; c < CDIM; c += 4) {
        float4* p = (float4*)(yb + (size_t)c * NPOS);
        float4 v = *p;
        int g = c >> 3;
        float sc = rs[g] * __ldg(gamma + c);
        float sh = __ldg(beta + c) - mu[g] * sc;
        v.x = v.x * sc + sh;
        v.y = v.y * sc + sh;
        v.z = v.z * sc + sh;
        v.w = v.w * sc + sh;
        *p = v;
    }
}

// ---------------------------------------------------------------------------
extern "C" void kernel_launch(void* const* d_in, const int* in_sizes, int n_in,
                              void* d_out, int out_size) {
    const float* x     = (const float*)d_in[0];
    const float* Wqkv  = (const float*)d_in[1];
    const float* Wout  = (const float*)d_in[2];
    const float* bout  = (const float*)d_in[3];
    const float* gamma = (const float*)d_in[4];
    const float* beta  = (const float*)d_in[5];
    float* y = (float*)d_out;

    cudaFuncSetAttribute(qkv_mma_kernel, cudaFuncAttributeMaxDynamicSharedMemorySize, K1_SMEM);
    cudaFuncSetAttribute(att_a_kernel, cudaFuncAttributeMaxDynamicSharedMemorySize, A2_SMEM);
    cudaFuncSetAttribute(weff_kernel, cudaFuncAttributeMaxDynamicSharedMemorySize, W2_SMEM);
    cudaFuncSetAttribute(outproj_mma_kernel, cudaFuncAttributeMaxDynamicSharedMemorySize, K3_SMEM);

    qkv_mma_kernel<<<dim3(18, 2, B_), 256, K1_SMEM>>>(x, Wqkv);
    att_a_kernel<<<dim3(NCH, 32, NSUB), 128, A2_SMEM>>>();
    weff_kernel<<<dim3(NCH, B_, 4), 256, W2_SMEM>>>(Wqkv, Wout);
    outproj_mma_kernel<<<dim3(GN_TILES, B_), 256, K3_SMEM>>>(x, bout, y);
    gnorm_kernel<<<dim3(36, B_), 256>>>(y, gamma, beta);
}